// round 2
// baseline (speedup 1.0000x reference)
#include <cuda_runtime.h>
#include <math.h>

// ---------------- problem constants ----------------
#define BB 2
#define CC 180
#define DD 16
#define HH 32
#define WW 32
#define LL 16384            // D*H*W
#define LT 32768            // B*L
#define NHEADS 6
#define HDIM 30
#define NTOK 512            // tokens per window
#define NWIN 64
#define NTAB 3375
#define HIDD 720
#define CRR 60
#define QSCALE 0.18257418583505537f  // 30^-0.5

// ---------------- device scratch ----------------
__device__ float g_xn[LT * CC];
__device__ float g_ln2[LT * CC];
__device__ float g_x1[LT * CC];
__device__ float g_y1[LT * 64];                 // conv1 out, padded to 64 ch, gelu'd
__device__ float g_y2[LT * CC];                 // conv2 out + bias
__device__ float g_qkv[NWIN * 3 * NHEADS * NTOK * HDIM];
__device__ float g_ao[LT * CC];                 // attention output (window order)
__device__ float g_hbuf[LT * HIDD];             // fc1 gelu out
__device__ float g_biasT[NHEADS * NTOK * NTOK]; // [h][m][n]
__device__ float g_w1t[27 * 180 * 64];          // [tap][cin][cout64]
__device__ float g_w2t[27 * 64 * 192];          // [tap][cin64][cout192]
__device__ float g_pool[2 * CC];
__device__ float g_catt[2 * CC];

// window (win, n) -> flat row b*LL + l  (bijection; same map used forward & reverse)
__device__ __forceinline__ int win_src_row(int r) {
    int win = r >> 9, n = r & 511;
    int sb = win >> 2, wq = win & 3;
    int b = sb >> 3, isp = sb & 7;
    int id = isp >> 2, ih = (isp >> 1) & 1, iw = isp & 1;
    int nhi = wq >> 1, nwi = wq & 1;
    int wd = n >> 6, wh = (n >> 3) & 7, ww = n & 7;
    int d = wd * 2 + id;
    int h = (nhi * 8 + wh) * 2 + ih;
    int w = (nwi * 8 + ww) * 2 + iw;
    return ((b * DD + d) * HH + h) * WW + w;
}

__device__ __forceinline__ float gelu_exact(float v) {
    return 0.5f * v * (1.f + erff(v * 0.70710678118654752f));
}

// ---------------- small prep kernels ----------------
__global__ void repack1_kernel(const float* __restrict__ cw1, float* __restrict__ w1t) {
    int idx = blockIdx.x * 256 + threadIdx.x;
    if (idx >= 27 * 180 * 64) return;
    int tap = idx / (180 * 64);
    int r = idx - tap * 180 * 64;
    int c = r >> 6, o = r & 63;
    w1t[idx] = (o < 60) ? cw1[(o * 180 + c) * 27 + tap] : 0.f;
}

__global__ void repack2_kernel(const float* __restrict__ cw2, float* __restrict__ w2t) {
    int idx = blockIdx.x * 256 + threadIdx.x;
    if (idx >= 27 * 64 * 192) return;
    int tap = idx / (64 * 192);
    int r = idx - tap * 64 * 192;
    int c = r / 192, o = r - c * 192;
    w2t[idx] = (o < 180 && c < 60) ? cw2[(o * 60 + c) * 27 + tap] : 0.f;
}

__global__ void biasprep_kernel(const int* __restrict__ rpi, const float* __restrict__ rpb,
                                float* __restrict__ biasT) {
    int m = blockIdx.x, n = threadIdx.x;
    int t = rpi[n * 512 + m];
#pragma unroll
    for (int h = 0; h < NHEADS; h++)
        biasT[(h * 512 + m) * 512 + n] = rpb[t * NHEADS + h];
}

__global__ void zero_pool_kernel(float* __restrict__ pool) {
    if (threadIdx.x < 2 * CC) pool[threadIdx.x] = 0.f;
}

// ---------------- layernorm (warp per row) ----------------
__global__ void __launch_bounds__(256) ln_kernel(const float* __restrict__ in,
        const float* __restrict__ gg, const float* __restrict__ bb,
        float* __restrict__ outp) {
    int row = blockIdx.x * 8 + (threadIdx.x >> 5);
    int lane = threadIdx.x & 31;
    const float* p = in + row * CC;
    float v[6];
    float s = 0.f;
#pragma unroll
    for (int i = 0; i < 6; i++) {
        int c = lane + i * 32;
        v[i] = (c < CC) ? p[c] : 0.f;
        s += v[i];
    }
    for (int o = 16; o; o >>= 1) s += __shfl_xor_sync(~0u, s, o);
    float mean = s * (1.f / CC);
    float vs = 0.f;
#pragma unroll
    for (int i = 0; i < 6; i++) {
        int c = lane + i * 32;
        float d = (c < CC) ? (v[i] - mean) : 0.f;
        vs += d * d;
    }
    for (int o = 16; o; o >>= 1) vs += __shfl_xor_sync(~0u, vs, o);
    float inv = rsqrtf(vs * (1.f / CC) + 1e-5f);
    float* q = outp + row * CC;
#pragma unroll
    for (int i = 0; i < 6; i++) {
        int c = lane + i * 32;
        if (c < CC) q[c] = (v[i] - mean) * inv * gg[c] + bb[c];
    }
}

// ---------------- conv1: 180 -> 60(pad 64), 3x3x3 SAME, + bias + gelu ----------------
// block = one (b,d,h) row of 32 w positions x 64 out channels
__global__ void __launch_bounds__(256) conv1_kernel(const float* __restrict__ xn,
        const float* __restrict__ w1t, const float* __restrict__ cb1,
        float* __restrict__ y1) {
    __shared__ float Xs[34 * 90];
    __shared__ float Ws[90 * 64];
    int bdh = blockIdx.x;
    int b = bdh >> 9, d = (bdh >> 5) & 15, hrow = bdh & 31;
    int tid = threadIdx.x, cg = tid & 15, wg = tid >> 4;
    float acc[2][4] = {};
    for (int kd = 0; kd < 3; kd++) {
        int dd = d + kd - 1;
        if ((unsigned)dd >= (unsigned)DD) continue;
        for (int kh = 0; kh < 3; kh++) {
            int hh2 = hrow + kh - 1;
            if ((unsigned)hh2 >= (unsigned)HH) continue;
            const float* src = xn + (((b * DD + dd) * HH + hh2) * WW) * CC;
            for (int cc = 0; cc < 180; cc += 90) {
                __syncthreads();
                for (int idx = tid; idx < 34 * 90; idx += 256) {
                    int wq = idx / 90, c = idx - wq * 90;
                    int w = wq - 1;
                    Xs[idx] = ((unsigned)w < 32u) ? src[w * CC + cc + c] : 0.f;
                }
                for (int kw = 0; kw < 3; kw++) {
                    int tap = (kd * 3 + kh) * 3 + kw;
                    __syncthreads();
                    for (int idx = tid; idx < 90 * 64; idx += 256)
                        Ws[idx] = w1t[(tap * 180 + cc) * 64 + idx];
                    __syncthreads();
#pragma unroll 2
                    for (int c = 0; c < 90; c++) {
                        float xa = Xs[(wg * 2 + kw) * 90 + c];
                        float xb = Xs[(wg * 2 + 1 + kw) * 90 + c];
                        float4 wv = *(const float4*)&Ws[c * 64 + cg * 4];
                        acc[0][0] += xa * wv.x; acc[0][1] += xa * wv.y;
                        acc[0][2] += xa * wv.z; acc[0][3] += xa * wv.w;
                        acc[1][0] += xb * wv.x; acc[1][1] += xb * wv.y;
                        acc[1][2] += xb * wv.z; acc[1][3] += xb * wv.w;
                    }
                }
            }
        }
    }
    int w0 = wg * 2;
    float* dst = y1 + (((b * DD + d) * HH + hrow) * WW) * 64;
#pragma unroll
    for (int i = 0; i < 2; i++)
#pragma unroll
        for (int j = 0; j < 4; j++) {
            int o = cg * 4 + j;
            float v = acc[i][j] + ((o < 60) ? cb1[o] : 0.f);
            dst[(w0 + i) * 64 + o] = gelu_exact(v);
        }
}

// ---------------- conv2: 60(pad64) -> 180, 3x3x3, + bias ----------------
__global__ void __launch_bounds__(256) conv2_kernel(const float* __restrict__ y1,
        const float* __restrict__ w2t, const float* __restrict__ cb2,
        float* __restrict__ y2) {
    __shared__ float Xs[34 * 64];
    __shared__ float Ws[64 * 64];
    int bdh = blockIdx.x;
    int ob = blockIdx.y * 64;
    int b = bdh >> 9, d = (bdh >> 5) & 15, hrow = bdh & 31;
    int tid = threadIdx.x, cg = tid & 15, wg = tid >> 4;
    float acc[2][4] = {};
    for (int kd = 0; kd < 3; kd++) {
        int dd = d + kd - 1;
        if ((unsigned)dd >= (unsigned)DD) continue;
        for (int kh = 0; kh < 3; kh++) {
            int hh2 = hrow + kh - 1;
            if ((unsigned)hh2 >= (unsigned)HH) continue;
            const float* src = y1 + (((b * DD + dd) * HH + hh2) * WW) * 64;
            __syncthreads();
            for (int idx = tid; idx < 34 * 64; idx += 256) {
                int wq = idx >> 6, c = idx & 63;
                int w = wq - 1;
                Xs[idx] = ((unsigned)w < 32u) ? src[w * 64 + c] : 0.f;
            }
            for (int kw = 0; kw < 3; kw++) {
                int tap = (kd * 3 + kh) * 3 + kw;
                __syncthreads();
                for (int idx = tid; idx < 64 * 64; idx += 256) {
                    int c = idx >> 6, o = idx & 63;
                    Ws[idx] = w2t[(tap * 64 + c) * 192 + ob + o];
                }
                __syncthreads();
#pragma unroll 2
                for (int c = 0; c < 64; c++) {
                    float xa = Xs[(wg * 2 + kw) * 64 + c];
                    float xb = Xs[(wg * 2 + 1 + kw) * 64 + c];
                    float4 wv = *(const float4*)&Ws[c * 64 + cg * 4];
                    acc[0][0] += xa * wv.x; acc[0][1] += xa * wv.y;
                    acc[0][2] += xa * wv.z; acc[0][3] += xa * wv.w;
                    acc[1][0] += xb * wv.x; acc[1][1] += xb * wv.y;
                    acc[1][2] += xb * wv.z; acc[1][3] += xb * wv.w;
                }
            }
        }
    }
    int w0 = wg * 2;
    float* dst = y2 + (((b * DD + d) * HH + hrow) * WW) * CC;
#pragma unroll
    for (int i = 0; i < 2; i++)
#pragma unroll
        for (int j = 0; j < 4; j++) {
            int o = ob + cg * 4 + j;
            if (o < CC) dst[(w0 + i) * CC + o] = acc[i][j] + cb2[o];
        }
}

// ---------------- pooled sum + channel attention ----------------
__global__ void pooled_kernel(const float* __restrict__ y2, float* __restrict__ pool) {
    int r0 = blockIdx.x * 64;
    int b = r0 >> 14;
    int c = threadIdx.x;
    if (c >= CC) return;
    float s = 0.f;
    for (int i = 0; i < 64; i++) s += y2[(r0 + i) * CC + c];
    atomicAdd(&pool[b * CC + c], s);
}

__global__ void catt_kernel(const float* __restrict__ pool,
        const float* __restrict__ caw1, const float* __restrict__ cab1,
        const float* __restrict__ caw2, const float* __restrict__ cab2,
        float* __restrict__ catt) {
    __shared__ float sq[2][8];
    int tid = threadIdx.x;
    if (tid < 12) {
        int b = tid / 6, j = tid % 6;
        float s = cab1[j];
        for (int c = 0; c < CC; c++)
            s += (pool[b * CC + c] * (1.f / LL)) * caw1[j * CC + c];
        sq[b][j] = fmaxf(s, 0.f);
    }
    __syncthreads();
    if (tid < CC) {
        for (int b = 0; b < 2; b++) {
            float s = cab2[tid];
#pragma unroll
            for (int j = 0; j < 6; j++) s += sq[b][j] * caw2[tid * 6 + j];
            catt[b * CC + tid] = 1.f / (1.f + __expf(-s));
        }
    }
}

// ---------------- generic tiled SGEMM: C = A @ W^T + bias, fused epilogues ----------------
// BM=64 BN=64 BK=30, 256 threads, 4x4 micro-tile
// EPI 0: qkv scatter (+q scale); 1: proj scatter + triple residual; 2: gelu; 3: residual->out
template <int EPI, bool GATHER>
__global__ void __launch_bounds__(256) gemm_kernel(const float* __restrict__ A,
        const float* __restrict__ Wm, const float* __restrict__ bias,
        float* __restrict__ Cout, int Nc, int K,
        const float* __restrict__ e0, const float* __restrict__ e1,
        const float* __restrict__ e2) {
    __shared__ float As[30][68];
    __shared__ float Bs[30][68];
    const int row0 = blockIdx.x * 64, col0 = blockIdx.y * 64;
    const int tid = threadIdx.x, tx = tid & 15, ty = tid >> 4;
    float acc[4][4] = {};
    for (int k0 = 0; k0 < K; k0 += 30) {
        __syncthreads();
        for (int idx = tid; idx < 64 * 30; idx += 256) {
            int m = idx / 30, k = idx - m * 30;
            int r = row0 + m;
            int src = GATHER ? win_src_row(r) : r;
            As[k][m] = A[src * K + k0 + k];
        }
        for (int idx = tid; idx < 64 * 30; idx += 256) {
            int nn = idx / 30, k = idx - nn * 30;
            int col = col0 + nn;
            Bs[k][nn] = (col < Nc) ? Wm[col * K + k0 + k] : 0.f;
        }
        __syncthreads();
#pragma unroll
        for (int k = 0; k < 30; k++) {
            float4 av = *(const float4*)&As[k][ty * 4];
            float4 bv = *(const float4*)&Bs[k][tx * 4];
            acc[0][0] += av.x * bv.x; acc[0][1] += av.x * bv.y;
            acc[0][2] += av.x * bv.z; acc[0][3] += av.x * bv.w;
            acc[1][0] += av.y * bv.x; acc[1][1] += av.y * bv.y;
            acc[1][2] += av.y * bv.z; acc[1][3] += av.y * bv.w;
            acc[2][0] += av.z * bv.x; acc[2][1] += av.z * bv.y;
            acc[2][2] += av.z * bv.z; acc[2][3] += av.z * bv.w;
            acc[3][0] += av.w * bv.x; acc[3][1] += av.w * bv.y;
            acc[3][2] += av.w * bv.z; acc[3][3] += av.w * bv.w;
        }
    }
#pragma unroll
    for (int i = 0; i < 4; i++) {
        int row = row0 + ty * 4 + i;
#pragma unroll
        for (int j = 0; j < 4; j++) {
            int col = col0 + tx * 4 + j;
            if (col >= Nc) continue;
            float v = acc[i][j] + bias[col];
            if constexpr (EPI == 0) {
                int t = col / 180;
                int rem = col - t * 180;
                int hh = rem / 30, hd = rem - hh * 30;
                if (t == 0) v *= QSCALE;
                int win = row >> 9, n = row & 511;
                Cout[(((win * 3 + t) * NHEADS + hh) * NTOK + n) * HDIM + hd] = v;
            } else if constexpr (EPI == 1) {
                int src = win_src_row(row);
                int gi = src * CC + col;
                int b = src >> 14;
                Cout[gi] = e0[gi] + v + 0.01f * e1[gi] * e2[b * CC + col];
            } else if constexpr (EPI == 2) {
                Cout[row * Nc + col] = gelu_exact(v);
            } else {
                int gi = row * CC + col;
                Cout[gi] = e0[gi] + v;
            }
        }
    }
}

// ---------------- flash-style window attention ----------------
// block = (win, head); 256 threads, 2 queries/thread; K/V tiles of 128 in smem
__global__ void __launch_bounds__(256) attn_kernel(const float* __restrict__ qkv,
        const float* __restrict__ biasT, float* __restrict__ outp) {
    const int win = blockIdx.x / NHEADS, hh = blockIdx.x % NHEADS;
    const float* qb = qkv + ((win * 3 + 0) * NHEADS + hh) * NTOK * HDIM;
    const float* kb = qkv + ((win * 3 + 1) * NHEADS + hh) * NTOK * HDIM;
    const float* vb = qkv + ((win * 3 + 2) * NHEADS + hh) * NTOK * HDIM;
    const float* bbp = biasT + hh * NTOK * NTOK;
    __shared__ float Ks[128 * HDIM];
    __shared__ float Vs[128 * HDIM];
    const int tid = threadIdx.x;
    const int n1 = tid, n2 = tid + 256;
    float q1[HDIM], q2[HDIM], a1[HDIM], a2[HDIM];
#pragma unroll
    for (int d = 0; d < HDIM; d++) {
        q1[d] = qb[n1 * HDIM + d];
        q2[d] = qb[n2 * HDIM + d];
        a1[d] = 0.f; a2[d] = 0.f;
    }
    float m1 = -1e30f, m2 = -1e30f, l1 = 0.f, l2 = 0.f;
    for (int t0 = 0; t0 < NTOK; t0 += 128) {
        __syncthreads();
        for (int idx = tid; idx < 128 * HDIM; idx += 256) {
            Ks[idx] = kb[t0 * HDIM + idx];
            Vs[idx] = vb[t0 * HDIM + idx];
        }
        __syncthreads();
        for (int mm = 0; mm < 128; mm++) {
            const float* kr = Ks + mm * HDIM;
            const float* vr = Vs + mm * HDIM;
            int m = t0 + mm;
            float s1 = bbp[m * 512 + n1];
            float s2 = bbp[m * 512 + n2];
#pragma unroll
            for (int d = 0; d < HDIM; d++) {
                float kk = kr[d];
                s1 += kk * q1[d];
                s2 += kk * q2[d];
            }
            if (s1 > m1) {
                float f = __expf(m1 - s1);
                l1 *= f;
#pragma unroll
                for (int d = 0; d < HDIM; d++) a1[d] *= f;
                m1 = s1;
            }
            float p1 = __expf(s1 - m1);
            l1 += p1;
            if (s2 > m2) {
                float f = __expf(m2 - s2);
                l2 *= f;
#pragma unroll
                for (int d = 0; d < HDIM; d++) a2[d] *= f;
                m2 = s2;
            }
            float p2 = __expf(s2 - m2);
            l2 += p2;
#pragma unroll
            for (int d = 0; d < HDIM; d++) {
                float vv = vr[d];
                a1[d] += p1 * vv;
                a2[d] += p2 * vv;
            }
        }
    }
    float inv1 = 1.f / l1, inv2 = 1.f / l2;
    float* o1 = outp + (win * NTOK + n1) * CC + hh * HDIM;
    float* o2 = outp + (win * NTOK + n2) * CC + hh * HDIM;
#pragma unroll
    for (int d = 0; d < HDIM; d++) {
        o1[d] = a1[d] * inv1;
        o2[d] = a2[d] * inv2;
    }
}

// ---------------- host launch ----------------
extern "C" void kernel_launch(void* const* d_in, const int* in_sizes, int n_in,
                              void* d_out, int out_size) {
    const float* x      = (const float*)d_in[0];
    const int*   rpi    = (const int*)  d_in[4];
    const float* g1     = (const float*)d_in[7];
    const float* b1     = (const float*)d_in[8];
    const float* qkv_w  = (const float*)d_in[9];
    const float* qkv_b  = (const float*)d_in[10];
    const float* rpb    = (const float*)d_in[11];
    const float* proj_w = (const float*)d_in[12];
    const float* proj_b = (const float*)d_in[13];
    const float* cw1    = (const float*)d_in[14];
    const float* cb1    = (const float*)d_in[15];
    const float* cw2    = (const float*)d_in[16];
    const float* cb2    = (const float*)d_in[17];
    const float* caw1   = (const float*)d_in[18];
    const float* cab1   = (const float*)d_in[19];
    const float* caw2   = (const float*)d_in[20];
    const float* cab2   = (const float*)d_in[21];
    const float* g2     = (const float*)d_in[22];
    const float* b2     = (const float*)d_in[23];
    const float* fc1_w  = (const float*)d_in[24];
    const float* fc1_b  = (const float*)d_in[25];
    const float* fc2_w  = (const float*)d_in[26];
    const float* fc2_b  = (const float*)d_in[27];
    float* outp = (float*)d_out;

    float *p_xn, *p_ln2, *p_x1, *p_y1, *p_y2, *p_qkv, *p_ao, *p_h, *p_bt;
    float *p_w1t, *p_w2t, *p_pool, *p_catt;
    cudaGetSymbolAddress((void**)&p_xn,   g_xn);
    cudaGetSymbolAddress((void**)&p_ln2,  g_ln2);
    cudaGetSymbolAddress((void**)&p_x1,   g_x1);
    cudaGetSymbolAddress((void**)&p_y1,   g_y1);
    cudaGetSymbolAddress((void**)&p_y2,   g_y2);
    cudaGetSymbolAddress((void**)&p_qkv,  g_qkv);
    cudaGetSymbolAddress((void**)&p_ao,   g_ao);
    cudaGetSymbolAddress((void**)&p_h,    g_hbuf);
    cudaGetSymbolAddress((void**)&p_bt,   g_biasT);
    cudaGetSymbolAddress((void**)&p_w1t,  g_w1t);
    cudaGetSymbolAddress((void**)&p_w2t,  g_w2t);
    cudaGetSymbolAddress((void**)&p_pool, g_pool);
    cudaGetSymbolAddress((void**)&p_catt, g_catt);

    // weight / bias prep
    repack1_kernel<<<(27 * 180 * 64 + 255) / 256, 256>>>(cw1, p_w1t);
    repack2_kernel<<<(27 * 64 * 192 + 255) / 256, 256>>>(cw2, p_w2t);
    biasprep_kernel<<<512, 512>>>(rpi, rpb, p_bt);
    zero_pool_kernel<<<1, 384>>>(p_pool);

    // LN1
    ln_kernel<<<LT / 8, 256>>>(x, g1, b1, p_xn);

    // CAB conv branch
    conv1_kernel<<<BB * DD * HH, 256>>>(p_xn, p_w1t, cb1, p_y1);
    conv2_kernel<<<dim3(BB * DD * HH, 3), 256>>>(p_y1, p_w2t, cb2, p_y2);
    pooled_kernel<<<LT / 64, 192>>>(p_y2, p_pool);
    catt_kernel<<<1, 192>>>(p_pool, caw1, cab1, caw2, cab2, p_catt);

    // window attention path
    gemm_kernel<0, true><<<dim3(LT / 64, 9), 256>>>(p_xn, qkv_w, qkv_b, p_qkv,
                                                    540, 180, nullptr, nullptr, nullptr);
    attn_kernel<<<NWIN * NHEADS, 256>>>(p_qkv, p_bt, p_ao);
    gemm_kernel<1, false><<<dim3(LT / 64, 3), 256>>>(p_ao, proj_w, proj_b, p_x1,
                                                     180, 180, x, p_y2, p_catt);

    // MLP
    ln_kernel<<<LT / 8, 256>>>(p_x1, g2, b2, p_ln2);
    gemm_kernel<2, false><<<dim3(LT / 64, 12), 256>>>(p_ln2, fc1_w, fc1_b, p_h,
                                                      720, 180, nullptr, nullptr, nullptr);
    gemm_kernel<3, false><<<dim3(LT / 64, 3), 256>>>(p_h, fc2_w, fc2_b, outp,
                                                     180, 720, p_x1, nullptr, nullptr);
}

// round 3
// speedup vs baseline: 1.9357x; 1.9357x over previous
#include <cuda_runtime.h>
#include <math.h>
#include <stdint.h>

// ---------------- problem constants ----------------
#define BB 2
#define CC 180
#define CP 192              // padded channel stride (multiple of 16)
#define DD 16
#define HH 32
#define WW 32
#define LL 16384            // D*H*W
#define LT 32768            // B*L
#define NHEADS 6
#define HDIM 30
#define NTOK 512
#define NWIN 64
#define NTAB 3375
#define HIDD 720
#define QSCALE 0.18257418583505537f  // 30^-0.5

// ---------------- device scratch (zero-initialized; pads never written) ----------------
__device__ float g_xn[LT * CP];
__device__ float g_ln2[LT * CP];
__device__ float g_ao[LT * CP];                 // attention output (window order), padded
__device__ float g_x1[LT * CC];
__device__ float g_y1[LT * 64];                 // conv1 out, padded to 64 ch, gelu'd
__device__ float g_y2[LT * CC];                 // conv2 out + bias
__device__ float g_qkv[NWIN * 3 * NHEADS * NTOK * HDIM];
__device__ float g_hbuf[LT * HIDD];             // fc1 gelu out
__device__ float g_biasT[NHEADS * NTOK * NTOK]; // [h][m][n]
__device__ float g_w1m[27 * 64 * 192];          // [tap][cout64][cin192]
__device__ float g_w2m[27 * 192 * 64];          // [tap][cout192][cin64]
__device__ float g_pool[2 * CC];
__device__ float g_catt[2 * CC];

// window (win, n) -> flat row b*LL + l  (bijection)
__device__ __forceinline__ int win_src_row(int r) {
    int win = r >> 9, n = r & 511;
    int sb = win >> 2, wq = win & 3;
    int b = sb >> 3, isp = sb & 7;
    int id = isp >> 2, ih = (isp >> 1) & 1, iw = isp & 1;
    int nhi = wq >> 1, nwi = wq & 1;
    int wd = n >> 6, wh = (n >> 3) & 7, ww = n & 7;
    int d = wd * 2 + id;
    int h = (nhi * 8 + wh) * 2 + ih;
    int w = (nwi * 8 + ww) * 2 + iw;
    return ((b * DD + d) * HH + h) * WW + w;
}

__device__ __forceinline__ float gelu_exact(float v) {
    return 0.5f * v * (1.f + erff(v * 0.70710678118654752f));
}

__device__ __forceinline__ uint32_t f2tf(float f) {
    uint32_t u;
    asm("cvt.rna.tf32.f32 %0, %1;" : "=r"(u) : "f"(f));
    return u;
}

__device__ __forceinline__ void mma8(float* c, const uint32_t* a, const uint32_t* b) {
    asm volatile(
        "mma.sync.aligned.m16n8k8.row.col.f32.tf32.tf32.f32 "
        "{%0,%1,%2,%3},{%4,%5,%6,%7},{%8,%9},{%0,%1,%2,%3};\n"
        : "+f"(c[0]), "+f"(c[1]), "+f"(c[2]), "+f"(c[3])
        : "r"(a[0]), "r"(a[1]), "r"(a[2]), "r"(a[3]), "r"(b[0]), "r"(b[1]));
}

// shared compute step: one BK=16 tile, warp tile 32x32, 2x4 m16n8 frags
__device__ __forceinline__ void tile_mma(const uint32_t (*As)[20], const uint32_t (*Bs)[20],
                                         float acc[2][4][4], int wm, int wn, int lr, int lc) {
#pragma unroll
    for (int ks = 0; ks < 2; ks++) {
        uint32_t a[2][4], b[4][2];
#pragma unroll
        for (int mt = 0; mt < 2; mt++) {
            int r = wm * 32 + mt * 16 + lr;
            a[mt][0] = As[r][lc + 8 * ks];
            a[mt][1] = As[r + 8][lc + 8 * ks];
            a[mt][2] = As[r][lc + 4 + 8 * ks];
            a[mt][3] = As[r + 8][lc + 4 + 8 * ks];
        }
#pragma unroll
        for (int nt = 0; nt < 4; nt++) {
            int c2 = wn * 32 + nt * 8 + lr;
            b[nt][0] = Bs[c2][lc + 8 * ks];
            b[nt][1] = Bs[c2][lc + 4 + 8 * ks];
        }
#pragma unroll
        for (int mt = 0; mt < 2; mt++)
#pragma unroll
            for (int nt = 0; nt < 4; nt++)
                mma8(acc[mt][nt], a[mt], b[nt]);
    }
}

// ---------------- small prep kernels ----------------
__global__ void repack1_kernel(const float* __restrict__ cw1, float* __restrict__ w1m) {
    int idx = blockIdx.x * 256 + threadIdx.x;
    if (idx >= 27 * 64 * 192) return;
    int tap = idx / (64 * 192);
    int rem = idx - tap * 64 * 192;
    int o = rem / 192, c = rem - o * 192;
    w1m[idx] = (o < 60 && c < 180) ? cw1[(o * 180 + c) * 27 + tap] : 0.f;
}

__global__ void repack2_kernel(const float* __restrict__ cw2, float* __restrict__ w2m) {
    int idx = blockIdx.x * 256 + threadIdx.x;
    if (idx >= 27 * 192 * 64) return;
    int tap = idx / (192 * 64);
    int rem = idx - tap * 192 * 64;
    int o = rem >> 6, c = rem & 63;
    w2m[idx] = (o < 180 && c < 60) ? cw2[(o * 60 + c) * 27 + tap] : 0.f;
}

__global__ void biasprep_kernel(const int* __restrict__ rpi, const float* __restrict__ rpb,
                                float* __restrict__ biasT) {
    int m = blockIdx.x, n = threadIdx.x;
    int t = rpi[n * 512 + m];
#pragma unroll
    for (int h = 0; h < NHEADS; h++)
        biasT[(h * 512 + m) * 512 + n] = rpb[t * NHEADS + h];
}

__global__ void zero_pool_kernel(float* __restrict__ pool) {
    if (threadIdx.x < 2 * CC) pool[threadIdx.x] = 0.f;
}

// ---------------- layernorm (warp per row) ----------------
__global__ void __launch_bounds__(256) ln_kernel(const float* __restrict__ in, int ins,
        const float* __restrict__ gg, const float* __restrict__ bb,
        float* __restrict__ outp, int outs) {
    int row = blockIdx.x * 8 + (threadIdx.x >> 5);
    int lane = threadIdx.x & 31;
    const float* p = in + (long)row * ins;
    float v[6];
    float s = 0.f;
#pragma unroll
    for (int i = 0; i < 6; i++) {
        int c = lane + i * 32;
        v[i] = (c < CC) ? p[c] : 0.f;
        s += v[i];
    }
    for (int o = 16; o; o >>= 1) s += __shfl_xor_sync(~0u, s, o);
    float mean = s * (1.f / CC);
    float vs = 0.f;
#pragma unroll
    for (int i = 0; i < 6; i++) {
        int c = lane + i * 32;
        float d = (c < CC) ? (v[i] - mean) : 0.f;
        vs += d * d;
    }
    for (int o = 16; o; o >>= 1) vs += __shfl_xor_sync(~0u, vs, o);
    float inv = rsqrtf(vs * (1.f / CC) + 1e-5f);
    float* q = outp + (long)row * outs;
#pragma unroll
    for (int i = 0; i < 6; i++) {
        int c = lane + i * 32;
        if (c < CC) q[c] = (v[i] - mean) * inv * gg[c] + bb[c];
    }
}

// ---------------- TF32 MMA GEMM: C = A @ W^T + bias, fused epilogues ----------------
// BM=128 BN=64 BK=16, 256 thr (8 warps as 4x2), double-buffered smem
// EPI 0: qkv scatter (+q scale); 1: proj scatter + triple residual; 2: gelu; 3: residual->out
template <int EPI, bool GATHER>
__global__ void __launch_bounds__(256) mma_gemm(
        const float* __restrict__ A, int Asr,
        const float* __restrict__ Wm, const float* __restrict__ bias,
        float* __restrict__ Cout, int Nc, int K, int T,
        const float* __restrict__ e0, const float* __restrict__ e1,
        const float* __restrict__ e2) {
    __shared__ uint32_t As[2][128][20];
    __shared__ uint32_t Bs[2][64][20];
    const int tid = threadIdx.x;
    const int row0 = blockIdx.x * 128, col0 = blockIdx.y * 64;

    // A loader: 2 float4 per thread, rows fixed across tiles
    int ar[2], akq[2];
    long abase[2];
#pragma unroll
    for (int i = 0; i < 2; i++) {
        int id = tid + i * 256;
        ar[i] = id >> 2;
        akq[i] = id & 3;
        int r = row0 + ar[i];
        int src = GATHER ? win_src_row(r) : r;
        abase[i] = (long)src * Asr + akq[i] * 4;
    }
    const int bn = tid >> 2, bkq = tid & 3;
    const int bcol = col0 + bn;

    const int wid = tid >> 5, lane = tid & 31, lr = lane >> 2, lc = lane & 3;
    const int wm = wid >> 1, wn = wid & 1;
    float acc[2][4][4] = {};

    auto loadT = [&](int t, int buf) {
        int k0 = t * 16;
#pragma unroll
        for (int i = 0; i < 2; i++) {
            float4 v = *(const float4*)(A + abase[i] + k0);
            uint4 u = make_uint4(f2tf(v.x), f2tf(v.y), f2tf(v.z), f2tf(v.w));
            *(uint4*)&As[buf][ar[i]][akq[i] * 4] = u;
        }
        int k = k0 + bkq * 4;
        float4 v = make_float4(0.f, 0.f, 0.f, 0.f);
        if (bcol < Nc && k < K) v = *(const float4*)(Wm + (long)bcol * K + k);
        uint4 u = make_uint4(f2tf(v.x), f2tf(v.y), f2tf(v.z), f2tf(v.w));
        *(uint4*)&Bs[buf][bn][bkq * 4] = u;
    };

    loadT(0, 0);
    __syncthreads();
    for (int t = 0; t < T; t++) {
        if (t + 1 < T) loadT(t + 1, (t + 1) & 1);
        tile_mma(As[t & 1], Bs[t & 1], acc, wm, wn, lr, lc);
        __syncthreads();
    }

    // epilogue
#pragma unroll
    for (int mt = 0; mt < 2; mt++) {
#pragma unroll
        for (int nt = 0; nt < 4; nt++) {
            int rbase = row0 + wm * 32 + mt * 16 + lr;
            int cbase = col0 + wn * 32 + nt * 8 + lc * 2;
#pragma unroll
            for (int e = 0; e < 4; e++) {
                int row = rbase + (e >> 1) * 8;
                int col = cbase + (e & 1);
                if (col >= Nc) continue;
                float v = acc[mt][nt][e] + bias[col];
                if constexpr (EPI == 0) {
                    int tq = col / 180;
                    int rem = col - tq * 180;
                    int hh = rem / 30, hd = rem - hh * 30;
                    if (tq == 0) v *= QSCALE;
                    int win = row >> 9, n = row & 511;
                    Cout[(((win * 3 + tq) * NHEADS + hh) * NTOK + n) * HDIM + hd] = v;
                } else if constexpr (EPI == 1) {
                    int src = win_src_row(row);
                    long gi = (long)src * CC + col;
                    int b = src >> 14;
                    Cout[gi] = e0[gi] + v + 0.01f * e1[gi] * e2[b * CC + col];
                } else if constexpr (EPI == 2) {
                    Cout[(long)row * Nc + col] = gelu_exact(v);
                } else {
                    long gi = (long)row * CC + col;
                    Cout[gi] = e0[gi] + v;
                }
            }
        }
    }
}

// ---------------- TF32 MMA implicit-GEMM 3x3x3 conv ----------------
// CV=1: 180(pad192)->60(pad64), +bias +gelu -> y1 (stride 64)
// CV=2: 60(pad64)->180, +bias -> y2 (stride 180)
template <int CV>
__global__ void __launch_bounds__(256) mma_conv(
        const float* __restrict__ A, const float* __restrict__ Wt,
        const float* __restrict__ bias, float* __restrict__ Out) {
    constexpr int Asr = (CV == 1) ? 192 : 64;
    constexpr int KT = (CV == 1) ? 12 : 4;     // k-tiles per tap
    constexpr int T = 27 * KT;
    constexpr int Wn = (CV == 1) ? 64 : 192;
    constexpr int Wk = (CV == 1) ? 192 : 64;
    __shared__ uint32_t As[2][128][20];
    __shared__ uint32_t Bs[2][64][20];
    const int tid = threadIdx.x;
    const int row0 = blockIdx.x * 128, col0 = blockIdx.y * 64;

    int ar[2], akq[2], pd[2], ph[2], pw[2];
#pragma unroll
    for (int i = 0; i < 2; i++) {
        int id = tid + i * 256;
        ar[i] = id >> 2;
        akq[i] = id & 3;
        int p = row0 + ar[i];
        pd[i] = (p >> 10) & 15;
        ph[i] = (p >> 5) & 31;
        pw[i] = p & 31;
    }
    const int bn = tid >> 2, bkq = tid & 3;

    const int wid = tid >> 5, lane = tid & 31, lr = lane >> 2, lc = lane & 3;
    const int wm = wid >> 1, wn = wid & 1;
    float acc[2][4][4] = {};

    auto loadT = [&](int t, int buf) {
        int tap = t / KT;
        int kt = t - tap * KT;
        int k0 = kt * 16;
        int kd = tap / 9 - 1;
        int r9 = tap - (kd + 1) * 9;
        int kh = r9 / 3 - 1;
        int kw = r9 - (kh + 1) * 3 - 1;
        int off = (kd << 10) + (kh << 5) + kw;
#pragma unroll
        for (int i = 0; i < 2; i++) {
            bool valid = ((unsigned)(pd[i] + kd) < 16u) &&
                         ((unsigned)(ph[i] + kh) < 32u) &&
                         ((unsigned)(pw[i] + kw) < 32u);
            float4 v = make_float4(0.f, 0.f, 0.f, 0.f);
            if (valid)
                v = *(const float4*)(A + (long)(row0 + ar[i] + off) * Asr + k0 + akq[i] * 4);
            uint4 u = make_uint4(f2tf(v.x), f2tf(v.y), f2tf(v.z), f2tf(v.w));
            *(uint4*)&As[buf][ar[i]][akq[i] * 4] = u;
        }
        float4 v = *(const float4*)(Wt + ((long)tap * Wn + col0 + bn) * Wk + k0 + bkq * 4);
        uint4 u = make_uint4(f2tf(v.x), f2tf(v.y), f2tf(v.z), f2tf(v.w));
        *(uint4*)&Bs[buf][bn][bkq * 4] = u;
    };

    loadT(0, 0);
    __syncthreads();
    for (int t = 0; t < T; t++) {
        if (t + 1 < T) loadT(t + 1, (t + 1) & 1);
        tile_mma(As[t & 1], Bs[t & 1], acc, wm, wn, lr, lc);
        __syncthreads();
    }

#pragma unroll
    for (int mt = 0; mt < 2; mt++) {
#pragma unroll
        for (int nt = 0; nt < 4; nt++) {
            int rbase = row0 + wm * 32 + mt * 16 + lr;
            int cbase = col0 + wn * 32 + nt * 8 + lc * 2;
#pragma unroll
            for (int e = 0; e < 4; e++) {
                int row = rbase + (e >> 1) * 8;
                int col = cbase + (e & 1);
                float v = acc[mt][nt][e];
                if constexpr (CV == 1) {
                    v += (col < 60) ? bias[col] : 0.f;
                    Out[(long)row * 64 + col] = gelu_exact(v);
                } else {
                    if (col < CC) Out[(long)row * CC + col] = v + bias[col];
                }
            }
        }
    }
}

// ---------------- pooled sum + channel attention ----------------
__global__ void pooled_kernel(const float* __restrict__ y2, float* __restrict__ pool) {
    int r0 = blockIdx.x * 64;
    int b = r0 >> 14;
    int c = threadIdx.x;
    if (c >= CC) return;
    float s = 0.f;
    for (int i = 0; i < 64; i++) s += y2[(long)(r0 + i) * CC + c];
    atomicAdd(&pool[b * CC + c], s);
}

__global__ void catt_kernel(const float* __restrict__ pool,
        const float* __restrict__ caw1, const float* __restrict__ cab1,
        const float* __restrict__ caw2, const float* __restrict__ cab2,
        float* __restrict__ catt) {
    __shared__ float sq[2][8];
    int tid = threadIdx.x;
    if (tid < 12) {
        int b = tid / 6, j = tid % 6;
        float s = cab1[j];
        for (int c = 0; c < CC; c++)
            s += (pool[b * CC + c] * (1.f / LL)) * caw1[j * CC + c];
        sq[b][j] = fmaxf(s, 0.f);
    }
    __syncthreads();
    if (tid < CC) {
        for (int b = 0; b < 2; b++) {
            float s = cab2[tid];
#pragma unroll
            for (int j = 0; j < 6; j++) s += sq[b][j] * caw2[tid * 6 + j];
            catt[b * CC + tid] = 1.f / (1.f + __expf(-s));
        }
    }
}

// ---------------- flash-style window attention (SIMT) ----------------
__global__ void __launch_bounds__(256) attn_kernel(const float* __restrict__ qkv,
        const float* __restrict__ biasT, float* __restrict__ outp) {
    const int win = blockIdx.x / NHEADS, hh = blockIdx.x % NHEADS;
    const float* qb = qkv + ((win * 3 + 0) * NHEADS + hh) * NTOK * HDIM;
    const float* kb = qkv + ((win * 3 + 1) * NHEADS + hh) * NTOK * HDIM;
    const float* vb = qkv + ((win * 3 + 2) * NHEADS + hh) * NTOK * HDIM;
    const float* bbp = biasT + hh * NTOK * NTOK;
    __shared__ float Ks[128 * HDIM];
    __shared__ float Vs[128 * HDIM];
    const int tid = threadIdx.x;
    const int n1 = tid, n2 = tid + 256;
    float q1[HDIM], q2[HDIM], a1[HDIM], a2[HDIM];
#pragma unroll
    for (int d = 0; d < HDIM; d++) {
        q1[d] = qb[n1 * HDIM + d];
        q2[d] = qb[n2 * HDIM + d];
        a1[d] = 0.f; a2[d] = 0.f;
    }
    float m1 = -1e30f, m2 = -1e30f, l1 = 0.f, l2 = 0.f;
    for (int t0 = 0; t0 < NTOK; t0 += 128) {
        __syncthreads();
        for (int idx = tid; idx < 128 * HDIM; idx += 256) {
            Ks[idx] = kb[t0 * HDIM + idx];
            Vs[idx] = vb[t0 * HDIM + idx];
        }
        __syncthreads();
        for (int mm = 0; mm < 128; mm++) {
            const float* kr = Ks + mm * HDIM;
            const float* vr = Vs + mm * HDIM;
            int m = t0 + mm;
            float s1 = bbp[m * 512 + n1];
            float s2 = bbp[m * 512 + n2];
#pragma unroll
            for (int d = 0; d < HDIM; d++) {
                float kk = kr[d];
                s1 += kk * q1[d];
                s2 += kk * q2[d];
            }
            if (s1 > m1) {
                float f = __expf(m1 - s1);
                l1 *= f;
#pragma unroll
                for (int d = 0; d < HDIM; d++) a1[d] *= f;
                m1 = s1;
            }
            float p1 = __expf(s1 - m1);
            l1 += p1;
            if (s2 > m2) {
                float f = __expf(m2 - s2);
                l2 *= f;
#pragma unroll
                for (int d = 0; d < HDIM; d++) a2[d] *= f;
                m2 = s2;
            }
            float p2 = __expf(s2 - m2);
            l2 += p2;
#pragma unroll
            for (int d = 0; d < HDIM; d++) {
                float vv = vr[d];
                a1[d] += p1 * vv;
                a2[d] += p2 * vv;
            }
        }
    }
    float inv1 = 1.f / l1, inv2 = 1.f / l2;
    float* o1 = outp + (long)(win * NTOK + n1) * CP + hh * HDIM;
    float* o2 = outp + (long)(win * NTOK + n2) * CP + hh * HDIM;
#pragma unroll
    for (int d = 0; d < HDIM; d++) {
        o1[d] = a1[d] * inv1;
        o2[d] = a2[d] * inv2;
    }
}

// ---------------- host launch ----------------
extern "C" void kernel_launch(void* const* d_in, const int* in_sizes, int n_in,
                              void* d_out, int out_size) {
    const float* x      = (const float*)d_in[0];
    const int*   rpi    = (const int*)  d_in[4];
    const float* g1     = (const float*)d_in[7];
    const float* b1     = (const float*)d_in[8];
    const float* qkv_w  = (const float*)d_in[9];
    const float* qkv_b  = (const float*)d_in[10];
    const float* rpb    = (const float*)d_in[11];
    const float* proj_w = (const float*)d_in[12];
    const float* proj_b = (const float*)d_in[13];
    const float* cw1    = (const float*)d_in[14];
    const float* cb1    = (const float*)d_in[15];
    const float* cw2    = (const float*)d_in[16];
    const float* cb2    = (const float*)d_in[17];
    const float* caw1   = (const float*)d_in[18];
    const float* cab1   = (const float*)d_in[19];
    const float* caw2   = (const float*)d_in[20];
    const float* cab2   = (const float*)d_in[21];
    const float* g2     = (const float*)d_in[22];
    const float* b2     = (const float*)d_in[23];
    const float* fc1_w  = (const float*)d_in[24];
    const float* fc1_b  = (const float*)d_in[25];
    const float* fc2_w  = (const float*)d_in[26];
    const float* fc2_b  = (const float*)d_in[27];
    float* outp = (float*)d_out;

    float *p_xn, *p_ln2, *p_x1, *p_y1, *p_y2, *p_qkv, *p_ao, *p_h, *p_bt;
    float *p_w1m, *p_w2m, *p_pool, *p_catt;
    cudaGetSymbolAddress((void**)&p_xn,   g_xn);
    cudaGetSymbolAddress((void**)&p_ln2,  g_ln2);
    cudaGetSymbolAddress((void**)&p_x1,   g_x1);
    cudaGetSymbolAddress((void**)&p_y1,   g_y1);
    cudaGetSymbolAddress((void**)&p_y2,   g_y2);
    cudaGetSymbolAddress((void**)&p_qkv,  g_qkv);
    cudaGetSymbolAddress((void**)&p_ao,   g_ao);
    cudaGetSymbolAddress((void**)&p_h,    g_hbuf);
    cudaGetSymbolAddress((void**)&p_bt,   g_biasT);
    cudaGetSymbolAddress((void**)&p_w1m,  g_w1m);
    cudaGetSymbolAddress((void**)&p_w2m,  g_w2m);
    cudaGetSymbolAddress((void**)&p_pool, g_pool);
    cudaGetSymbolAddress((void**)&p_catt, g_catt);

    // prep
    repack1_kernel<<<(27 * 64 * 192 + 255) / 256, 256>>>(cw1, p_w1m);
    repack2_kernel<<<(27 * 192 * 64 + 255) / 256, 256>>>(cw2, p_w2m);
    biasprep_kernel<<<512, 512>>>(rpi, rpb, p_bt);
    zero_pool_kernel<<<1, 384>>>(p_pool);

    // LN1 (write padded stride 192; pad columns stay zero from static init)
    ln_kernel<<<LT / 8, 256>>>(x, CC, g1, b1, p_xn, CP);

    // CAB conv branch (tensor-core implicit GEMM)
    mma_conv<1><<<dim3(LT / 128, 1), 256>>>(p_xn, p_w1m, cb1, p_y1);
    mma_conv<2><<<dim3(LT / 128, 3), 256>>>(p_y1, p_w2m, cb2, p_y2);
    pooled_kernel<<<LT / 64, 192>>>(p_y2, p_pool);
    catt_kernel<<<1, 192>>>(p_pool, caw1, cab1, caw2, cab2, p_catt);

    // window attention path
    mma_gemm<0, true><<<dim3(LT / 128, 9), 256>>>(p_xn, CP, qkv_w, qkv_b, p_qkv,
                                                  540, 180, 12, nullptr, nullptr, nullptr);
    attn_kernel<<<NWIN * NHEADS, 256>>>(p_qkv, p_bt, p_ao);
    mma_gemm<1, false><<<dim3(LT / 128, 3), 256>>>(p_ao, CP, proj_w, proj_b, p_x1,
                                                   180, 180, 12, x, p_y2, p_catt);

    // MLP
    ln_kernel<<<LT / 8, 256>>>(p_x1, CC, g2, b2, p_ln2, CP);
    mma_gemm<2, false><<<dim3(LT / 128, 12), 256>>>(p_ln2, CP, fc1_w, fc1_b, p_h,
                                                    720, 180, 12, nullptr, nullptr, nullptr);
    mma_gemm<3, false><<<dim3(LT / 128, 3), 256>>>(p_h, HIDD, fc2_w, fc2_b, outp,
                                                   180, 720, 45, p_x1, nullptr, nullptr);
}

// round 4
// speedup vs baseline: 2.4498x; 1.2656x over previous
#include <cuda_runtime.h>
#include <math.h>
#include <stdint.h>

// ---------------- problem constants ----------------
#define BB 2
#define CC 180
#define CP 192              // padded channel stride (multiple of 16)
#define DD 16
#define HH 32
#define WW 32
#define LL 16384            // D*H*W
#define LT 32768            // B*L
#define NHEADS 6
#define HDIM 30
#define NTOK 512
#define NWIN 64
#define NTAB 3375
#define HIDD 720
#define QSCALE 0.18257418583505537f  // 30^-0.5

// ---------------- device scratch (zero-initialized; pads never written) ----------------
__device__ float g_xn[LT * CP];
__device__ float g_ln2[LT * CP];
__device__ float g_ao[LT * CP];                 // attention output (window order), padded
__device__ float g_x1[LT * CC];
__device__ float g_y1[LT * 64];                 // conv1 out, padded to 64 ch, gelu'd
__device__ float g_y2[LT * CC];                 // conv2 out + bias
__device__ float g_qkv[NWIN * 3 * NHEADS * NTOK * HDIM];
__device__ float g_hbuf[LT * HIDD];             // fc1 gelu out
__device__ float g_biasT[NHEADS * NTOK * NTOK]; // [h][query][key]
__device__ float g_w1m[27 * 64 * 192];          // [tap][cout64][cin192]
__device__ float g_w2m[27 * 192 * 64];          // [tap][cout192][cin64]
__device__ float g_pool[2 * CC];
__device__ float g_catt[2 * CC];

// window (win, n) -> flat row b*LL + l  (bijection)
__device__ __forceinline__ int win_src_row(int r) {
    int win = r >> 9, n = r & 511;
    int sb = win >> 2, wq = win & 3;
    int b = sb >> 3, isp = sb & 7;
    int id = isp >> 2, ih = (isp >> 1) & 1, iw = isp & 1;
    int nhi = wq >> 1, nwi = wq & 1;
    int wd = n >> 6, wh = (n >> 3) & 7, ww = n & 7;
    int d = wd * 2 + id;
    int h = (nhi * 8 + wh) * 2 + ih;
    int w = (nwi * 8 + ww) * 2 + iw;
    return ((b * DD + d) * HH + h) * WW + w;
}

__device__ __forceinline__ float gelu_exact(float v) {
    return 0.5f * v * (1.f + erff(v * 0.70710678118654752f));
}

__device__ __forceinline__ uint32_t f2tf(float f) {
    uint32_t u;
    asm("cvt.rna.tf32.f32 %0, %1;" : "=r"(u) : "f"(f));
    return u;
}

__device__ __forceinline__ void mma8(float* c, const uint32_t* a, const uint32_t* b) {
    asm volatile(
        "mma.sync.aligned.m16n8k8.row.col.f32.tf32.tf32.f32 "
        "{%0,%1,%2,%3},{%4,%5,%6,%7},{%8,%9},{%0,%1,%2,%3};\n"
        : "+f"(c[0]), "+f"(c[1]), "+f"(c[2]), "+f"(c[3])
        : "r"(a[0]), "r"(a[1]), "r"(a[2]), "r"(a[3]), "r"(b[0]), "r"(b[1]));
}

// shared compute step: one BK=16 tile, warp tile 32x32, 2x4 m16n8 frags
__device__ __forceinline__ void tile_mma(const uint32_t (*As)[20], const uint32_t (*Bs)[20],
                                         float acc[2][4][4], int wm, int wn, int lr, int lc) {
#pragma unroll
    for (int ks = 0; ks < 2; ks++) {
        uint32_t a[2][4], b[4][2];
#pragma unroll
        for (int mt = 0; mt < 2; mt++) {
            int r = wm * 32 + mt * 16 + lr;
            a[mt][0] = As[r][lc + 8 * ks];
            a[mt][1] = As[r + 8][lc + 8 * ks];
            a[mt][2] = As[r][lc + 4 + 8 * ks];
            a[mt][3] = As[r + 8][lc + 4 + 8 * ks];
        }
#pragma unroll
        for (int nt = 0; nt < 4; nt++) {
            int c2 = wn * 32 + nt * 8 + lr;
            b[nt][0] = Bs[c2][lc + 8 * ks];
            b[nt][1] = Bs[c2][lc + 4 + 8 * ks];
        }
#pragma unroll
        for (int mt = 0; mt < 2; mt++)
#pragma unroll
            for (int nt = 0; nt < 4; nt++)
                mma8(acc[mt][nt], a[mt], b[nt]);
    }
}

// ---------------- small prep kernels ----------------
__global__ void repack1_kernel(const float* __restrict__ cw1, float* __restrict__ w1m) {
    int idx = blockIdx.x * 256 + threadIdx.x;
    if (idx >= 27 * 64 * 192) return;
    int tap = idx / (64 * 192);
    int rem = idx - tap * 64 * 192;
    int o = rem / 192, c = rem - o * 192;
    w1m[idx] = (o < 60 && c < 180) ? cw1[(o * 180 + c) * 27 + tap] : 0.f;
}

__global__ void repack2_kernel(const float* __restrict__ cw2, float* __restrict__ w2m) {
    int idx = blockIdx.x * 256 + threadIdx.x;
    if (idx >= 27 * 192 * 64) return;
    int tap = idx / (192 * 64);
    int rem = idx - tap * 192 * 64;
    int o = rem >> 6, c = rem & 63;
    w2m[idx] = (o < 180 && c < 60) ? cw2[(o * 60 + c) * 27 + tap] : 0.f;
}

// bias table: [h][query][key]
__global__ void biasprep_kernel(const int* __restrict__ rpi, const float* __restrict__ rpb,
                                float* __restrict__ biasT) {
    int q = blockIdx.x, k = threadIdx.x;
    int t = rpi[q * 512 + k];
#pragma unroll
    for (int h = 0; h < NHEADS; h++)
        biasT[(h * 512 + q) * 512 + k] = rpb[t * NHEADS + h];
}

__global__ void zero_pool_kernel(float* __restrict__ pool) {
    if (threadIdx.x < 2 * CC) pool[threadIdx.x] = 0.f;
}

// ---------------- layernorm (warp per row) ----------------
__global__ void __launch_bounds__(256) ln_kernel(const float* __restrict__ in, int ins,
        const float* __restrict__ gg, const float* __restrict__ bb,
        float* __restrict__ outp, int outs) {
    int row = blockIdx.x * 8 + (threadIdx.x >> 5);
    int lane = threadIdx.x & 31;
    const float* p = in + (long)row * ins;
    float v[6];
    float s = 0.f;
#pragma unroll
    for (int i = 0; i < 6; i++) {
        int c = lane + i * 32;
        v[i] = (c < CC) ? p[c] : 0.f;
        s += v[i];
    }
    for (int o = 16; o; o >>= 1) s += __shfl_xor_sync(~0u, s, o);
    float mean = s * (1.f / CC);
    float vs = 0.f;
#pragma unroll
    for (int i = 0; i < 6; i++) {
        int c = lane + i * 32;
        float d = (c < CC) ? (v[i] - mean) : 0.f;
        vs += d * d;
    }
    for (int o = 16; o; o >>= 1) vs += __shfl_xor_sync(~0u, vs, o);
    float inv = rsqrtf(vs * (1.f / CC) + 1e-5f);
    float* q = outp + (long)row * outs;
#pragma unroll
    for (int i = 0; i < 6; i++) {
        int c = lane + i * 32;
        if (c < CC) q[c] = (v[i] - mean) * inv * gg[c] + bb[c];
    }
}

// ---------------- TF32 MMA GEMM: C = A @ W^T + bias, fused epilogues ----------------
// BM=128 BN=64 BK=16, 256 thr (8 warps as 4x2), double-buffered smem
// EPI 0: qkv scatter (+q scale); 1: proj scatter + triple residual; 2: gelu; 3: residual->out
template <int EPI, bool GATHER>
__global__ void __launch_bounds__(256) mma_gemm(
        const float* __restrict__ A, int Asr,
        const float* __restrict__ Wm, const float* __restrict__ bias,
        float* __restrict__ Cout, int Nc, int K, int T,
        const float* __restrict__ e0, const float* __restrict__ e1,
        const float* __restrict__ e2) {
    __shared__ uint32_t As[2][128][20];
    __shared__ uint32_t Bs[2][64][20];
    const int tid = threadIdx.x;
    const int row0 = blockIdx.x * 128, col0 = blockIdx.y * 64;

    int ar[2], akq[2];
    long abase[2];
#pragma unroll
    for (int i = 0; i < 2; i++) {
        int id = tid + i * 256;
        ar[i] = id >> 2;
        akq[i] = id & 3;
        int r = row0 + ar[i];
        int src = GATHER ? win_src_row(r) : r;
        abase[i] = (long)src * Asr + akq[i] * 4;
    }
    const int bn = tid >> 2, bkq = tid & 3;
    const int bcol = col0 + bn;

    const int wid = tid >> 5, lane = tid & 31, lr = lane >> 2, lc = lane & 3;
    const int wm = wid >> 1, wn = wid & 1;
    float acc[2][4][4] = {};

    auto loadT = [&](int t, int buf) {
        int k0 = t * 16;
#pragma unroll
        for (int i = 0; i < 2; i++) {
            float4 v = *(const float4*)(A + abase[i] + k0);
            uint4 u = make_uint4(f2tf(v.x), f2tf(v.y), f2tf(v.z), f2tf(v.w));
            *(uint4*)&As[buf][ar[i]][akq[i] * 4] = u;
        }
        int k = k0 + bkq * 4;
        float4 v = make_float4(0.f, 0.f, 0.f, 0.f);
        if (bcol < Nc && k < K) v = *(const float4*)(Wm + (long)bcol * K + k);
        uint4 u = make_uint4(f2tf(v.x), f2tf(v.y), f2tf(v.z), f2tf(v.w));
        *(uint4*)&Bs[buf][bn][bkq * 4] = u;
    };

    loadT(0, 0);
    __syncthreads();
    for (int t = 0; t < T; t++) {
        if (t + 1 < T) loadT(t + 1, (t + 1) & 1);
        tile_mma(As[t & 1], Bs[t & 1], acc, wm, wn, lr, lc);
        __syncthreads();
    }

#pragma unroll
    for (int mt = 0; mt < 2; mt++) {
#pragma unroll
        for (int nt = 0; nt < 4; nt++) {
            int rbase = row0 + wm * 32 + mt * 16 + lr;
            int cbase = col0 + wn * 32 + nt * 8 + lc * 2;
#pragma unroll
            for (int e = 0; e < 4; e++) {
                int row = rbase + (e >> 1) * 8;
                int col = cbase + (e & 1);
                if (col >= Nc) continue;
                float v = acc[mt][nt][e] + bias[col];
                if constexpr (EPI == 0) {
                    int tq = col / 180;
                    int rem = col - tq * 180;
                    int hh = rem / 30, hd = rem - hh * 30;
                    if (tq == 0) v *= QSCALE;
                    int win = row >> 9, n = row & 511;
                    Cout[(((win * 3 + tq) * NHEADS + hh) * NTOK + n) * HDIM + hd] = v;
                } else if constexpr (EPI == 1) {
                    int src = win_src_row(row);
                    long gi = (long)src * CC + col;
                    int b = src >> 14;
                    Cout[gi] = e0[gi] + v + 0.01f * e1[gi] * e2[b * CC + col];
                } else if constexpr (EPI == 2) {
                    Cout[(long)row * Nc + col] = gelu_exact(v);
                } else {
                    long gi = (long)row * CC + col;
                    Cout[gi] = e0[gi] + v;
                }
            }
        }
    }
}

// ---------------- TF32 MMA implicit-GEMM 3x3x3 conv ----------------
template <int CV>
__global__ void __launch_bounds__(256) mma_conv(
        const float* __restrict__ A, const float* __restrict__ Wt,
        const float* __restrict__ bias, float* __restrict__ Out) {
    constexpr int Asr = (CV == 1) ? 192 : 64;
    constexpr int KT = (CV == 1) ? 12 : 4;
    constexpr int T = 27 * KT;
    constexpr int Wn = (CV == 1) ? 64 : 192;
    constexpr int Wk = (CV == 1) ? 192 : 64;
    __shared__ uint32_t As[2][128][20];
    __shared__ uint32_t Bs[2][64][20];
    const int tid = threadIdx.x;
    const int row0 = blockIdx.x * 128, col0 = blockIdx.y * 64;

    int ar[2], akq[2], pd[2], ph[2], pw[2];
#pragma unroll
    for (int i = 0; i < 2; i++) {
        int id = tid + i * 256;
        ar[i] = id >> 2;
        akq[i] = id & 3;
        int p = row0 + ar[i];
        pd[i] = (p >> 10) & 15;
        ph[i] = (p >> 5) & 31;
        pw[i] = p & 31;
    }
    const int bn = tid >> 2, bkq = tid & 3;

    const int wid = tid >> 5, lane = tid & 31, lr = lane >> 2, lc = lane & 3;
    const int wm = wid >> 1, wn = wid & 1;
    float acc[2][4][4] = {};

    auto loadT = [&](int t, int buf) {
        int tap = t / KT;
        int kt = t - tap * KT;
        int k0 = kt * 16;
        int kd = tap / 9 - 1;
        int r9 = tap - (kd + 1) * 9;
        int kh = r9 / 3 - 1;
        int kw = r9 - (kh + 1) * 3 - 1;
        int off = (kd << 10) + (kh << 5) + kw;
#pragma unroll
        for (int i = 0; i < 2; i++) {
            bool valid = ((unsigned)(pd[i] + kd) < 16u) &&
                         ((unsigned)(ph[i] + kh) < 32u) &&
                         ((unsigned)(pw[i] + kw) < 32u);
            float4 v = make_float4(0.f, 0.f, 0.f, 0.f);
            if (valid)
                v = *(const float4*)(A + (long)(row0 + ar[i] + off) * Asr + k0 + akq[i] * 4);
            uint4 u = make_uint4(f2tf(v.x), f2tf(v.y), f2tf(v.z), f2tf(v.w));
            *(uint4*)&As[buf][ar[i]][akq[i] * 4] = u;
        }
        float4 v = *(const float4*)(Wt + ((long)tap * Wn + col0 + bn) * Wk + k0 + bkq * 4);
        uint4 u = make_uint4(f2tf(v.x), f2tf(v.y), f2tf(v.z), f2tf(v.w));
        *(uint4*)&Bs[buf][bn][bkq * 4] = u;
    };

    loadT(0, 0);
    __syncthreads();
    for (int t = 0; t < T; t++) {
        if (t + 1 < T) loadT(t + 1, (t + 1) & 1);
        tile_mma(As[t & 1], Bs[t & 1], acc, wm, wn, lr, lc);
        __syncthreads();
    }

#pragma unroll
    for (int mt = 0; mt < 2; mt++) {
#pragma unroll
        for (int nt = 0; nt < 4; nt++) {
            int rbase = row0 + wm * 32 + mt * 16 + lr;
            int cbase = col0 + wn * 32 + nt * 8 + lc * 2;
#pragma unroll
            for (int e = 0; e < 4; e++) {
                int row = rbase + (e >> 1) * 8;
                int col = cbase + (e & 1);
                float v = acc[mt][nt][e];
                if constexpr (CV == 1) {
                    v += (col < 60) ? bias[col] : 0.f;
                    Out[(long)row * 64 + col] = gelu_exact(v);
                } else {
                    if (col < CC) Out[(long)row * CC + col] = v + bias[col];
                }
            }
        }
    }
}

// ---------------- pooled sum + channel attention ----------------
__global__ void pooled_kernel(const float* __restrict__ y2, float* __restrict__ pool) {
    int r0 = blockIdx.x * 64;
    int b = r0 >> 14;
    int c = threadIdx.x;
    if (c >= CC) return;
    float s = 0.f;
    for (int i = 0; i < 64; i++) s += y2[(long)(r0 + i) * CC + c];
    atomicAdd(&pool[b * CC + c], s);
}

__global__ void catt_kernel(const float* __restrict__ pool,
        const float* __restrict__ caw1, const float* __restrict__ cab1,
        const float* __restrict__ caw2, const float* __restrict__ cab2,
        float* __restrict__ catt) {
    __shared__ float sq[2][8];
    int tid = threadIdx.x;
    if (tid < 12) {
        int b = tid / 6, j = tid % 6;
        float s = cab1[j];
        for (int c = 0; c < CC; c++)
            s += (pool[b * CC + c] * (1.f / LL)) * caw1[j * CC + c];
        sq[b][j] = fmaxf(s, 0.f);
    }
    __syncthreads();
    if (tid < CC) {
        for (int b = 0; b < 2; b++) {
            float s = cab2[tid];
#pragma unroll
            for (int j = 0; j < 6; j++) s += sq[b][j] * caw2[tid * 6 + j];
            catt[b * CC + tid] = 1.f / (1.f + __expf(-s));
        }
    }
}

// ---------------- TF32 MMA flash attention ----------------
// block = (q-tile 128, win*6+head); 256 thr = 8 warps (4x2)
// smem: Qs[128][36] Ks[128][36] (tf32), Vs[32][132] (tf32, [d][k]),
//       Ss[128][132] (f32 scores -> tf32 P in place), fs[128]
#define ATTN_SMEM ((128 * 36 * 2 + 32 * 132 + 128 * 132 + 128) * 4)
__global__ void __launch_bounds__(256) attn_mma(const float* __restrict__ qkv,
        const float* __restrict__ biasQ, float* __restrict__ outp) {
    extern __shared__ char smraw[];
    uint32_t* Qs = (uint32_t*)smraw;
    uint32_t* Ks = Qs + 128 * 36;
    uint32_t* Vs = Ks + 128 * 36;
    float* Ss = (float*)(Vs + 32 * 132);
    float* fs = Ss + 128 * 132;

    const int qt = blockIdx.x;
    const int win = blockIdx.y / NHEADS, hh = blockIdx.y % NHEADS;
    const float* qb = qkv + (((win * 3 + 0) * NHEADS + hh) * NTOK + qt * 128) * HDIM;
    const float* kb = qkv + ((win * 3 + 1) * NHEADS + hh) * NTOK * HDIM;
    const float* vb = qkv + ((win * 3 + 2) * NHEADS + hh) * NTOK * HDIM;
    const float* bq = biasQ + ((long)(hh * NTOK) + qt * 128) * NTOK;

    const int tid = threadIdx.x;
    const int w = tid >> 5, lane = tid & 31, g = lane >> 2, lc = lane & 3;
    const int wm = w >> 1, wn = w & 1;

    for (int idx = tid; idx < 128 * 32; idx += 256) {
        int r = idx >> 5, d = idx & 31;
        Qs[r * 36 + d] = f2tf((d < HDIM) ? qb[r * HDIM + d] : 0.f);
    }

    const int srow = w * 16 + (lane >> 1);
    const int shalf = lane & 1;
    float m_run = -1e30f, l_run = 0.f;
    float oacc[2][2][4] = {};

    for (int t0 = 0; t0 < NTOK; t0 += 128) {
        __syncthreads();
        for (int idx = tid; idx < 128 * 32; idx += 256) {
            int r = idx >> 5, d = idx & 31;
            Ks[r * 36 + d] = f2tf((d < HDIM) ? kb[(t0 + r) * HDIM + d] : 0.f);
            Vs[d * 132 + r] = f2tf((d < HDIM) ? vb[(t0 + r) * HDIM + d] : 0.f);
        }
        __syncthreads();

        // S = Q K^T : warp tile 32(q) x 64(k)
        float sacc[2][8][4] = {};
#pragma unroll
        for (int ks = 0; ks < 4; ks++) {
            uint32_t a[2][4];
#pragma unroll
            for (int mt = 0; mt < 2; mt++) {
                int r = wm * 32 + mt * 16 + g;
                a[mt][0] = Qs[r * 36 + lc + 8 * ks];
                a[mt][1] = Qs[(r + 8) * 36 + lc + 8 * ks];
                a[mt][2] = Qs[r * 36 + lc + 4 + 8 * ks];
                a[mt][3] = Qs[(r + 8) * 36 + lc + 4 + 8 * ks];
            }
#pragma unroll
            for (int nt = 0; nt < 8; nt++) {
                int c = wn * 64 + nt * 8 + g;
                uint32_t b[2];
                b[0] = Ks[c * 36 + lc + 8 * ks];
                b[1] = Ks[c * 36 + lc + 4 + 8 * ks];
#pragma unroll
                for (int mt = 0; mt < 2; mt++) mma8(sacc[mt][nt], a[mt], b);
            }
        }
        // bias add + store S to smem
#pragma unroll
        for (int mt = 0; mt < 2; mt++)
#pragma unroll
            for (int nt = 0; nt < 8; nt++) {
                int r0 = wm * 32 + mt * 16 + g;
                int c0 = wn * 64 + nt * 8 + lc * 2;
                float2 b0 = *(const float2*)&bq[(long)r0 * NTOK + t0 + c0];
                float2 b1 = *(const float2*)&bq[(long)(r0 + 8) * NTOK + t0 + c0];
                Ss[r0 * 132 + c0]       = sacc[mt][nt][0] + b0.x;
                Ss[r0 * 132 + c0 + 1]   = sacc[mt][nt][1] + b0.y;
                Ss[(r0 + 8) * 132 + c0]     = sacc[mt][nt][2] + b1.x;
                Ss[(r0 + 8) * 132 + c0 + 1] = sacc[mt][nt][3] + b1.y;
            }
        __syncthreads();

        // online softmax: lane pair per row, strided cols
        float* rowp = Ss + srow * 132;
        float tmax = -1e30f;
#pragma unroll
        for (int j = 0; j < 64; j++) tmax = fmaxf(tmax, rowp[shalf + 2 * j]);
        tmax = fmaxf(tmax, __shfl_xor_sync(~0u, tmax, 1));
        float newm = fmaxf(m_run, tmax);
        float f = __expf(m_run - newm);
        float ssum = 0.f;
#pragma unroll
        for (int j = 0; j < 64; j++) {
            float e = __expf(rowp[shalf + 2 * j] - newm);
            ssum += e;
            ((uint32_t*)rowp)[shalf + 2 * j] = f2tf(e);
        }
        ssum += __shfl_xor_sync(~0u, ssum, 1);
        l_run = l_run * f + ssum;
        m_run = newm;
        if (!shalf) fs[srow] = f;
        __syncthreads();

        // rescale O, then O += P @ V : warp tile 32(q) x 16(d)
        uint32_t* Ps = (uint32_t*)Ss;
#pragma unroll
        for (int mt = 0; mt < 2; mt++) {
            int r = wm * 32 + mt * 16 + g;
            float f0 = fs[r], f1 = fs[r + 8];
#pragma unroll
            for (int nt = 0; nt < 2; nt++) {
                oacc[mt][nt][0] *= f0; oacc[mt][nt][1] *= f0;
                oacc[mt][nt][2] *= f1; oacc[mt][nt][3] *= f1;
            }
        }
#pragma unroll
        for (int ks = 0; ks < 16; ks++) {
            uint32_t a[2][4];
#pragma unroll
            for (int mt = 0; mt < 2; mt++) {
                int r = wm * 32 + mt * 16 + g;
                a[mt][0] = Ps[r * 132 + lc + 8 * ks];
                a[mt][1] = Ps[(r + 8) * 132 + lc + 8 * ks];
                a[mt][2] = Ps[r * 132 + lc + 4 + 8 * ks];
                a[mt][3] = Ps[(r + 8) * 132 + lc + 4 + 8 * ks];
            }
#pragma unroll
            for (int nt = 0; nt < 2; nt++) {
                int c = wn * 16 + nt * 8 + g;
                uint32_t b[2];
                b[0] = Vs[c * 132 + lc + 8 * ks];
                b[1] = Vs[c * 132 + lc + 4 + 8 * ks];
#pragma unroll
                for (int mt = 0; mt < 2; mt++) mma8(oacc[mt][nt], a[mt], b);
            }
        }
    }

    __syncthreads();
    if (!shalf) fs[srow] = 1.f / l_run;
    __syncthreads();

    float* ob = outp + (long)(win * NTOK + qt * 128) * CP + hh * HDIM;
#pragma unroll
    for (int mt = 0; mt < 2; mt++) {
        int r = wm * 32 + mt * 16 + g;
        float i0 = fs[r], i1 = fs[r + 8];
#pragma unroll
        for (int nt = 0; nt < 2; nt++) {
            int c = wn * 16 + nt * 8 + lc * 2;
            if (c < HDIM) {
                ob[(long)r * CP + c] = oacc[mt][nt][0] * i0;
                ob[(long)(r + 8) * CP + c] = oacc[mt][nt][2] * i1;
                if (c + 1 < HDIM) {
                    ob[(long)r * CP + c + 1] = oacc[mt][nt][1] * i0;
                    ob[(long)(r + 8) * CP + c + 1] = oacc[mt][nt][3] * i1;
                }
            }
        }
    }
}

// ---------------- host launch ----------------
extern "C" void kernel_launch(void* const* d_in, const int* in_sizes, int n_in,
                              void* d_out, int out_size) {
    const float* x      = (const float*)d_in[0];
    const int*   rpi    = (const int*)  d_in[4];
    const float* g1     = (const float*)d_in[7];
    const float* b1     = (const float*)d_in[8];
    const float* qkv_w  = (const float*)d_in[9];
    const float* qkv_b  = (const float*)d_in[10];
    const float* rpb    = (const float*)d_in[11];
    const float* proj_w = (const float*)d_in[12];
    const float* proj_b = (const float*)d_in[13];
    const float* cw1    = (const float*)d_in[14];
    const float* cb1    = (const float*)d_in[15];
    const float* cw2    = (const float*)d_in[16];
    const float* cb2    = (const float*)d_in[17];
    const float* caw1   = (const float*)d_in[18];
    const float* cab1   = (const float*)d_in[19];
    const float* caw2   = (const float*)d_in[20];
    const float* cab2   = (const float*)d_in[21];
    const float* g2     = (const float*)d_in[22];
    const float* b2     = (const float*)d_in[23];
    const float* fc1_w  = (const float*)d_in[24];
    const float* fc1_b  = (const float*)d_in[25];
    const float* fc2_w  = (const float*)d_in[26];
    const float* fc2_b  = (const float*)d_in[27];
    float* outp = (float*)d_out;

    float *p_xn, *p_ln2, *p_x1, *p_y1, *p_y2, *p_qkv, *p_ao, *p_h, *p_bt;
    float *p_w1m, *p_w2m, *p_pool, *p_catt;
    cudaGetSymbolAddress((void**)&p_xn,   g_xn);
    cudaGetSymbolAddress((void**)&p_ln2,  g_ln2);
    cudaGetSymbolAddress((void**)&p_x1,   g_x1);
    cudaGetSymbolAddress((void**)&p_y1,   g_y1);
    cudaGetSymbolAddress((void**)&p_y2,   g_y2);
    cudaGetSymbolAddress((void**)&p_qkv,  g_qkv);
    cudaGetSymbolAddress((void**)&p_ao,   g_ao);
    cudaGetSymbolAddress((void**)&p_h,    g_hbuf);
    cudaGetSymbolAddress((void**)&p_bt,   g_biasT);
    cudaGetSymbolAddress((void**)&p_w1m,  g_w1m);
    cudaGetSymbolAddress((void**)&p_w2m,  g_w2m);
    cudaGetSymbolAddress((void**)&p_pool, g_pool);
    cudaGetSymbolAddress((void**)&p_catt, g_catt);

    cudaFuncSetAttribute(attn_mma, cudaFuncAttributeMaxDynamicSharedMemorySize, ATTN_SMEM);

    // prep
    repack1_kernel<<<(27 * 64 * 192 + 255) / 256, 256>>>(cw1, p_w1m);
    repack2_kernel<<<(27 * 192 * 64 + 255) / 256, 256>>>(cw2, p_w2m);
    biasprep_kernel<<<512, 512>>>(rpi, rpb, p_bt);
    zero_pool_kernel<<<1, 384>>>(p_pool);

    // LN1 (write padded stride 192; pad columns stay zero from static init)
    ln_kernel<<<LT / 8, 256>>>(x, CC, g1, b1, p_xn, CP);

    // CAB conv branch (tensor-core implicit GEMM)
    mma_conv<1><<<dim3(LT / 128, 1), 256>>>(p_xn, p_w1m, cb1, p_y1);
    mma_conv<2><<<dim3(LT / 128, 3), 256>>>(p_y1, p_w2m, cb2, p_y2);
    pooled_kernel<<<LT / 64, 192>>>(p_y2, p_pool);
    catt_kernel<<<1, 192>>>(p_pool, caw1, cab1, caw2, cab2, p_catt);

    // window attention path
    mma_gemm<0, true><<<dim3(LT / 128, 9), 256>>>(p_xn, CP, qkv_w, qkv_b, p_qkv,
                                                  540, 180, 12, nullptr, nullptr, nullptr);
    attn_mma<<<dim3(4, NWIN * NHEADS), 256, ATTN_SMEM>>>(p_qkv, p_bt, p_ao);
    mma_gemm<1, false><<<dim3(LT / 128, 3), 256>>>(p_ao, CP, proj_w, proj_b, p_x1,
                                                   180, 180, 12, x, p_y2, p_catt);

    // MLP
    ln_kernel<<<LT / 8, 256>>>(p_x1, CC, g2, b2, p_ln2, CP);
    mma_gemm<2, false><<<dim3(LT / 128, 12), 256>>>(p_ln2, CP, fc1_w, fc1_b, p_h,
                                                    720, 180, 12, nullptr, nullptr, nullptr);
    mma_gemm<3, false><<<dim3(LT / 128, 3), 256>>>(p_h, HIDD, fc2_w, fc2_b, outp,
                                                   180, 720, 45, p_x1, nullptr, nullptr);
}

// round 5
// speedup vs baseline: 3.4350x; 1.4022x over previous
#include <cuda_runtime.h>
#include <math.h>
#include <stdint.h>

// ---------------- problem constants ----------------
#define BB 2
#define CC 180
#define CP 192              // padded channel stride (multiple of 16)
#define DD 16
#define HH 32
#define WW 32
#define LL 16384            // D*H*W
#define LT 32768            // B*L
#define NHEADS 6
#define HDIM 30
#define NTOK 512
#define NWIN 64
#define NTAB 3375
#define HIDD 720
#define QSCALE 0.18257418583505537f  // 30^-0.5

// ---------------- device scratch (zero-initialized; pads never written) ----------------
__device__ float g_xn[LT * CP];
__device__ float g_ln2[LT * CP];
__device__ float g_ao[LT * CP];                 // attention output (window order), padded
__device__ float g_x1[LT * CC];
__device__ float g_y1[LT * 64];                 // conv1 out, padded to 64 ch, gelu'd
__device__ float g_y2[LT * CC];                 // conv2 out + bias
__device__ float g_qkv[NWIN * 3 * NHEADS * NTOK * HDIM];
__device__ float g_hbuf[LT * HIDD];             // fc1 gelu out
__device__ float g_biasT[NHEADS * NTOK * NTOK]; // [h][query][key]
__device__ float g_w1m[27 * 64 * 192];          // [tap][cout64][cin192]
__device__ float g_w2m[27 * 192 * 64];          // [tap][cout192][cin64]
__device__ float g_pool[2 * CC];
__device__ float g_catt[2 * CC];

// window (win, n) -> flat row b*LL + l  (bijection)
__device__ __forceinline__ int win_src_row(int r) {
    int win = r >> 9, n = r & 511;
    int sb = win >> 2, wq = win & 3;
    int b = sb >> 3, isp = sb & 7;
    int id = isp >> 2, ih = (isp >> 1) & 1, iw = isp & 1;
    int nhi = wq >> 1, nwi = wq & 1;
    int wd = n >> 6, wh = (n >> 3) & 7, ww = n & 7;
    int d = wd * 2 + id;
    int h = (nhi * 8 + wh) * 2 + ih;
    int w = (nwi * 8 + ww) * 2 + iw;
    return ((b * DD + d) * HH + h) * WW + w;
}

__device__ __forceinline__ float gelu_exact(float v) {
    return 0.5f * v * (1.f + erff(v * 0.70710678118654752f));
}

// pack two floats -> bf16x2 (lo = first, hi = second)
__device__ __forceinline__ uint32_t pk(float lo, float hi) {
    uint32_t r;
    asm("cvt.rn.bf16x2.f32 %0, %1, %2;" : "=r"(r) : "f"(hi), "f"(lo));
    return r;
}

__device__ __forceinline__ void mma16(float* c, const uint32_t* a, const uint32_t* b) {
    asm volatile(
        "mma.sync.aligned.m16n8k16.row.col.f32.bf16.bf16.f32 "
        "{%0,%1,%2,%3},{%4,%5,%6,%7},{%8,%9},{%0,%1,%2,%3};\n"
        : "+f"(c[0]), "+f"(c[1]), "+f"(c[2]), "+f"(c[3])
        : "r"(a[0]), "r"(a[1]), "r"(a[2]), "r"(a[3]), "r"(b[0]), "r"(b[1]));
}

// one BK=16 tile (packed bf16x2 words, 8 per row), warp tile 32x32, 2x4 m16n8k16 frags
__device__ __forceinline__ void tile_mma(const uint32_t (*As)[12], const uint32_t (*Bs)[12],
                                         float acc[2][4][4], int wm, int wn, int lr, int lc) {
    uint32_t a[2][4], b[4][2];
#pragma unroll
    for (int mt = 0; mt < 2; mt++) {
        int r = wm * 32 + mt * 16 + lr;
        a[mt][0] = As[r][lc];
        a[mt][1] = As[r + 8][lc];
        a[mt][2] = As[r][lc + 4];
        a[mt][3] = As[r + 8][lc + 4];
    }
#pragma unroll
    for (int nt = 0; nt < 4; nt++) {
        int c2 = wn * 32 + nt * 8 + lr;
        b[nt][0] = Bs[c2][lc];
        b[nt][1] = Bs[c2][lc + 4];
    }
#pragma unroll
    for (int mt = 0; mt < 2; mt++)
#pragma unroll
        for (int nt = 0; nt < 4; nt++)
            mma16(acc[mt][nt], a[mt], b[nt]);
}

// ---------------- small prep kernels ----------------
__global__ void repack1_kernel(const float* __restrict__ cw1, float* __restrict__ w1m) {
    int idx = blockIdx.x * 256 + threadIdx.x;
    if (idx >= 27 * 64 * 192) return;
    int tap = idx / (64 * 192);
    int rem = idx - tap * 64 * 192;
    int o = rem / 192, c = rem - o * 192;
    w1m[idx] = (o < 60 && c < 180) ? cw1[(o * 180 + c) * 27 + tap] : 0.f;
}

__global__ void repack2_kernel(const float* __restrict__ cw2, float* __restrict__ w2m) {
    int idx = blockIdx.x * 256 + threadIdx.x;
    if (idx >= 27 * 192 * 64) return;
    int tap = idx / (192 * 64);
    int rem = idx - tap * 192 * 64;
    int o = rem >> 6, c = rem & 63;
    w2m[idx] = (o < 180 && c < 60) ? cw2[(o * 60 + c) * 27 + tap] : 0.f;
}

// bias table: [h][query][key]
__global__ void biasprep_kernel(const int* __restrict__ rpi, const float* __restrict__ rpb,
                                float* __restrict__ biasT) {
    int q = blockIdx.x, k = threadIdx.x;
    int t = rpi[q * 512 + k];
#pragma unroll
    for (int h = 0; h < NHEADS; h++)
        biasT[(h * 512 + q) * 512 + k] = rpb[t * NHEADS + h];
}

__global__ void zero_pool_kernel(float* __restrict__ pool) {
    if (threadIdx.x < 2 * CC) pool[threadIdx.x] = 0.f;
}

// ---------------- layernorm (warp per row) ----------------
__global__ void __launch_bounds__(256) ln_kernel(const float* __restrict__ in, int ins,
        const float* __restrict__ gg, const float* __restrict__ bb,
        float* __restrict__ outp, int outs) {
    int row = blockIdx.x * 8 + (threadIdx.x >> 5);
    int lane = threadIdx.x & 31;
    const float* p = in + (long)row * ins;
    float v[6];
    float s = 0.f;
#pragma unroll
    for (int i = 0; i < 6; i++) {
        int c = lane + i * 32;
        v[i] = (c < CC) ? p[c] : 0.f;
        s += v[i];
    }
    for (int o = 16; o; o >>= 1) s += __shfl_xor_sync(~0u, s, o);
    float mean = s * (1.f / CC);
    float vs = 0.f;
#pragma unroll
    for (int i = 0; i < 6; i++) {
        int c = lane + i * 32;
        float d = (c < CC) ? (v[i] - mean) : 0.f;
        vs += d * d;
    }
    for (int o = 16; o; o >>= 1) vs += __shfl_xor_sync(~0u, vs, o);
    float inv = rsqrtf(vs * (1.f / CC) + 1e-5f);
    float* q = outp + (long)row * outs;
#pragma unroll
    for (int i = 0; i < 6; i++) {
        int c = lane + i * 32;
        if (c < CC) q[c] = (v[i] - mean) * inv * gg[c] + bb[c];
    }
}

// ---------------- bf16 MMA GEMM: C = A @ W^T + bias, fused epilogues ----------------
// BM=128 BN=64 BK=16, 256 thr (8 warps as 4x2), double-buffered smem
// EPI 0: qkv scatter (+q scale); 1: proj scatter + triple residual; 2: gelu; 3: residual->out
template <int EPI, bool GATHER>
__global__ void __launch_bounds__(256) mma_gemm(
        const float* __restrict__ A, int Asr,
        const float* __restrict__ Wm, const float* __restrict__ bias,
        float* __restrict__ Cout, int Nc, int K, int T,
        const float* __restrict__ e0, const float* __restrict__ e1,
        const float* __restrict__ e2) {
    __shared__ uint32_t As[2][128][12];
    __shared__ uint32_t Bs[2][64][12];
    const int tid = threadIdx.x;
    const int row0 = blockIdx.x * 128, col0 = blockIdx.y * 64;

    int ar[2], akq[2];
    long abase[2];
#pragma unroll
    for (int i = 0; i < 2; i++) {
        int id = tid + i * 256;
        ar[i] = id >> 2;
        akq[i] = id & 3;
        int r = row0 + ar[i];
        int src = GATHER ? win_src_row(r) : r;
        abase[i] = (long)src * Asr + akq[i] * 4;
    }
    const int bn = tid >> 2, bkq = tid & 3;
    const int bcol = col0 + bn;

    const int wid = tid >> 5, lane = tid & 31, lr = lane >> 2, lc = lane & 3;
    const int wm = wid >> 1, wn = wid & 1;
    float acc[2][4][4] = {};

    auto loadT = [&](int t, int buf) {
        int k0 = t * 16;
#pragma unroll
        for (int i = 0; i < 2; i++) {
            float4 v = *(const float4*)(A + abase[i] + k0);
            *(uint2*)&As[buf][ar[i]][akq[i] * 2] = make_uint2(pk(v.x, v.y), pk(v.z, v.w));
        }
        int k = k0 + bkq * 4;
        float4 v = make_float4(0.f, 0.f, 0.f, 0.f);
        if (bcol < Nc && k < K) v = *(const float4*)(Wm + (long)bcol * K + k);
        *(uint2*)&Bs[buf][bn][bkq * 2] = make_uint2(pk(v.x, v.y), pk(v.z, v.w));
    };

    loadT(0, 0);
    __syncthreads();
    for (int t = 0; t < T; t++) {
        if (t + 1 < T) loadT(t + 1, (t + 1) & 1);
        tile_mma(As[t & 1], Bs[t & 1], acc, wm, wn, lr, lc);
        __syncthreads();
    }

#pragma unroll
    for (int mt = 0; mt < 2; mt++) {
#pragma unroll
        for (int nt = 0; nt < 4; nt++) {
            int rbase = row0 + wm * 32 + mt * 16 + lr;
            int cbase = col0 + wn * 32 + nt * 8 + lc * 2;
#pragma unroll
            for (int e = 0; e < 4; e++) {
                int row = rbase + (e >> 1) * 8;
                int col = cbase + (e & 1);
                if (col >= Nc) continue;
                float v = acc[mt][nt][e] + bias[col];
                if constexpr (EPI == 0) {
                    int tq = col / 180;
                    int rem = col - tq * 180;
                    int hh = rem / 30, hd = rem - hh * 30;
                    if (tq == 0) v *= QSCALE;
                    int win = row >> 9, n = row & 511;
                    Cout[(((win * 3 + tq) * NHEADS + hh) * NTOK + n) * HDIM + hd] = v;
                } else if constexpr (EPI == 1) {
                    int src = win_src_row(row);
                    long gi = (long)src * CC + col;
                    int b = src >> 14;
                    Cout[gi] = e0[gi] + v + 0.01f * e1[gi] * e2[b * CC + col];
                } else if constexpr (EPI == 2) {
                    Cout[(long)row * Nc + col] = gelu_exact(v);
                } else {
                    long gi = (long)row * CC + col;
                    Cout[gi] = e0[gi] + v;
                }
            }
        }
    }
}

// ---------------- bf16 MMA implicit-GEMM 3x3x3 conv ----------------
template <int CV>
__global__ void __launch_bounds__(256) mma_conv(
        const float* __restrict__ A, const float* __restrict__ Wt,
        const float* __restrict__ bias, float* __restrict__ Out) {
    constexpr int Asr = (CV == 1) ? 192 : 64;
    constexpr int KT = (CV == 1) ? 12 : 4;
    constexpr int T = 27 * KT;
    constexpr int Wn = (CV == 1) ? 64 : 192;
    constexpr int Wk = (CV == 1) ? 192 : 64;
    __shared__ uint32_t As[2][128][12];
    __shared__ uint32_t Bs[2][64][12];
    const int tid = threadIdx.x;
    const int row0 = blockIdx.x * 128, col0 = blockIdx.y * 64;

    int ar[2], akq[2], pd[2], ph[2], pw[2];
#pragma unroll
    for (int i = 0; i < 2; i++) {
        int id = tid + i * 256;
        ar[i] = id >> 2;
        akq[i] = id & 3;
        int p = row0 + ar[i];
        pd[i] = (p >> 10) & 15;
        ph[i] = (p >> 5) & 31;
        pw[i] = p & 31;
    }
    const int bn = tid >> 2, bkq = tid & 3;

    const int wid = tid >> 5, lane = tid & 31, lr = lane >> 2, lc = lane & 3;
    const int wm = wid >> 1, wn = wid & 1;
    float acc[2][4][4] = {};

    auto loadT = [&](int t, int buf) {
        int tap = t / KT;
        int kt = t - tap * KT;
        int k0 = kt * 16;
        int kd = tap / 9 - 1;
        int r9 = tap - (kd + 1) * 9;
        int kh = r9 / 3 - 1;
        int kw = r9 - (kh + 1) * 3 - 1;
        int off = (kd << 10) + (kh << 5) + kw;
#pragma unroll
        for (int i = 0; i < 2; i++) {
            bool valid = ((unsigned)(pd[i] + kd) < 16u) &&
                         ((unsigned)(ph[i] + kh) < 32u) &&
                         ((unsigned)(pw[i] + kw) < 32u);
            float4 v = make_float4(0.f, 0.f, 0.f, 0.f);
            if (valid)
                v = *(const float4*)(A + (long)(row0 + ar[i] + off) * Asr + k0 + akq[i] * 4);
            *(uint2*)&As[buf][ar[i]][akq[i] * 2] = make_uint2(pk(v.x, v.y), pk(v.z, v.w));
        }
        float4 v = *(const float4*)(Wt + ((long)tap * Wn + col0 + bn) * Wk + k0 + bkq * 4);
        *(uint2*)&Bs[buf][bn][bkq * 2] = make_uint2(pk(v.x, v.y), pk(v.z, v.w));
    };

    loadT(0, 0);
    __syncthreads();
    for (int t = 0; t < T; t++) {
        if (t + 1 < T) loadT(t + 1, (t + 1) & 1);
        tile_mma(As[t & 1], Bs[t & 1], acc, wm, wn, lr, lc);
        __syncthreads();
    }

#pragma unroll
    for (int mt = 0; mt < 2; mt++) {
#pragma unroll
        for (int nt = 0; nt < 4; nt++) {
            int rbase = row0 + wm * 32 + mt * 16 + lr;
            int cbase = col0 + wn * 32 + nt * 8 + lc * 2;
#pragma unroll
            for (int e = 0; e < 4; e++) {
                int row = rbase + (e >> 1) * 8;
                int col = cbase + (e & 1);
                float v = acc[mt][nt][e];
                if constexpr (CV == 1) {
                    v += (col < 60) ? bias[col] : 0.f;
                    Out[(long)row * 64 + col] = gelu_exact(v);
                } else {
                    if (col < CC) Out[(long)row * CC + col] = v + bias[col];
                }
            }
        }
    }
}

// ---------------- pooled sum + channel attention ----------------
__global__ void pooled_kernel(const float* __restrict__ y2, float* __restrict__ pool) {
    int r0 = blockIdx.x * 64;
    int b = r0 >> 14;
    int c = threadIdx.x;
    if (c >= CC) return;
    float s = 0.f;
    for (int i = 0; i < 64; i++) s += y2[(long)(r0 + i) * CC + c];
    atomicAdd(&pool[b * CC + c], s);
}

__global__ void catt_kernel(const float* __restrict__ pool,
        const float* __restrict__ caw1, const float* __restrict__ cab1,
        const float* __restrict__ caw2, const float* __restrict__ cab2,
        float* __restrict__ catt) {
    __shared__ float sq[2][8];
    int tid = threadIdx.x;
    if (tid < 12) {
        int b = tid / 6, j = tid % 6;
        float s = cab1[j];
        for (int c = 0; c < CC; c++)
            s += (pool[b * CC + c] * (1.f / LL)) * caw1[j * CC + c];
        sq[b][j] = fmaxf(s, 0.f);
    }
    __syncthreads();
    if (tid < CC) {
        for (int b = 0; b < 2; b++) {
            float s = cab2[tid];
#pragma unroll
            for (int j = 0; j < 6; j++) s += sq[b][j] * caw2[tid * 6 + j];
            catt[b * CC + tid] = 1.f / (1.f + __expf(-s));
        }
    }
}

// ---------------- bf16 MMA flash attention ----------------
// block = (q-tile 128, win*6+head); 256 thr = 8 warps (4x2)
// smem (words): Qs[128][18] Ks[128][18] packed bf16x2 (32 k-elems = 16 words + pad),
//   Vs[32][68] packed [d][kpair], Ss[128][132] f32 scores (P repacked in place), fs[128]
#define ATTN_WORDS (128 * 18 * 2 + 32 * 68 + 128 * 132 + 128)
#define ATTN_SMEM (ATTN_WORDS * 4)
__global__ void __launch_bounds__(256) attn_mma(const float* __restrict__ qkv,
        const float* __restrict__ biasQ, float* __restrict__ outp) {
    extern __shared__ char smraw[];
    uint32_t* Qs = (uint32_t*)smraw;
    uint32_t* Ks = Qs + 128 * 18;
    uint32_t* Vs = Ks + 128 * 18;
    float* Ss = (float*)(Vs + 32 * 68);
    float* fs = Ss + 128 * 132;

    const int qt = blockIdx.x;
    const int win = blockIdx.y / NHEADS, hh = blockIdx.y % NHEADS;
    const float* qb = qkv + (((win * 3 + 0) * NHEADS + hh) * NTOK + qt * 128) * HDIM;
    const float* kb = qkv + ((win * 3 + 1) * NHEADS + hh) * NTOK * HDIM;
    const float* vb = qkv + ((win * 3 + 2) * NHEADS + hh) * NTOK * HDIM;
    const float* bq = biasQ + ((long)(hh * NTOK) + qt * 128) * NTOK;

    const int tid = threadIdx.x;
    const int w = tid >> 5, lane = tid & 31, g = lane >> 2, lc = lane & 3;
    const int wm = w >> 1, wn = w & 1;

    // Q: 128 rows x 16 packed words (cols 30,31 zero)
    for (int idx = tid; idx < 128 * 16; idx += 256) {
        int r = idx >> 4, d = idx & 15;
        float lo = (2 * d < HDIM) ? qb[r * HDIM + 2 * d] : 0.f;
        float hi = (2 * d + 1 < HDIM) ? qb[r * HDIM + 2 * d + 1] : 0.f;
        Qs[r * 18 + d] = pk(lo, hi);
    }

    const int srow = w * 16 + (lane >> 1);
    const int shalf = lane & 1;
    float m_run = -1e30f, l_run = 0.f;
    float oacc[2][2][4] = {};

    for (int t0 = 0; t0 < NTOK; t0 += 128) {
        __syncthreads();
        for (int idx = tid; idx < 128 * 16; idx += 256) {
            int r = idx >> 4, d = idx & 15;
            float lo = (2 * d < HDIM) ? kb[(t0 + r) * HDIM + 2 * d] : 0.f;
            float hi = (2 * d + 1 < HDIM) ? kb[(t0 + r) * HDIM + 2 * d + 1] : 0.f;
            Ks[r * 18 + d] = pk(lo, hi);
        }
        // V transposed: Vs[d][j] = {V[2j][d], V[2j+1][d]}
        for (int idx = tid; idx < 32 * 64; idx += 256) {
            int d = idx >> 6, j = idx & 63;
            float lo = (d < HDIM) ? vb[(t0 + 2 * j) * HDIM + d] : 0.f;
            float hi = (d < HDIM) ? vb[(t0 + 2 * j + 1) * HDIM + d] : 0.f;
            Vs[d * 68 + j] = pk(lo, hi);
        }
        __syncthreads();

        // S = Q K^T : warp tile 32(q) x 64(k), K-dim 32 elems = 2 k16 steps
        float sacc[2][8][4] = {};
#pragma unroll
        for (int ks = 0; ks < 2; ks++) {
            uint32_t a[2][4];
#pragma unroll
            for (int mt = 0; mt < 2; mt++) {
                int r = wm * 32 + mt * 16 + g;
                a[mt][0] = Qs[r * 18 + lc + 8 * ks];
                a[mt][1] = Qs[(r + 8) * 18 + lc + 8 * ks];
                a[mt][2] = Qs[r * 18 + lc + 4 + 8 * ks];
                a[mt][3] = Qs[(r + 8) * 18 + lc + 4 + 8 * ks];
            }
#pragma unroll
            for (int nt = 0; nt < 8; nt++) {
                int c = wn * 64 + nt * 8 + g;
                uint32_t b[2];
                b[0] = Ks[c * 18 + lc + 8 * ks];
                b[1] = Ks[c * 18 + lc + 4 + 8 * ks];
#pragma unroll
                for (int mt = 0; mt < 2; mt++) mma16(sacc[mt][nt], a[mt], b);
            }
        }
        // bias add + store S (f32) to smem
#pragma unroll
        for (int mt = 0; mt < 2; mt++)
#pragma unroll
            for (int nt = 0; nt < 8; nt++) {
                int r0 = wm * 32 + mt * 16 + g;
                int c0 = wn * 64 + nt * 8 + lc * 2;
                float2 b0 = *(const float2*)&bq[(long)r0 * NTOK + t0 + c0];
                float2 b1 = *(const float2*)&bq[(long)(r0 + 8) * NTOK + t0 + c0];
                Ss[r0 * 132 + c0]       = sacc[mt][nt][0] + b0.x;
                Ss[r0 * 132 + c0 + 1]   = sacc[mt][nt][1] + b0.y;
                Ss[(r0 + 8) * 132 + c0]     = sacc[mt][nt][2] + b1.x;
                Ss[(r0 + 8) * 132 + c0 + 1] = sacc[mt][nt][3] + b1.y;
            }
        __syncthreads();

        // online softmax: lane pair per row; each half-lane owns contiguous 64 keys.
        // P packed bf16x2 in place: word j <- cols (2j, 2j+1); write idx <= read idx -> safe.
        float* rowp = Ss + srow * 132;
        uint32_t* prow = (uint32_t*)rowp;
        float tmax = -1e30f;
#pragma unroll
        for (int j = 0; j < 64; j++) tmax = fmaxf(tmax, rowp[shalf * 64 + j]);
        tmax = fmaxf(tmax, __shfl_xor_sync(~0u, tmax, 1));
        float newm = fmaxf(m_run, tmax);
        float f = __expf(m_run - newm);
        float ssum = 0.f;
#pragma unroll
        for (int j = 0; j < 32; j++) {
            float e0 = __expf(rowp[shalf * 64 + 2 * j] - newm);
            float e1 = __expf(rowp[shalf * 64 + 2 * j + 1] - newm);
            ssum += e0 + e1;
            prow[shalf * 32 + j] = pk(e0, e1);
        }
        ssum += __shfl_xor_sync(~0u, ssum, 1);
        l_run = l_run * f + ssum;
        m_run = newm;
        if (!shalf) fs[srow] = f;
        __syncthreads();

        // rescale O, then O += P @ V : warp tile 32(q) x 16(d), 8 k16 steps
        uint32_t* Ps = (uint32_t*)Ss;
#pragma unroll
        for (int mt = 0; mt < 2; mt++) {
            int r = wm * 32 + mt * 16 + g;
            float f0 = fs[r], f1 = fs[r + 8];
#pragma unroll
            for (int nt = 0; nt < 2; nt++) {
                oacc[mt][nt][0] *= f0; oacc[mt][nt][1] *= f0;
                oacc[mt][nt][2] *= f1; oacc[mt][nt][3] *= f1;
            }
        }
#pragma unroll
        for (int ks = 0; ks < 8; ks++) {
            uint32_t a[2][4];
#pragma unroll
            for (int mt = 0; mt < 2; mt++) {
                int r = wm * 32 + mt * 16 + g;
                a[mt][0] = Ps[r * 132 + lc + 8 * ks];
                a[mt][1] = Ps[(r + 8) * 132 + lc + 8 * ks];
                a[mt][2] = Ps[r * 132 + lc + 4 + 8 * ks];
                a[mt][3] = Ps[(r + 8) * 132 + lc + 4 + 8 * ks];
            }
#pragma unroll
            for (int nt = 0; nt < 2; nt++) {
                int c = wn * 16 + nt * 8 + g;
                uint32_t b[2];
                b[0] = Vs[c * 68 + lc + 8 * ks];
                b[1] = Vs[c * 68 + lc + 4 + 8 * ks];
#pragma unroll
                for (int mt = 0; mt < 2; mt++) mma16(oacc[mt][nt], a[mt], b);
            }
        }
    }

    __syncthreads();
    if (!shalf) fs[srow] = 1.f / l_run;
    __syncthreads();

    float* ob = outp + (long)(win * NTOK + qt * 128) * CP + hh * HDIM;
#pragma unroll
    for (int mt = 0; mt < 2; mt++) {
        int r = wm * 32 + mt * 16 + g;
        float i0 = fs[r], i1 = fs[r + 8];
#pragma unroll
        for (int nt = 0; nt < 2; nt++) {
            int c = wn * 16 + nt * 8 + lc * 2;
            if (c < HDIM) {
                ob[(long)r * CP + c] = oacc[mt][nt][0] * i0;
                ob[(long)(r + 8) * CP + c] = oacc[mt][nt][2] * i1;
                if (c + 1 < HDIM) {
                    ob[(long)r * CP + c + 1] = oacc[mt][nt][1] * i0;
                    ob[(long)(r + 8) * CP + c + 1] = oacc[mt][nt][3] * i1;
                }
            }
        }
    }
}

// ---------------- host launch ----------------
extern "C" void kernel_launch(void* const* d_in, const int* in_sizes, int n_in,
                              void* d_out, int out_size) {
    const float* x      = (const float*)d_in[0];
    const int*   rpi    = (const int*)  d_in[4];
    const float* g1     = (const float*)d_in[7];
    const float* b1     = (const float*)d_in[8];
    const float* qkv_w  = (const float*)d_in[9];
    const float* qkv_b  = (const float*)d_in[10];
    const float* rpb    = (const float*)d_in[11];
    const float* proj_w = (const float*)d_in[12];
    const float* proj_b = (const float*)d_in[13];
    const float* cw1    = (const float*)d_in[14];
    const float* cb1    = (const float*)d_in[15];
    const float* cw2    = (const float*)d_in[16];
    const float* cb2    = (const float*)d_in[17];
    const float* caw1   = (const float*)d_in[18];
    const float* cab1   = (const float*)d_in[19];
    const float* caw2   = (const float*)d_in[20];
    const float* cab2   = (const float*)d_in[21];
    const float* g2     = (const float*)d_in[22];
    const float* b2     = (const float*)d_in[23];
    const float* fc1_w  = (const float*)d_in[24];
    const float* fc1_b  = (const float*)d_in[25];
    const float* fc2_w  = (const float*)d_in[26];
    const float* fc2_b  = (const float*)d_in[27];
    float* outp = (float*)d_out;

    float *p_xn, *p_ln2, *p_x1, *p_y1, *p_y2, *p_qkv, *p_ao, *p_h, *p_bt;
    float *p_w1m, *p_w2m, *p_pool, *p_catt;
    cudaGetSymbolAddress((void**)&p_xn,   g_xn);
    cudaGetSymbolAddress((void**)&p_ln2,  g_ln2);
    cudaGetSymbolAddress((void**)&p_x1,   g_x1);
    cudaGetSymbolAddress((void**)&p_y1,   g_y1);
    cudaGetSymbolAddress((void**)&p_y2,   g_y2);
    cudaGetSymbolAddress((void**)&p_qkv,  g_qkv);
    cudaGetSymbolAddress((void**)&p_ao,   g_ao);
    cudaGetSymbolAddress((void**)&p_h,    g_hbuf);
    cudaGetSymbolAddress((void**)&p_bt,   g_biasT);
    cudaGetSymbolAddress((void**)&p_w1m,  g_w1m);
    cudaGetSymbolAddress((void**)&p_w2m,  g_w2m);
    cudaGetSymbolAddress((void**)&p_pool, g_pool);
    cudaGetSymbolAddress((void**)&p_catt, g_catt);

    cudaFuncSetAttribute(attn_mma, cudaFuncAttributeMaxDynamicSharedMemorySize, ATTN_SMEM);

    // prep
    repack1_kernel<<<(27 * 64 * 192 + 255) / 256, 256>>>(cw1, p_w1m);
    repack2_kernel<<<(27 * 192 * 64 + 255) / 256, 256>>>(cw2, p_w2m);
    biasprep_kernel<<<512, 512>>>(rpi, rpb, p_bt);
    zero_pool_kernel<<<1, 384>>>(p_pool);

    // LN1 (write padded stride 192; pad columns stay zero from static init)
    ln_kernel<<<LT / 8, 256>>>(x, CC, g1, b1, p_xn, CP);

    // CAB conv branch (tensor-core implicit GEMM)
    mma_conv<1><<<dim3(LT / 128, 1), 256>>>(p_xn, p_w1m, cb1, p_y1);
    mma_conv<2><<<dim3(LT / 128, 3), 256>>>(p_y1, p_w2m, cb2, p_y2);
    pooled_kernel<<<LT / 64, 192>>>(p_y2, p_pool);
    catt_kernel<<<1, 192>>>(p_pool, caw1, cab1, caw2, cab2, p_catt);

    // window attention path
    mma_gemm<0, true><<<dim3(LT / 128, 9), 256>>>(p_xn, CP, qkv_w, qkv_b, p_qkv,
                                                  540, 180, 12, nullptr, nullptr, nullptr);
    attn_mma<<<dim3(4, NWIN * NHEADS), 256, ATTN_SMEM>>>(p_qkv, p_bt, p_ao);
    mma_gemm<1, false><<<dim3(LT / 128, 3), 256>>>(p_ao, CP, proj_w, proj_b, p_x1,
                                                   180, 180, 12, x, p_y2, p_catt);

    // MLP
    ln_kernel<<<LT / 8, 256>>>(p_x1, CC, g2, b2, p_ln2, CP);
    mma_gemm<2, false><<<dim3(LT / 128, 12), 256>>>(p_ln2, CP, fc1_w, fc1_b, p_h,
                                                    720, 180, 12, nullptr, nullptr, nullptr);
    mma_gemm<3, false><<<dim3(LT / 128, 3), 256>>>(p_h, HIDD, fc2_w, fc2_b, outp,
                                                   180, 720, 45, p_x1, nullptr, nullptr);
}

// round 7
// speedup vs baseline: 4.7174x; 1.3734x over previous
#include <cuda_runtime.h>
#include <math.h>
#include <stdint.h>

// ---------------- problem constants ----------------
#define BB 2
#define CC 180
#define CP 192              // padded channel stride (multiple of 32)
#define DD 16
#define HH 32
#define WW 32
#define LL 16384            // D*H*W
#define LT 32768            // B*L
#define NHEADS 6
#define HDIM 30
#define NTOK 512
#define NWIN 64
#define HIDD 720
#define HIDP 736            // padded fc2 K (multiple of 32)
#define QSCALE 0.18257418583505537f  // 30^-0.5

// ---------------- device scratch (zero-initialized; pads never written) ----------------
__device__ uint16_t g_xn[LT * CP];              // bf16, LN1 out
__device__ uint16_t g_ln2[LT * CP];             // bf16, LN2 out
__device__ uint16_t g_ao[LT * CP];              // bf16, attention out (window order)
__device__ float    g_x1[LT * CC];              // fp32 residual
__device__ uint16_t g_y1[LT * 64];              // bf16 conv1 out (gelu'd, 64-pad)
__device__ float    g_y2[LT * CC];              // fp32 conv2 out + bias
__device__ uint16_t g_qkv[NWIN * 3 * NHEADS * NTOK * HDIM];  // bf16
__device__ uint16_t g_hbuf[LT * HIDP];          // bf16 fc1 gelu out (K-pad 736)
__device__ uint16_t g_biasT[NHEADS * NTOK * NTOK]; // bf16 [h][query][key]
__device__ uint16_t g_w1m[27 * 64 * 192];       // bf16 [tap][cout64][cin192]
__device__ uint16_t g_w2m[27 * 192 * 64];       // bf16 [tap][cout192][cin64]
__device__ uint16_t g_wq[576 * 192];            // bf16 qkv_w (row-pad 576)
__device__ uint16_t g_wp[192 * 192];            // bf16 proj_w (row-pad 192)
__device__ uint16_t g_wf1[768 * 192];           // bf16 fc1_w (row-pad 768)
__device__ uint16_t g_wf2[192 * HIDP];          // bf16 fc2_w (row-pad 192)
__device__ float g_pool[2 * CC];
__device__ float g_catt[2 * CC];

// window (win, n) -> flat row b*LL + l  (bijection)
__device__ __forceinline__ int win_src_row(int r) {
    int win = r >> 9, n = r & 511;
    int sb = win >> 2, wq = win & 3;
    int b = sb >> 3, isp = sb & 7;
    int id = isp >> 2, ih = (isp >> 1) & 1, iw = isp & 1;
    int nhi = wq >> 1, nwi = wq & 1;
    int wd = n >> 6, wh = (n >> 3) & 7, ww = n & 7;
    int d = wd * 2 + id;
    int h = (nhi * 8 + wh) * 2 + ih;
    int w = (nwi * 8 + ww) * 2 + iw;
    return ((b * DD + d) * HH + h) * WW + w;
}

__device__ __forceinline__ float gelu_exact(float v) {
    return 0.5f * v * (1.f + erff(v * 0.70710678118654752f));
}

// pack two floats -> bf16x2 word (lo = first)
__device__ __forceinline__ uint32_t pk(float lo, float hi) {
    uint32_t r;
    asm("cvt.rn.bf16x2.f32 %0, %1, %2;" : "=r"(r) : "f"(hi), "f"(lo));
    return r;
}
__device__ __forceinline__ uint16_t f2b(float v) { return (uint16_t)pk(v, 0.f); }
__device__ __forceinline__ float b2f(uint32_t bits16) {
    return __int_as_float((int)(bits16 << 16));
}

__device__ __forceinline__ void mma16(float* c, const uint32_t* a, const uint32_t* b) {
    asm volatile(
        "mma.sync.aligned.m16n8k16.row.col.f32.bf16.bf16.f32 "
        "{%0,%1,%2,%3},{%4,%5,%6,%7},{%8,%9},{%0,%1,%2,%3};\n"
        : "+f"(c[0]), "+f"(c[1]), "+f"(c[2]), "+f"(c[3])
        : "r"(a[0]), "r"(a[1]), "r"(a[2]), "r"(a[3]), "r"(b[0]), "r"(b[1]));
}

// one BK=32 tile (rows = 16 packed words + 4 pad), warp tile 32x32, 2 k16 steps
__device__ __forceinline__ void tile_mma32(const uint32_t (*As)[20], const uint32_t (*Bs)[20],
                                           float acc[2][4][4], int wm, int wn, int lr, int lc) {
#pragma unroll
    for (int ks = 0; ks < 2; ks++) {
        uint32_t a[2][4], b[4][2];
#pragma unroll
        for (int mt = 0; mt < 2; mt++) {
            int r = wm * 32 + mt * 16 + lr;
            a[mt][0] = As[r][lc + 8 * ks];
            a[mt][1] = As[r + 8][lc + 8 * ks];
            a[mt][2] = As[r][lc + 4 + 8 * ks];
            a[mt][3] = As[r + 8][lc + 4 + 8 * ks];
        }
#pragma unroll
        for (int nt = 0; nt < 4; nt++) {
            int c2 = wn * 32 + nt * 8 + lr;
            b[nt][0] = Bs[c2][lc + 8 * ks];
            b[nt][1] = Bs[c2][lc + 4 + 8 * ks];
        }
#pragma unroll
        for (int mt = 0; mt < 2; mt++)
#pragma unroll
            for (int nt = 0; nt < 4; nt++)
                mma16(acc[mt][nt], a[mt], b[nt]);
    }
}

// ---------------- prep kernels ----------------
// generic dense weight prepack: out[n][Ksm] bf16 from w[n][K] fp32 (zero pad)
__global__ void wpack_kernel(const float* __restrict__ w, uint16_t* __restrict__ out,
                             int N, int K, int Ksm) {
    int idx = blockIdx.x * 256 + threadIdx.x;
    if (idx >= N * Ksm) return;
    int n = idx / Ksm, k = idx - n * Ksm;
    out[idx] = (k < K) ? f2b(w[n * K + k]) : (uint16_t)0;
}

__global__ void repack1_kernel(const float* __restrict__ cw1, uint16_t* __restrict__ w1m) {
    int idx = blockIdx.x * 256 + threadIdx.x;
    if (idx >= 27 * 64 * 192) return;
    int tap = idx / (64 * 192);
    int rem = idx - tap * 64 * 192;
    int o = rem / 192, c = rem - o * 192;
    w1m[idx] = (o < 60 && c < 180) ? f2b(cw1[(o * 180 + c) * 27 + tap]) : (uint16_t)0;
}

__global__ void repack2_kernel(const float* __restrict__ cw2, uint16_t* __restrict__ w2m) {
    int idx = blockIdx.x * 256 + threadIdx.x;
    if (idx >= 27 * 192 * 64) return;
    int tap = idx / (192 * 64);
    int rem = idx - tap * 192 * 64;
    int o = rem >> 6, c = rem & 63;
    w2m[idx] = (o < 180 && c < 60) ? f2b(cw2[(o * 60 + c) * 27 + tap]) : (uint16_t)0;
}

// bias table: [h][query][key] bf16
__global__ void biasprep_kernel(const int* __restrict__ rpi, const float* __restrict__ rpb,
                                uint16_t* __restrict__ biasT) {
    int q = blockIdx.x, k = threadIdx.x;
    int t = rpi[q * 512 + k];
#pragma unroll
    for (int h = 0; h < NHEADS; h++)
        biasT[(h * 512 + q) * 512 + k] = f2b(rpb[t * NHEADS + h]);
}

__global__ void zero_pool_kernel(float* __restrict__ pool) {
    if (threadIdx.x < 2 * CC) pool[threadIdx.x] = 0.f;
}

// ---------------- layernorm (warp per row), bf16 out ----------------
__global__ void __launch_bounds__(256) ln_kernel(const float* __restrict__ in, int ins,
        const float* __restrict__ gg, const float* __restrict__ bb,
        uint16_t* __restrict__ outp, int outs) {
    int row = blockIdx.x * 8 + (threadIdx.x >> 5);
    int lane = threadIdx.x & 31;
    const float* p = in + (long)row * ins;
    float v[6];
    float s = 0.f;
#pragma unroll
    for (int i = 0; i < 6; i++) {
        int c = lane + i * 32;
        v[i] = (c < CC) ? p[c] : 0.f;
        s += v[i];
    }
    for (int o = 16; o; o >>= 1) s += __shfl_xor_sync(~0u, s, o);
    float mean = s * (1.f / CC);
    float vs = 0.f;
#pragma unroll
    for (int i = 0; i < 6; i++) {
        int c = lane + i * 32;
        float d = (c < CC) ? (v[i] - mean) : 0.f;
        vs += d * d;
    }
    for (int o = 16; o; o >>= 1) vs += __shfl_xor_sync(~0u, vs, o);
    float inv = rsqrtf(vs * (1.f / CC) + 1e-5f);
    uint16_t* q = outp + (long)row * outs;
#pragma unroll
    for (int i = 0; i < 6; i++) {
        int c = lane + i * 32;
        if (c < CC) q[c] = f2b((v[i] - mean) * inv * gg[c] + bb[c]);
    }
}

// ---------------- bf16 MMA GEMM: C = A @ W^T + bias, BK=32, fused epilogues ----------------
// BM=128 BN=64, 256 thr (8 warps as 4x2), double-buffered smem
// EPI 0: qkv scatter bf16 (+q scale); 1: proj scatter + triple residual fp32;
//     2: gelu -> bf16 (stride OS); 3: residual -> fp32 out
template <int EPI, bool GATHER>
__global__ void __launch_bounds__(256) mma_gemm(
        const uint16_t* __restrict__ A, int Asr,
        const uint16_t* __restrict__ Wm, const float* __restrict__ bias,
        void* __restrict__ CoutV, int Nc, int Ksm, int OS,
        const float* __restrict__ e0, const float* __restrict__ e1,
        const float* __restrict__ e2) {
    __shared__ uint32_t As[2][128][20];
    __shared__ uint32_t Bs[2][64][20];
    const int tid = threadIdx.x;
    const int row0 = blockIdx.x * 128, col0 = blockIdx.y * 64;
    const int T = Ksm >> 5;

    // loaders: 4 threads per row, each thread = 8 bf16 elements (one uint4)
    int ar[2], akq[2];
    long abase[2];
#pragma unroll
    for (int i = 0; i < 2; i++) {
        int id = tid + i * 256;
        ar[i] = id >> 2;
        akq[i] = id & 3;
        int r = row0 + ar[i];
        int src = GATHER ? win_src_row(r) : r;
        abase[i] = (long)src * Asr + akq[i] * 8;
    }
    const int bn = tid >> 2, bkq = tid & 3;
    const long bbase = (long)(col0 + bn) * Ksm + bkq * 8;

    const int wid = tid >> 5, lane = tid & 31, lr = lane >> 2, lc = lane & 3;
    const int wm = wid >> 1, wn = wid & 1;
    float acc[2][4][4] = {};

    auto loadT = [&](int t, int buf) {
        int k0 = t * 32;
#pragma unroll
        for (int i = 0; i < 2; i++)
            *(uint4*)&As[buf][ar[i]][akq[i] * 4] = *(const uint4*)(A + abase[i] + k0);
        *(uint4*)&Bs[buf][bn][bkq * 4] = *(const uint4*)(Wm + bbase + k0);
    };

    loadT(0, 0);
    __syncthreads();
    for (int t = 0; t < T; t++) {
        if (t + 1 < T) loadT(t + 1, (t + 1) & 1);
        tile_mma32(As[t & 1], Bs[t & 1], acc, wm, wn, lr, lc);
        __syncthreads();
    }

#pragma unroll
    for (int mt = 0; mt < 2; mt++) {
#pragma unroll
        for (int nt = 0; nt < 4; nt++) {
            int rbase = row0 + wm * 32 + mt * 16 + lr;
            int cb = col0 + wn * 32 + nt * 8 + lc * 2;   // even
            if (cb >= Nc) continue;
#pragma unroll
            for (int half = 0; half < 2; half++) {
                int row = rbase + half * 8;
                float v0 = acc[mt][nt][half * 2] + bias[cb];
                float v1 = acc[mt][nt][half * 2 + 1] + bias[cb + 1];
                if constexpr (EPI == 0) {
                    int tq = cb / 180;
                    int rem = cb - tq * 180;
                    int hh = rem / 30, hd = rem - hh * 30;   // hd even
                    if (tq == 0) { v0 *= QSCALE; v1 *= QSCALE; }
                    int win = row >> 9, n = row & 511;
                    long idx = ((long)((win * 3 + tq) * NHEADS + hh) * NTOK + n) * HDIM + hd;
                    ((uint32_t*)CoutV)[idx >> 1] = pk(v0, v1);
                } else if constexpr (EPI == 1) {
                    int src = win_src_row(row);
                    long gi = (long)src * CC + cb;
                    int b = src >> 14;
                    float* Cf = (float*)CoutV;
                    Cf[gi]     = e0[gi]     + v0 + 0.01f * e1[gi]     * e2[b * CC + cb];
                    Cf[gi + 1] = e0[gi + 1] + v1 + 0.01f * e1[gi + 1] * e2[b * CC + cb + 1];
                } else if constexpr (EPI == 2) {
                    long idx = (long)row * OS + cb;
                    ((uint32_t*)CoutV)[idx >> 1] = pk(gelu_exact(v0), gelu_exact(v1));
                } else {
                    long gi = (long)row * CC + cb;
                    float* Cf = (float*)CoutV;
                    Cf[gi]     = e0[gi]     + v0;
                    Cf[gi + 1] = e0[gi + 1] + v1;
                }
            }
        }
    }
}

// ---------------- bf16 MMA implicit-GEMM 3x3x3 conv, BK=32 ----------------
template <int CV>
__global__ void __launch_bounds__(256) mma_conv(
        const uint16_t* __restrict__ A, const uint16_t* __restrict__ Wt,
        const float* __restrict__ bias, void* __restrict__ OutV) {
    constexpr int Asr = (CV == 1) ? 192 : 64;
    constexpr int KT = (CV == 1) ? 6 : 2;      // 32-wide k-tiles per tap
    constexpr int T = 27 * KT;
    constexpr int Wn = (CV == 1) ? 64 : 192;
    constexpr int Wk = (CV == 1) ? 192 : 64;
    __shared__ uint32_t As[2][128][20];
    __shared__ uint32_t Bs[2][64][20];
    const int tid = threadIdx.x;
    const int row0 = blockIdx.x * 128, col0 = blockIdx.y * 64;

    int ar[2], akq[2], pd[2], ph[2], pw[2];
#pragma unroll
    for (int i = 0; i < 2; i++) {
        int id = tid + i * 256;
        ar[i] = id >> 2;
        akq[i] = id & 3;
        int p = row0 + ar[i];
        pd[i] = (p >> 10) & 15;
        ph[i] = (p >> 5) & 31;
        pw[i] = p & 31;
    }
    const int bn = tid >> 2, bkq = tid & 3;

    const int wid = tid >> 5, lane = tid & 31, lr = lane >> 2, lc = lane & 3;
    const int wm = wid >> 1, wn = wid & 1;
    float acc[2][4][4] = {};

    auto loadT = [&](int t, int buf) {
        int tap = t / KT;
        int kt = t - tap * KT;
        int k0 = kt * 32;
        int kd = tap / 9 - 1;
        int r9 = tap - (kd + 1) * 9;
        int kh = r9 / 3 - 1;
        int kw = r9 - (kh + 1) * 3 - 1;
        int off = (kd << 10) + (kh << 5) + kw;
#pragma unroll
        for (int i = 0; i < 2; i++) {
            bool valid = ((unsigned)(pd[i] + kd) < 16u) &&
                         ((unsigned)(ph[i] + kh) < 32u) &&
                         ((unsigned)(pw[i] + kw) < 32u);
            uint4 v = make_uint4(0u, 0u, 0u, 0u);
            if (valid)
                v = *(const uint4*)(A + (long)(row0 + ar[i] + off) * Asr + k0 + akq[i] * 8);
            *(uint4*)&As[buf][ar[i]][akq[i] * 4] = v;
        }
        *(uint4*)&Bs[buf][bn][bkq * 4] =
            *(const uint4*)(Wt + ((long)tap * Wn + col0 + bn) * Wk + k0 + bkq * 8);
    };

    loadT(0, 0);
    __syncthreads();
    for (int t = 0; t < T; t++) {
        if (t + 1 < T) loadT(t + 1, (t + 1) & 1);
        tile_mma32(As[t & 1], Bs[t & 1], acc, wm, wn, lr, lc);
        __syncthreads();
    }

#pragma unroll
    for (int mt = 0; mt < 2; mt++) {
#pragma unroll
        for (int nt = 0; nt < 4; nt++) {
            int rbase = row0 + wm * 32 + mt * 16 + lr;
            int cb = col0 + wn * 32 + nt * 8 + lc * 2;   // even
#pragma unroll
            for (int half = 0; half < 2; half++) {
                int row = rbase + half * 8;
                float v0 = acc[mt][nt][half * 2];
                float v1 = acc[mt][nt][half * 2 + 1];
                if constexpr (CV == 1) {
                    v0 = gelu_exact(v0 + ((cb < 60) ? bias[cb] : 0.f));
                    v1 = gelu_exact(v1 + ((cb + 1 < 60) ? bias[cb + 1] : 0.f));
                    ((uint32_t*)OutV)[((long)row * 64 + cb) >> 1] = pk(v0, v1);
                } else {
                    if (cb < CC) {
                        float* Of = (float*)OutV;
                        Of[(long)row * CC + cb] = v0 + bias[cb];
                        if (cb + 1 < CC) Of[(long)row * CC + cb + 1] = v1 + bias[cb + 1];
                    }
                }
            }
        }
    }
}

// ---------------- pooled sum + channel attention ----------------
__global__ void pooled_kernel(const float* __restrict__ y2, float* __restrict__ pool) {
    int r0 = blockIdx.x * 64;
    int b = r0 >> 14;
    int c = threadIdx.x;
    if (c >= CC) return;
    float s = 0.f;
    for (int i = 0; i < 64; i++) s += y2[(long)(r0 + i) * CC + c];
    atomicAdd(&pool[b * CC + c], s);
}

__global__ void catt_kernel(const float* __restrict__ pool,
        const float* __restrict__ caw1, const float* __restrict__ cab1,
        const float* __restrict__ caw2, const float* __restrict__ cab2,
        float* __restrict__ catt) {
    __shared__ float sq[2][8];
    int tid = threadIdx.x;
    if (tid < 12) {
        int b = tid / 6, j = tid % 6;
        float s = cab1[j];
        for (int c = 0; c < CC; c++)
            s += (pool[b * CC + c] * (1.f / LL)) * caw1[j * CC + c];
        sq[b][j] = fmaxf(s, 0.f);
    }
    __syncthreads();
    if (tid < CC) {
        for (int b = 0; b < 2; b++) {
            float s = cab2[tid];
#pragma unroll
            for (int j = 0; j < 6; j++) s += sq[b][j] * caw2[tid * 6 + j];
            catt[b * CC + tid] = 1.f / (1.f + __expf(-s));
        }
    }
}

// ---------------- bf16 MMA flash attention ----------------
// block = (q-tile 128, win*6+head); 256 thr = 8 warps (4x2)
// smem (words): Qs[128][18] Ks[128][18] packed bf16x2 from bf16 gmem (direct copy),
//   Vs[32][68] packed [d][kpair], Ss[128][132] f32 scores (P repacked in place), fs[128]
#define ATTN_WORDS (128 * 18 * 2 + 32 * 68 + 128 * 132 + 128)
#define ATTN_SMEM (ATTN_WORDS * 4)
__global__ void __launch_bounds__(256) attn_mma(const uint16_t* __restrict__ qkv,
        const uint16_t* __restrict__ biasQ, uint16_t* __restrict__ outp) {
    extern __shared__ char smraw[];
    uint32_t* Qs = (uint32_t*)smraw;
    uint32_t* Ks = Qs + 128 * 18;
    uint32_t* Vs = Ks + 128 * 18;
    float* Ss = (float*)(Vs + 32 * 68);
    float* fs = Ss + 128 * 132;

    const int qt = blockIdx.x;
    const int win = blockIdx.y / NHEADS, hh = blockIdx.y % NHEADS;
    const uint32_t* qbu = (const uint32_t*)(qkv +
        ((long)((win * 3 + 0) * NHEADS + hh) * NTOK + qt * 128) * HDIM);
    const uint32_t* kbu = (const uint32_t*)(qkv +
        (long)((win * 3 + 1) * NHEADS + hh) * NTOK * HDIM);
    const uint16_t* vb = qkv + (long)((win * 3 + 2) * NHEADS + hh) * NTOK * HDIM;
    const uint16_t* bq = biasQ + ((long)(hh * NTOK) + qt * 128) * NTOK;

    const int tid = threadIdx.x;
    const int w = tid >> 5, lane = tid & 31, g = lane >> 2, lc = lane & 3;
    const int wm = w >> 1, wn = w & 1;

    // Q: 128 rows x 16 words (15 data words = 30 bf16, word 15 zero)
    for (int idx = tid; idx < 128 * 16; idx += 256) {
        int r = idx >> 4, d = idx & 15;
        Qs[r * 18 + d] = (d < 15) ? qbu[r * 15 + d] : 0u;
    }

    const int srow = w * 16 + (lane >> 1);
    const int shalf = lane & 1;
    float m_run = -1e30f, l_run = 0.f;
    float oacc[2][2][4] = {};

    for (int t0 = 0; t0 < NTOK; t0 += 128) {
        __syncthreads();
        for (int idx = tid; idx < 128 * 16; idx += 256) {
            int r = idx >> 4, d = idx & 15;
            Ks[r * 18 + d] = (d < 15) ? kbu[(t0 + r) * 15 + d] : 0u;
        }
        // V transposed: Vs[d][j] = {V[2j][d], V[2j+1][d]}
        for (int idx = tid; idx < 32 * 64; idx += 256) {
            int d = idx >> 6, j = idx & 63;
            uint32_t u = 0u;
            if (d < HDIM) {
                uint32_t lo = vb[(long)(t0 + 2 * j) * HDIM + d];
                uint32_t hi = vb[(long)(t0 + 2 * j + 1) * HDIM + d];
                u = lo | (hi << 16);
            }
            Vs[d * 68 + j] = u;
        }
        __syncthreads();

        // S = Q K^T : warp tile 32(q) x 64(k)
        float sacc[2][8][4] = {};
#pragma unroll
        for (int ks = 0; ks < 2; ks++) {
            uint32_t a[2][4];
#pragma unroll
            for (int mt = 0; mt < 2; mt++) {
                int r = wm * 32 + mt * 16 + g;
                a[mt][0] = Qs[r * 18 + lc + 8 * ks];
                a[mt][1] = Qs[(r + 8) * 18 + lc + 8 * ks];
                a[mt][2] = Qs[r * 18 + lc + 4 + 8 * ks];
                a[mt][3] = Qs[(r + 8) * 18 + lc + 4 + 8 * ks];
            }
#pragma unroll
            for (int nt = 0; nt < 8; nt++) {
                int c = wn * 64 + nt * 8 + g;
                uint32_t b[2];
                b[0] = Ks[c * 18 + lc + 8 * ks];
                b[1] = Ks[c * 18 + lc + 4 + 8 * ks];
#pragma unroll
                for (int mt = 0; mt < 2; mt++) mma16(sacc[mt][nt], a[mt], b);
            }
        }
        // bias add (bf16 words) + store S (f32) to smem
        const uint32_t* bqu = (const uint32_t*)bq;
#pragma unroll
        for (int mt = 0; mt < 2; mt++)
#pragma unroll
            for (int nt = 0; nt < 8; nt++) {
                int r0 = wm * 32 + mt * 16 + g;
                int c0 = wn * 64 + nt * 8 + lc * 2;   // even
                uint32_t u0 = bqu[((long)r0 * NTOK + t0 + c0) >> 1];
                uint32_t u1 = bqu[((long)(r0 + 8) * NTOK + t0 + c0) >> 1];
                Ss[r0 * 132 + c0]           = sacc[mt][nt][0] + b2f(u0 & 0xFFFF);
                Ss[r0 * 132 + c0 + 1]       = sacc[mt][nt][1] + b2f(u0 >> 16);
                Ss[(r0 + 8) * 132 + c0]     = sacc[mt][nt][2] + b2f(u1 & 0xFFFF);
                Ss[(r0 + 8) * 132 + c0 + 1] = sacc[mt][nt][3] + b2f(u1 >> 16);
            }
        __syncthreads();

        // online softmax: lane pair per row; each half-lane owns contiguous 64 keys.
        float* rowp = Ss + srow * 132;
        uint32_t* prow = (uint32_t*)rowp;
        float tmax = -1e30f;
#pragma unroll
        for (int j = 0; j < 64; j++) tmax = fmaxf(tmax, rowp[shalf * 64 + j]);
        tmax = fmaxf(tmax, __shfl_xor_sync(~0u, tmax, 1));
        float newm = fmaxf(m_run, tmax);
        float f = __expf(m_run - newm);
        float ssum = 0.f;
#pragma unroll
        for (int j = 0; j < 32; j++) {
            float e0 = __expf(rowp[shalf * 64 + 2 * j] - newm);
            float e1 = __expf(rowp[shalf * 64 + 2 * j + 1] - newm);
            ssum += e0 + e1;
            prow[shalf * 32 + j] = pk(e0, e1);
        }
        ssum += __shfl_xor_sync(~0u, ssum, 1);
        l_run = l_run * f + ssum;
        m_run = newm;
        if (!shalf) fs[srow] = f;
        __syncthreads();

        // rescale O, then O += P @ V : warp tile 32(q) x 16(d), 8 k16 steps
        uint32_t* Ps = (uint32_t*)Ss;
#pragma unroll
        for (int mt = 0; mt < 2; mt++) {
            int r = wm * 32 + mt * 16 + g;
            float f0 = fs[r], f1 = fs[r + 8];
#pragma unroll
            for (int nt = 0; nt < 2; nt++) {
                oacc[mt][nt][0] *= f0; oacc[mt][nt][1] *= f0;
                oacc[mt][nt][2] *= f1; oacc[mt][nt][3] *= f1;
            }
        }
#pragma unroll
        for (int ks = 0; ks < 8; ks++) {
            uint32_t a[2][4];
#pragma unroll
            for (int mt = 0; mt < 2; mt++) {
                int r = wm * 32 + mt * 16 + g;
                a[mt][0] = Ps[r * 132 + lc + 8 * ks];
                a[mt][1] = Ps[(r + 8) * 132 + lc + 8 * ks];
                a[mt][2] = Ps[r * 132 + lc + 4 + 8 * ks];
                a[mt][3] = Ps[(r + 8) * 132 + lc + 4 + 8 * ks];
            }
#pragma unroll
            for (int nt = 0; nt < 2; nt++) {
                int c = wn * 16 + nt * 8 + g;
                uint32_t b[2];
                b[0] = Vs[c * 68 + lc + 8 * ks];
                b[1] = Vs[c * 68 + lc + 4 + 8 * ks];
#pragma unroll
                for (int mt = 0; mt < 2; mt++) mma16(oacc[mt][nt], a[mt], b);
            }
        }
    }

    __syncthreads();
    if (!shalf) fs[srow] = 1.f / l_run;
    __syncthreads();

    uint16_t* ob = outp + (long)(win * NTOK + qt * 128) * CP + hh * HDIM;
#pragma unroll
    for (int mt = 0; mt < 2; mt++) {
        int r = wm * 32 + mt * 16 + g;
        float i0 = fs[r], i1 = fs[r + 8];
#pragma unroll
        for (int nt = 0; nt < 2; nt++) {
            int c = wn * 16 + nt * 8 + lc * 2;   // even
            if (c < HDIM) {
                *(uint32_t*)&ob[(long)r * CP + c] =
                    pk(oacc[mt][nt][0] * i0, oacc[mt][nt][1] * i0);
                *(uint32_t*)&ob[(long)(r + 8) * CP + c] =
                    pk(oacc[mt][nt][2] * i1, oacc[mt][nt][3] * i1);
            }
        }
    }
}

// ---------------- host launch ----------------
extern "C" void kernel_launch(void* const* d_in, const int* in_sizes, int n_in,
                              void* d_out, int out_size) {
    const float* x      = (const float*)d_in[0];
    const int*   rpi    = (const int*)  d_in[4];
    const float* g1     = (const float*)d_in[7];
    const float* b1     = (const float*)d_in[8];
    const float* qkv_w  = (const float*)d_in[9];
    const float* qkv_b  = (const float*)d_in[10];
    const float* rpb    = (const float*)d_in[11];
    const float* proj_w = (const float*)d_in[12];
    const float* proj_b = (const float*)d_in[13];
    const float* cw1    = (const float*)d_in[14];
    const float* cb1    = (const float*)d_in[15];
    const float* cw2    = (const float*)d_in[16];
    const float* cb2    = (const float*)d_in[17];
    const float* caw1   = (const float*)d_in[18];
    const float* cab1   = (const float*)d_in[19];
    const float* caw2   = (const float*)d_in[20];
    const float* cab2   = (const float*)d_in[21];
    const float* g2     = (const float*)d_in[22];
    const float* b2     = (const float*)d_in[23];
    const float* fc1_w  = (const float*)d_in[24];
    const float* fc1_b  = (const float*)d_in[25];
    const float* fc2_w  = (const float*)d_in[26];
    const float* fc2_b  = (const float*)d_in[27];
    float* outp = (float*)d_out;

    uint16_t *p_xn, *p_ln2, *p_ao, *p_y1, *p_qkv, *p_h, *p_bt;
    uint16_t *p_w1m, *p_w2m, *p_wq, *p_wp, *p_wf1, *p_wf2;
    float *p_x1, *p_y2, *p_pool, *p_catt;
    cudaGetSymbolAddress((void**)&p_xn,   g_xn);
    cudaGetSymbolAddress((void**)&p_ln2,  g_ln2);
    cudaGetSymbolAddress((void**)&p_ao,   g_ao);
    cudaGetSymbolAddress((void**)&p_x1,   g_x1);
    cudaGetSymbolAddress((void**)&p_y1,   g_y1);
    cudaGetSymbolAddress((void**)&p_y2,   g_y2);
    cudaGetSymbolAddress((void**)&p_qkv,  g_qkv);
    cudaGetSymbolAddress((void**)&p_h,    g_hbuf);
    cudaGetSymbolAddress((void**)&p_bt,   g_biasT);
    cudaGetSymbolAddress((void**)&p_w1m,  g_w1m);
    cudaGetSymbolAddress((void**)&p_w2m,  g_w2m);
    cudaGetSymbolAddress((void**)&p_wq,   g_wq);
    cudaGetSymbolAddress((void**)&p_wp,   g_wp);
    cudaGetSymbolAddress((void**)&p_wf1,  g_wf1);
    cudaGetSymbolAddress((void**)&p_wf2,  g_wf2);
    cudaGetSymbolAddress((void**)&p_pool, g_pool);
    cudaGetSymbolAddress((void**)&p_catt, g_catt);

    cudaFuncSetAttribute(attn_mma, cudaFuncAttributeMaxDynamicSharedMemorySize, ATTN_SMEM);

    // prep: weight/bias repack to bf16
    repack1_kernel<<<(27 * 64 * 192 + 255) / 256, 256>>>(cw1, p_w1m);
    repack2_kernel<<<(27 * 192 * 64 + 255) / 256, 256>>>(cw2, p_w2m);
    wpack_kernel<<<(540 * 192 + 255) / 256, 256>>>(qkv_w, p_wq, 540, 180, 192);
    wpack_kernel<<<(180 * 192 + 255) / 256, 256>>>(proj_w, p_wp, 180, 180, 192);
    wpack_kernel<<<(720 * 192 + 255) / 256, 256>>>(fc1_w, p_wf1, 720, 180, 192);
    wpack_kernel<<<(180 * HIDP + 255) / 256, 256>>>(fc2_w, p_wf2, 180, 720, HIDP);
    biasprep_kernel<<<512, 512>>>(rpi, rpb, p_bt);
    zero_pool_kernel<<<1, 384>>>(p_pool);

    // LN1 -> bf16 (stride 192; pads stay zero from static init)
    ln_kernel<<<LT / 8, 256>>>(x, CC, g1, b1, p_xn, CP);

    // CAB conv branch
    mma_conv<1><<<dim3(LT / 128, 1), 256>>>(p_xn, p_w1m, cb1, p_y1);
    mma_conv<2><<<dim3(LT / 128, 3), 256>>>(p_y1, p_w2m, cb2, p_y2);
    pooled_kernel<<<LT / 64, 192>>>(p_y2, p_pool);
    catt_kernel<<<1, 192>>>(p_pool, caw1, cab1, caw2, cab2, p_catt);

    // window attention path
    mma_gemm<0, true><<<dim3(LT / 128, 9), 256>>>(p_xn, CP, p_wq, qkv_b, p_qkv,
                                                  540, 192, 0, nullptr, nullptr, nullptr);
    attn_mma<<<dim3(4, NWIN * NHEADS), 256, ATTN_SMEM>>>(p_qkv, p_bt, p_ao);
    mma_gemm<1, false><<<dim3(LT / 128, 3), 256>>>(p_ao, CP, p_wp, proj_b, p_x1,
                                                   180, 192, 0, x, p_y2, p_catt);

    // MLP
    ln_kernel<<<LT / 8, 256>>>(p_x1, CC, g2, b2, p_ln2, CP);
    mma_gemm<2, false><<<dim3(LT / 128, 12), 256>>>(p_ln2, CP, p_wf1, fc1_b, p_h,
                                                    720, 192, HIDP, nullptr, nullptr, nullptr);
    mma_gemm<3, false><<<dim3(LT / 128, 3), 256>>>(p_h, HIDP, p_wf2, fc2_b, outp,
                                                   180, HIDP, 0, p_x1, nullptr, nullptr);
}

// round 8
// speedup vs baseline: 4.9968x; 1.0592x over previous
#include <cuda_runtime.h>
#include <math.h>
#include <stdint.h>

// ---------------- problem constants ----------------
#define BB 2
#define CC 180
#define CP 192              // padded channel stride (multiple of 32)
#define DD 16
#define HH 32
#define WW 32
#define LL 16384            // D*H*W
#define LT 32768            // B*L
#define NHEADS 6
#define HDIM 30
#define NTOK 512
#define NWIN 64
#define HIDD 720
#define HIDP 736            // padded fc2 K (multiple of 32)
#define QSCALE 0.18257418583505537f  // 30^-0.5

// ---------------- device scratch (zero-initialized; pads never written) ----------------
__device__ uint16_t g_xn[LT * CP];              // bf16, LN1 out
__device__ uint16_t g_ln2[LT * CP];             // bf16, LN2 out
__device__ uint16_t g_ao[LT * CP];              // bf16, attention out (window order)
__device__ float    g_x1[LT * CC];              // fp32 residual
__device__ uint16_t g_y1[LT * 64];              // bf16 conv1 out (gelu'd, 64-pad)
__device__ float    g_y2[LT * CC];              // fp32 conv2 out + bias
__device__ uint16_t g_qkv[NWIN * 3 * NHEADS * NTOK * HDIM];  // bf16
__device__ uint16_t g_hbuf[LT * HIDP];          // bf16 fc1 gelu out (K-pad 736)
__device__ uint16_t g_biasT[NHEADS * NTOK * NTOK]; // bf16 [h][query][key]
__device__ uint16_t g_w1m[27 * 64 * 192];       // bf16 [tap][cout64][cin192]
__device__ uint16_t g_w2m[27 * 192 * 64];       // bf16 [tap][cout192][cin64]
__device__ uint16_t g_wq[576 * 192];            // bf16 qkv_w (row-pad 576)
__device__ uint16_t g_wp[192 * 192];            // bf16 proj_w (row-pad 192)
__device__ uint16_t g_wf1[768 * 192];           // bf16 fc1_w (row-pad 768)
__device__ uint16_t g_wf2[192 * HIDP];          // bf16 fc2_w (row-pad 192)
__device__ float g_pool[2 * CC];
__device__ float g_catt[2 * CC];

// window (win, n) -> flat row b*LL + l  (bijection)
__device__ __forceinline__ int win_src_row(int r) {
    int win = r >> 9, n = r & 511;
    int sb = win >> 2, wq = win & 3;
    int b = sb >> 3, isp = sb & 7;
    int id = isp >> 2, ih = (isp >> 1) & 1, iw = isp & 1;
    int nhi = wq >> 1, nwi = wq & 1;
    int wd = n >> 6, wh = (n >> 3) & 7, ww = n & 7;
    int d = wd * 2 + id;
    int h = (nhi * 8 + wh) * 2 + ih;
    int w = (nwi * 8 + ww) * 2 + iw;
    return ((b * DD + d) * HH + h) * WW + w;
}

__device__ __forceinline__ float gelu_exact(float v) {
    return 0.5f * v * (1.f + erff(v * 0.70710678118654752f));
}

// pack two floats -> bf16x2 word (lo = first)
__device__ __forceinline__ uint32_t pk(float lo, float hi) {
    uint32_t r;
    asm("cvt.rn.bf16x2.f32 %0, %1, %2;" : "=r"(r) : "f"(hi), "f"(lo));
    return r;
}
__device__ __forceinline__ uint16_t f2b(float v) { return (uint16_t)pk(v, 0.f); }
__device__ __forceinline__ float b2f(uint32_t bits16) {
    return __int_as_float((int)(bits16 << 16));
}

__device__ __forceinline__ void mma16(float* c, const uint32_t* a, const uint32_t* b) {
    asm volatile(
        "mma.sync.aligned.m16n8k16.row.col.f32.bf16.bf16.f32 "
        "{%0,%1,%2,%3},{%4,%5,%6,%7},{%8,%9},{%0,%1,%2,%3};\n"
        : "+f"(c[0]), "+f"(c[1]), "+f"(c[2]), "+f"(c[3])
        : "r"(a[0]), "r"(a[1]), "r"(a[2]), "r"(a[3]), "r"(b[0]), "r"(b[1]));
}

// ldmatrix x4 (b16): 4 8x8 matrices; lane i of each 8-lane group supplies a row address
__device__ __forceinline__ void ldsm4(uint32_t* r, const void* p) {
    uint32_t addr = (uint32_t)__cvta_generic_to_shared(p);
    asm volatile("ldmatrix.sync.aligned.m8n8.x4.shared.b16 {%0,%1,%2,%3}, [%4];"
        : "=r"(r[0]), "=r"(r[1]), "=r"(r[2]), "=r"(r[3]) : "r"(addr));
}

// one BK=32 tile via ldmatrix: warp tile 32x32, 2 k16 steps
// A-frag lanes: row = base + (lane&15), word = ks*8 + (lane>>4)*4
// B-pair lanes: row = base + ((lane>>4)<<3) + (lane&7), word = ks*8 + ((lane>>3)&1)*4
__device__ __forceinline__ void tile_mma32(const uint32_t (*As)[20], const uint32_t (*Bs)[20],
                                           float acc[2][4][4], int wm, int wn, int lane) {
    const int ar = wm * 32 + (lane & 15);
    const int aw = (lane >> 4) * 4;
    const int br = wn * 32 + ((lane >> 4) << 3) + (lane & 7);
    const int bw = ((lane >> 3) & 1) * 4;
#pragma unroll
    for (int ks = 0; ks < 2; ks++) {
        uint32_t a[2][4], b[2][4];
        ldsm4(a[0], &As[ar][ks * 8 + aw]);
        ldsm4(a[1], &As[ar + 16][ks * 8 + aw]);
        ldsm4(b[0], &Bs[br][ks * 8 + bw]);
        ldsm4(b[1], &Bs[br + 16][ks * 8 + bw]);
#pragma unroll
        for (int mt = 0; mt < 2; mt++)
#pragma unroll
            for (int p = 0; p < 2; p++) {
                mma16(acc[mt][p * 2],     a[mt], b[p]);
                mma16(acc[mt][p * 2 + 1], a[mt], b[p] + 2);
            }
    }
}

// ---------------- prep kernels ----------------
__global__ void wpack_kernel(const float* __restrict__ w, uint16_t* __restrict__ out,
                             int N, int K, int Ksm) {
    int idx = blockIdx.x * 256 + threadIdx.x;
    if (idx >= N * Ksm) return;
    int n = idx / Ksm, k = idx - n * Ksm;
    out[idx] = (k < K) ? f2b(w[n * K + k]) : (uint16_t)0;
}

__global__ void repack1_kernel(const float* __restrict__ cw1, uint16_t* __restrict__ w1m) {
    int idx = blockIdx.x * 256 + threadIdx.x;
    if (idx >= 27 * 64 * 192) return;
    int tap = idx / (64 * 192);
    int rem = idx - tap * 64 * 192;
    int o = rem / 192, c = rem - o * 192;
    w1m[idx] = (o < 60 && c < 180) ? f2b(cw1[(o * 180 + c) * 27 + tap]) : (uint16_t)0;
}

__global__ void repack2_kernel(const float* __restrict__ cw2, uint16_t* __restrict__ w2m) {
    int idx = blockIdx.x * 256 + threadIdx.x;
    if (idx >= 27 * 192 * 64) return;
    int tap = idx / (192 * 64);
    int rem = idx - tap * 192 * 64;
    int o = rem >> 6, c = rem & 63;
    w2m[idx] = (o < 180 && c < 60) ? f2b(cw2[(o * 60 + c) * 27 + tap]) : (uint16_t)0;
}

// bias table: [h][query][key] bf16
__global__ void biasprep_kernel(const int* __restrict__ rpi, const float* __restrict__ rpb,
                                uint16_t* __restrict__ biasT) {
    int q = blockIdx.x, k = threadIdx.x;
    int t = rpi[q * 512 + k];
#pragma unroll
    for (int h = 0; h < NHEADS; h++)
        biasT[(h * 512 + q) * 512 + k] = f2b(rpb[t * NHEADS + h]);
}

__global__ void zero_pool_kernel(float* __restrict__ pool) {
    if (threadIdx.x < 2 * CC) pool[threadIdx.x] = 0.f;
}

// ---------------- layernorm (warp per row), bf16 out ----------------
__global__ void __launch_bounds__(256) ln_kernel(const float* __restrict__ in, int ins,
        const float* __restrict__ gg, const float* __restrict__ bb,
        uint16_t* __restrict__ outp, int outs) {
    int row = blockIdx.x * 8 + (threadIdx.x >> 5);
    int lane = threadIdx.x & 31;
    const float* p = in + (long)row * ins;
    float v[6];
    float s = 0.f;
#pragma unroll
    for (int i = 0; i < 6; i++) {
        int c = lane + i * 32;
        v[i] = (c < CC) ? p[c] : 0.f;
        s += v[i];
    }
    for (int o = 16; o; o >>= 1) s += __shfl_xor_sync(~0u, s, o);
    float mean = s * (1.f / CC);
    float vs = 0.f;
#pragma unroll
    for (int i = 0; i < 6; i++) {
        int c = lane + i * 32;
        float d = (c < CC) ? (v[i] - mean) : 0.f;
        vs += d * d;
    }
    for (int o = 16; o; o >>= 1) vs += __shfl_xor_sync(~0u, vs, o);
    float inv = rsqrtf(vs * (1.f / CC) + 1e-5f);
    uint16_t* q = outp + (long)row * outs;
#pragma unroll
    for (int i = 0; i < 6; i++) {
        int c = lane + i * 32;
        if (c < CC) q[c] = f2b((v[i] - mean) * inv * gg[c] + bb[c]);
    }
}

// ---------------- bf16 MMA GEMM: C = A @ W^T + bias, BK=32, fused epilogues ----------------
template <int EPI, bool GATHER>
__global__ void __launch_bounds__(256) mma_gemm(
        const uint16_t* __restrict__ A, int Asr,
        const uint16_t* __restrict__ Wm, const float* __restrict__ bias,
        void* __restrict__ CoutV, int Nc, int Ksm, int OS,
        const float* __restrict__ e0, const float* __restrict__ e1,
        const float* __restrict__ e2) {
    __shared__ uint32_t As[2][128][20];
    __shared__ uint32_t Bs[2][64][20];
    const int tid = threadIdx.x;
    const int row0 = blockIdx.x * 128, col0 = blockIdx.y * 64;
    const int T = Ksm >> 5;

    // loaders: 4 threads per row, each thread = 8 bf16 elements (one uint4)
    int ar[2], akq[2];
    long abase[2];
#pragma unroll
    for (int i = 0; i < 2; i++) {
        int id = tid + i * 256;
        ar[i] = id >> 2;
        akq[i] = id & 3;
        int r = row0 + ar[i];
        int src = GATHER ? win_src_row(r) : r;
        abase[i] = (long)src * Asr + akq[i] * 8;
    }
    const int bn = tid >> 2, bkq = tid & 3;
    const long bbase = (long)(col0 + bn) * Ksm + bkq * 8;

    const int wid = tid >> 5, lane = tid & 31, lr = lane >> 2, lc = lane & 3;
    const int wm = wid >> 1, wn = wid & 1;
    float acc[2][4][4] = {};

    auto loadT = [&](int t, int buf) {
        int k0 = t * 32;
#pragma unroll
        for (int i = 0; i < 2; i++)
            *(uint4*)&As[buf][ar[i]][akq[i] * 4] = *(const uint4*)(A + abase[i] + k0);
        *(uint4*)&Bs[buf][bn][bkq * 4] = *(const uint4*)(Wm + bbase + k0);
    };

    loadT(0, 0);
    __syncthreads();
    for (int t = 0; t < T; t++) {
        if (t + 1 < T) loadT(t + 1, (t + 1) & 1);
        tile_mma32(As[t & 1], Bs[t & 1], acc, wm, wn, lane);
        __syncthreads();
    }

#pragma unroll
    for (int mt = 0; mt < 2; mt++) {
#pragma unroll
        for (int nt = 0; nt < 4; nt++) {
            int rbase = row0 + wm * 32 + mt * 16 + lr;
            int cb = col0 + wn * 32 + nt * 8 + lc * 2;   // even
            if (cb >= Nc) continue;
#pragma unroll
            for (int half = 0; half < 2; half++) {
                int row = rbase + half * 8;
                float v0 = acc[mt][nt][half * 2] + bias[cb];
                float v1 = acc[mt][nt][half * 2 + 1] + bias[cb + 1];
                if constexpr (EPI == 0) {
                    int tq = cb / 180;
                    int rem = cb - tq * 180;
                    int hh = rem / 30, hd = rem - hh * 30;   // hd even
                    if (tq == 0) { v0 *= QSCALE; v1 *= QSCALE; }
                    int win = row >> 9, n = row & 511;
                    long idx = ((long)((win * 3 + tq) * NHEADS + hh) * NTOK + n) * HDIM + hd;
                    ((uint32_t*)CoutV)[idx >> 1] = pk(v0, v1);
                } else if constexpr (EPI == 1) {
                    int src = win_src_row(row);
                    long gi = (long)src * CC + cb;
                    int b = src >> 14;
                    float* Cf = (float*)CoutV;
                    Cf[gi]     = e0[gi]     + v0 + 0.01f * e1[gi]     * e2[b * CC + cb];
                    Cf[gi + 1] = e0[gi + 1] + v1 + 0.01f * e1[gi + 1] * e2[b * CC + cb + 1];
                } else if constexpr (EPI == 2) {
                    long idx = (long)row * OS + cb;
                    ((uint32_t*)CoutV)[idx >> 1] = pk(gelu_exact(v0), gelu_exact(v1));
                } else {
                    long gi = (long)row * CC + cb;
                    float* Cf = (float*)CoutV;
                    Cf[gi]     = e0[gi]     + v0;
                    Cf[gi + 1] = e0[gi + 1] + v1;
                }
            }
        }
    }
}

// ---------------- bf16 MMA implicit-GEMM 3x3x3 conv, BK=32 ----------------
template <int CV>
__global__ void __launch_bounds__(256) mma_conv(
        const uint16_t* __restrict__ A, const uint16_t* __restrict__ Wt,
        const float* __restrict__ bias, void* __restrict__ OutV) {
    constexpr int Asr = (CV == 1) ? 192 : 64;
    constexpr int KT = (CV == 1) ? 6 : 2;      // 32-wide k-tiles per tap
    constexpr int T = 27 * KT;
    constexpr int Wn = (CV == 1) ? 64 : 192;
    constexpr int Wk = (CV == 1) ? 192 : 64;
    __shared__ uint32_t As[2][128][20];
    __shared__ uint32_t Bs[2][64][20];
    const int tid = threadIdx.x;
    const int row0 = blockIdx.x * 128, col0 = blockIdx.y * 64;

    int ar[2], akq[2], pd[2], ph[2], pw[2];
#pragma unroll
    for (int i = 0; i < 2; i++) {
        int id = tid + i * 256;
        ar[i] = id >> 2;
        akq[i] = id & 3;
        int p = row0 + ar[i];
        pd[i] = (p >> 10) & 15;
        ph[i] = (p >> 5) & 31;
        pw[i] = p & 31;
    }
    const int bn = tid >> 2, bkq = tid & 3;

    const int wid = tid >> 5, lane = tid & 31, lr = lane >> 2, lc = lane & 3;
    const int wm = wid >> 1, wn = wid & 1;
    float acc[2][4][4] = {};

    auto loadT = [&](int t, int buf) {
        int tap = t / KT;
        int kt = t - tap * KT;
        int k0 = kt * 32;
        int kd = tap / 9 - 1;
        int r9 = tap - (kd + 1) * 9;
        int kh = r9 / 3 - 1;
        int kw = r9 - (kh + 1) * 3 - 1;
        int off = (kd << 10) + (kh << 5) + kw;
#pragma unroll
        for (int i = 0; i < 2; i++) {
            bool valid = ((unsigned)(pd[i] + kd) < 16u) &&
                         ((unsigned)(ph[i] + kh) < 32u) &&
                         ((unsigned)(pw[i] + kw) < 32u);
            uint4 v = make_uint4(0u, 0u, 0u, 0u);
            if (valid)
                v = *(const uint4*)(A + (long)(row0 + ar[i] + off) * Asr + k0 + akq[i] * 8);
            *(uint4*)&As[buf][ar[i]][akq[i] * 4] = v;
        }
        *(uint4*)&Bs[buf][bn][bkq * 4] =
            *(const uint4*)(Wt + ((long)tap * Wn + col0 + bn) * Wk + k0 + bkq * 8);
    };

    loadT(0, 0);
    __syncthreads();
    for (int t = 0; t < T; t++) {
        if (t + 1 < T) loadT(t + 1, (t + 1) & 1);
        tile_mma32(As[t & 1], Bs[t & 1], acc, wm, wn, lane);
        __syncthreads();
    }

#pragma unroll
    for (int mt = 0; mt < 2; mt++) {
#pragma unroll
        for (int nt = 0; nt < 4; nt++) {
            int rbase = row0 + wm * 32 + mt * 16 + lr;
            int cb = col0 + wn * 32 + nt * 8 + lc * 2;   // even
#pragma unroll
            for (int half = 0; half < 2; half++) {
                int row = rbase + half * 8;
                float v0 = acc[mt][nt][half * 2];
                float v1 = acc[mt][nt][half * 2 + 1];
                if constexpr (CV == 1) {
                    v0 = gelu_exact(v0 + ((cb < 60) ? bias[cb] : 0.f));
                    v1 = gelu_exact(v1 + ((cb + 1 < 60) ? bias[cb + 1] : 0.f));
                    ((uint32_t*)OutV)[((long)row * 64 + cb) >> 1] = pk(v0, v1);
                } else {
                    if (cb < CC) {
                        float* Of = (float*)OutV;
                        Of[(long)row * CC + cb] = v0 + bias[cb];
                        if (cb + 1 < CC) Of[(long)row * CC + cb + 1] = v1 + bias[cb + 1];
                    }
                }
            }
        }
    }
}

// ---------------- pooled sum + channel attention ----------------
__global__ void pooled_kernel(const float* __restrict__ y2, float* __restrict__ pool) {
    int r0 = blockIdx.x * 64;
    int b = r0 >> 14;
    int c = threadIdx.x;
    if (c >= CC) return;
    float s = 0.f;
    for (int i = 0; i < 64; i++) s += y2[(long)(r0 + i) * CC + c];
    atomicAdd(&pool[b * CC + c], s);
}

__global__ void catt_kernel(const float* __restrict__ pool,
        const float* __restrict__ caw1, const float* __restrict__ cab1,
        const float* __restrict__ caw2, const float* __restrict__ cab2,
        float* __restrict__ catt) {
    __shared__ float sq[2][8];
    int tid = threadIdx.x;
    if (tid < 12) {
        int b = tid / 6, j = tid % 6;
        float s = cab1[j];
        for (int c = 0; c < CC; c++)
            s += (pool[b * CC + c] * (1.f / LL)) * caw1[j * CC + c];
        sq[b][j] = fmaxf(s, 0.f);
    }
    __syncthreads();
    if (tid < CC) {
        for (int b = 0; b < 2; b++) {
            float s = cab2[tid];
#pragma unroll
            for (int j = 0; j < 6; j++) s += sq[b][j] * caw2[tid * 6 + j];
            catt[b * CC + tid] = 1.f / (1.f + __expf(-s));
        }
    }
}

// ---------------- bf16 MMA flash attention (ldmatrix frags) ----------------
// block = (q-tile 128, win*6+head); 256 thr = 8 warps (4x2)
// smem (words): Qs[128][20] Ks[128][20] packed bf16x2 (stride 20 = LDSM conflict-free),
//   Vs[32][68] packed [d][kpair], Ss[128][132] f32 scores (P repacked in place), fs[128]
#define ATTN_WORDS (128 * 20 * 2 + 32 * 68 + 128 * 132 + 128)
#define ATTN_SMEM (ATTN_WORDS * 4)
__global__ void __launch_bounds__(256) attn_mma(const uint16_t* __restrict__ qkv,
        const uint16_t* __restrict__ biasQ, uint16_t* __restrict__ outp) {
    extern __shared__ char smraw[];
    uint32_t* Qs = (uint32_t*)smraw;
    uint32_t* Ks = Qs + 128 * 20;
    uint32_t* Vs = Ks + 128 * 20;
    float* Ss = (float*)(Vs + 32 * 68);
    float* fs = Ss + 128 * 132;

    const int qt = blockIdx.x;
    const int win = blockIdx.y / NHEADS, hh = blockIdx.y % NHEADS;
    const uint32_t* qbu = (const uint32_t*)(qkv +
        ((long)((win * 3 + 0) * NHEADS + hh) * NTOK + qt * 128) * HDIM);
    const uint32_t* kbu = (const uint32_t*)(qkv +
        (long)((win * 3 + 1) * NHEADS + hh) * NTOK * HDIM);
    const uint16_t* vb = qkv + (long)((win * 3 + 2) * NHEADS + hh) * NTOK * HDIM;
    const uint16_t* bq = biasQ + ((long)(hh * NTOK) + qt * 128) * NTOK;

    const int tid = threadIdx.x;
    const int w = tid >> 5, lane = tid & 31, g = lane >> 2, lc = lane & 3;
    const int wm = w >> 1, wn = w & 1;

    // ldmatrix lane constants
    const int lar = lane & 15;                       // A row offset
    const int law = (lane >> 4) * 4;                 // A word offset
    const int lbr = ((lane >> 4) << 3) + (lane & 7); // B-pair row offset
    const int lbw = ((lane >> 3) & 1) * 4;           // B-pair word offset

    // Q: 128 rows x 16 words (15 data words = 30 bf16, word 15 zero)
    for (int idx = tid; idx < 128 * 16; idx += 256) {
        int r = idx >> 4, d = idx & 15;
        Qs[r * 20 + d] = (d < 15) ? qbu[r * 15 + d] : 0u;
    }

    const int srow = w * 16 + (lane >> 1);
    const int shalf = lane & 1;
    float m_run = -1e30f, l_run = 0.f;
    float oacc[2][2][4] = {};

    for (int t0 = 0; t0 < NTOK; t0 += 128) {
        __syncthreads();
        for (int idx = tid; idx < 128 * 16; idx += 256) {
            int r = idx >> 4, d = idx & 15;
            Ks[r * 20 + d] = (d < 15) ? kbu[(t0 + r) * 15 + d] : 0u;
        }
        // V transposed: Vs[d][j] = {V[2j][d], V[2j+1][d]}
        for (int idx = tid; idx < 32 * 64; idx += 256) {
            int d = idx >> 6, j = idx & 63;
            uint32_t u = 0u;
            if (d < HDIM) {
                uint32_t lo = vb[(long)(t0 + 2 * j) * HDIM + d];
                uint32_t hi = vb[(long)(t0 + 2 * j + 1) * HDIM + d];
                u = lo | (hi << 16);
            }
            Vs[d * 68 + j] = u;
        }
        __syncthreads();

        // S = Q K^T : warp tile 32(q) x 64(k), ldmatrix frags
        float sacc[2][8][4] = {};
        {
            const int qr = wm * 32 + lar;
#pragma unroll
            for (int ks = 0; ks < 2; ks++) {
                uint32_t a[2][4];
                ldsm4(a[0], &Qs[qr * 20 + ks * 8 + law]);
                ldsm4(a[1], &Qs[(qr + 16) * 20 + ks * 8 + law]);
#pragma unroll
                for (int p = 0; p < 4; p++) {
                    uint32_t b2[4];
                    ldsm4(b2, &Ks[(wn * 64 + p * 16 + lbr) * 20 + ks * 8 + lbw]);
#pragma unroll
                    for (int mt = 0; mt < 2; mt++) {
                        mma16(sacc[mt][p * 2],     a[mt], b2);
                        mma16(sacc[mt][p * 2 + 1], a[mt], b2 + 2);
                    }
                }
            }
        }
        // bias add (bf16 words) + store S (f32) to smem
        const uint32_t* bqu = (const uint32_t*)bq;
#pragma unroll
        for (int mt = 0; mt < 2; mt++)
#pragma unroll
            for (int nt = 0; nt < 8; nt++) {
                int r0 = wm * 32 + mt * 16 + g;
                int c0 = wn * 64 + nt * 8 + lc * 2;   // even
                uint32_t u0 = bqu[((long)r0 * NTOK + t0 + c0) >> 1];
                uint32_t u1 = bqu[((long)(r0 + 8) * NTOK + t0 + c0) >> 1];
                Ss[r0 * 132 + c0]           = sacc[mt][nt][0] + b2f(u0 & 0xFFFF);
                Ss[r0 * 132 + c0 + 1]       = sacc[mt][nt][1] + b2f(u0 >> 16);
                Ss[(r0 + 8) * 132 + c0]     = sacc[mt][nt][2] + b2f(u1 & 0xFFFF);
                Ss[(r0 + 8) * 132 + c0 + 1] = sacc[mt][nt][3] + b2f(u1 >> 16);
            }
        __syncthreads();

        // online softmax: lane pair per row; each half-lane owns contiguous 64 keys.
        float* rowp = Ss + srow * 132;
        uint32_t* prow = (uint32_t*)rowp;
        float tmax = -1e30f;
#pragma unroll
        for (int j = 0; j < 64; j++) tmax = fmaxf(tmax, rowp[shalf * 64 + j]);
        tmax = fmaxf(tmax, __shfl_xor_sync(~0u, tmax, 1));
        float newm = fmaxf(m_run, tmax);
        float f = __expf(m_run - newm);
        float ssum = 0.f;
#pragma unroll
        for (int j = 0; j < 32; j++) {
            float e0 = __expf(rowp[shalf * 64 + 2 * j] - newm);
            float e1 = __expf(rowp[shalf * 64 + 2 * j + 1] - newm);
            ssum += e0 + e1;
            prow[shalf * 32 + j] = pk(e0, e1);
        }
        ssum += __shfl_xor_sync(~0u, ssum, 1);
        l_run = l_run * f + ssum;
        m_run = newm;
        if (!shalf) fs[srow] = f;
        __syncthreads();

        // rescale O, then O += P @ V : warp tile 32(q) x 16(d), 8 k16 steps
        uint32_t* Ps = (uint32_t*)Ss;
#pragma unroll
        for (int mt = 0; mt < 2; mt++) {
            int r = wm * 32 + mt * 16 + g;
            float f0 = fs[r], f1 = fs[r + 8];
#pragma unroll
            for (int nt = 0; nt < 2; nt++) {
                oacc[mt][nt][0] *= f0; oacc[mt][nt][1] *= f0;
                oacc[mt][nt][2] *= f1; oacc[mt][nt][3] *= f1;
            }
        }
        {
            const int pr = wm * 32 + lar;
            const int vr = wn * 16 + lbr;
#pragma unroll
            for (int ks = 0; ks < 8; ks++) {
                uint32_t a[2][4], b2[4];
                ldsm4(a[0], &Ps[pr * 132 + ks * 8 + law]);
                ldsm4(a[1], &Ps[(pr + 16) * 132 + ks * 8 + law]);
                ldsm4(b2, &Vs[vr * 68 + ks * 8 + lbw]);
#pragma unroll
                for (int mt = 0; mt < 2; mt++) {
                    mma16(oacc[mt][0], a[mt], b2);
                    mma16(oacc[mt][1], a[mt], b2 + 2);
                }
            }
        }
    }

    __syncthreads();
    if (!shalf) fs[srow] = 1.f / l_run;
    __syncthreads();

    uint16_t* ob = outp + (long)(win * NTOK + qt * 128) * CP + hh * HDIM;
#pragma unroll
    for (int mt = 0; mt < 2; mt++) {
        int r = wm * 32 + mt * 16 + g;
        float i0 = fs[r], i1 = fs[r + 8];
#pragma unroll
        for (int nt = 0; nt < 2; nt++) {
            int c = wn * 16 + nt * 8 + lc * 2;   // even
            if (c < HDIM) {
                *(uint32_t*)&ob[(long)r * CP + c] =
                    pk(oacc[mt][nt][0] * i0, oacc[mt][nt][1] * i0);
                *(uint32_t*)&ob[(long)(r + 8) * CP + c] =
                    pk(oacc[mt][nt][2] * i1, oacc[mt][nt][3] * i1);
            }
        }
    }
}

// ---------------- host launch ----------------
extern "C" void kernel_launch(void* const* d_in, const int* in_sizes, int n_in,
                              void* d_out, int out_size) {
    const float* x      = (const float*)d_in[0];
    const int*   rpi    = (const int*)  d_in[4];
    const float* g1     = (const float*)d_in[7];
    const float* b1     = (const float*)d_in[8];
    const float* qkv_w  = (const float*)d_in[9];
    const float* qkv_b  = (const float*)d_in[10];
    const float* rpb    = (const float*)d_in[11];
    const float* proj_w = (const float*)d_in[12];
    const float* proj_b = (const float*)d_in[13];
    const float* cw1    = (const float*)d_in[14];
    const float* cb1    = (const float*)d_in[15];
    const float* cw2    = (const float*)d_in[16];
    const float* cb2    = (const float*)d_in[17];
    const float* caw1   = (const float*)d_in[18];
    const float* cab1   = (const float*)d_in[19];
    const float* caw2   = (const float*)d_in[20];
    const float* cab2   = (const float*)d_in[21];
    const float* g2     = (const float*)d_in[22];
    const float* b2     = (const float*)d_in[23];
    const float* fc1_w  = (const float*)d_in[24];
    const float* fc1_b  = (const float*)d_in[25];
    const float* fc2_w  = (const float*)d_in[26];
    const float* fc2_b  = (const float*)d_in[27];
    float* outp = (float*)d_out;

    uint16_t *p_xn, *p_ln2, *p_ao, *p_y1, *p_qkv, *p_h, *p_bt;
    uint16_t *p_w1m, *p_w2m, *p_wq, *p_wp, *p_wf1, *p_wf2;
    float *p_x1, *p_y2, *p_pool, *p_catt;
    cudaGetSymbolAddress((void**)&p_xn,   g_xn);
    cudaGetSymbolAddress((void**)&p_ln2,  g_ln2);
    cudaGetSymbolAddress((void**)&p_ao,   g_ao);
    cudaGetSymbolAddress((void**)&p_x1,   g_x1);
    cudaGetSymbolAddress((void**)&p_y1,   g_y1);
    cudaGetSymbolAddress((void**)&p_y2,   g_y2);
    cudaGetSymbolAddress((void**)&p_qkv,  g_qkv);
    cudaGetSymbolAddress((void**)&p_h,    g_hbuf);
    cudaGetSymbolAddress((void**)&p_bt,   g_biasT);
    cudaGetSymbolAddress((void**)&p_w1m,  g_w1m);
    cudaGetSymbolAddress((void**)&p_w2m,  g_w2m);
    cudaGetSymbolAddress((void**)&p_wq,   g_wq);
    cudaGetSymbolAddress((void**)&p_wp,   g_wp);
    cudaGetSymbolAddress((void**)&p_wf1,  g_wf1);
    cudaGetSymbolAddress((void**)&p_wf2,  g_wf2);
    cudaGetSymbolAddress((void**)&p_pool, g_pool);
    cudaGetSymbolAddress((void**)&p_catt, g_catt);

    cudaFuncSetAttribute(attn_mma, cudaFuncAttributeMaxDynamicSharedMemorySize, ATTN_SMEM);

    // prep: weight/bias repack to bf16
    repack1_kernel<<<(27 * 64 * 192 + 255) / 256, 256>>>(cw1, p_w1m);
    repack2_kernel<<<(27 * 192 * 64 + 255) / 256, 256>>>(cw2, p_w2m);
    wpack_kernel<<<(540 * 192 + 255) / 256, 256>>>(qkv_w, p_wq, 540, 180, 192);
    wpack_kernel<<<(180 * 192 + 255) / 256, 256>>>(proj_w, p_wp, 180, 180, 192);
    wpack_kernel<<<(720 * 192 + 255) / 256, 256>>>(fc1_w, p_wf1, 720, 180, 192);
    wpack_kernel<<<(180 * HIDP + 255) / 256, 256>>>(fc2_w, p_wf2, 180, 720, HIDP);
    biasprep_kernel<<<512, 512>>>(rpi, rpb, p_bt);
    zero_pool_kernel<<<1, 384>>>(p_pool);

    // LN1 -> bf16 (stride 192; pads stay zero from static init)
    ln_kernel<<<LT / 8, 256>>>(x, CC, g1, b1, p_xn, CP);

    // CAB conv branch
    mma_conv<1><<<dim3(LT / 128, 1), 256>>>(p_xn, p_w1m, cb1, p_y1);
    mma_conv<2><<<dim3(LT / 128, 3), 256>>>(p_y1, p_w2m, cb2, p_y2);
    pooled_kernel<<<LT / 64, 192>>>(p_y2, p_pool);
    catt_kernel<<<1, 192>>>(p_pool, caw1, cab1, caw2, cab2, p_catt);

    // window attention path
    mma_gemm<0, true><<<dim3(LT / 128, 9), 256>>>(p_xn, CP, p_wq, qkv_b, p_qkv,
                                                  540, 192, 0, nullptr, nullptr, nullptr);
    attn_mma<<<dim3(4, NWIN * NHEADS), 256, ATTN_SMEM>>>(p_qkv, p_bt, p_ao);
    mma_gemm<1, false><<<dim3(LT / 128, 3), 256>>>(p_ao, CP, p_wp, proj_b, p_x1,
                                                   180, 192, 0, x, p_y2, p_catt);

    // MLP
    ln_kernel<<<LT / 8, 256>>>(p_x1, CC, g2, b2, p_ln2, CP);
    mma_gemm<2, false><<<dim3(LT / 128, 12), 256>>>(p_ln2, CP, p_wf1, fc1_b, p_h,
                                                    720, 192, HIDP, nullptr, nullptr, nullptr);
    mma_gemm<3, false><<<dim3(LT / 128, 3), 256>>>(p_h, HIDP, p_wf2, fc2_b, outp,
                                                   180, HIDP, 0, p_x1, nullptr, nullptr);
}

// round 9
// speedup vs baseline: 5.5918x; 1.1191x over previous
#include <cuda_runtime.h>
#include <math.h>
#include <stdint.h>

// ---------------- problem constants ----------------
#define BB 2
#define CC 180
#define CP 192              // padded channel stride (multiple of 32)
#define DD 16
#define HH 32
#define WW 32
#define LL 16384            // D*H*W
#define LT 32768            // B*L
#define NHEADS 6
#define HDIM 30
#define NTOK 512
#define NWIN 64
#define HIDD 720
#define HIDP 736            // padded fc2 K (multiple of 32)
#define QSCALE 0.18257418583505537f  // 30^-0.5

// ---------------- device scratch (zero-initialized; pads never written) ----------------
__device__ uint16_t g_xn[LT * CP];              // bf16, LN1 out
__device__ uint16_t g_ln2[LT * CP];             // bf16, LN2 out
__device__ uint16_t g_ao[LT * CP];              // bf16, attention out (window order)
__device__ float    g_x1[LT * CC];              // fp32 residual
__device__ uint16_t g_y1[LT * 64];              // bf16 conv1 out (gelu'd, 64-pad)
__device__ float    g_y2[LT * CC];              // fp32 conv2 out + bias
__device__ uint16_t g_qkv[NWIN * 3 * NHEADS * NTOK * HDIM];  // bf16
__device__ uint16_t g_hbuf[LT * HIDP];          // bf16 fc1 gelu out (K-pad 736)
__device__ uint16_t g_biasT[NHEADS * NTOK * NTOK]; // bf16 [h][query][key]
__device__ uint16_t g_w1m[27 * 64 * 192];       // bf16 [tap][cout64][cin192]
__device__ uint16_t g_w2m[27 * 192 * 64];       // bf16 [tap][cout192][cin64]
__device__ uint16_t g_wq[576 * 192];            // bf16 qkv_w (row-pad 576)
__device__ uint16_t g_wp[192 * 192];            // bf16 proj_w (row-pad 192)
__device__ uint16_t g_wf1[768 * 192];           // bf16 fc1_w (row-pad 768)
__device__ uint16_t g_wf2[192 * HIDP];          // bf16 fc2_w (row-pad 192)
__device__ float g_pool[2 * CC];
__device__ float g_catt[2 * CC];

// window (win, n) -> flat row b*LL + l  (bijection)
__device__ __forceinline__ int win_src_row(int r) {
    int win = r >> 9, n = r & 511;
    int sb = win >> 2, wq = win & 3;
    int b = sb >> 3, isp = sb & 7;
    int id = isp >> 2, ih = (isp >> 1) & 1, iw = isp & 1;
    int nhi = wq >> 1, nwi = wq & 1;
    int wd = n >> 6, wh = (n >> 3) & 7, ww = n & 7;
    int d = wd * 2 + id;
    int h = (nhi * 8 + wh) * 2 + ih;
    int w = (nwi * 8 + ww) * 2 + iw;
    return ((b * DD + d) * HH + h) * WW + w;
}

__device__ __forceinline__ float gelu_exact(float v) {
    return 0.5f * v * (1.f + erff(v * 0.70710678118654752f));
}

// pack two floats -> bf16x2 word (lo = first)
__device__ __forceinline__ uint32_t pk(float lo, float hi) {
    uint32_t r;
    asm("cvt.rn.bf16x2.f32 %0, %1, %2;" : "=r"(r) : "f"(hi), "f"(lo));
    return r;
}
__device__ __forceinline__ uint16_t f2b(float v) { return (uint16_t)pk(v, 0.f); }
__device__ __forceinline__ float b2f(uint32_t bits16) {
    return __int_as_float((int)(bits16 << 16));
}

__device__ __forceinline__ void mma16(float* c, const uint32_t* a, const uint32_t* b) {
    asm volatile(
        "mma.sync.aligned.m16n8k16.row.col.f32.bf16.bf16.f32 "
        "{%0,%1,%2,%3},{%4,%5,%6,%7},{%8,%9},{%0,%1,%2,%3};\n"
        : "+f"(c[0]), "+f"(c[1]), "+f"(c[2]), "+f"(c[3])
        : "r"(a[0]), "r"(a[1]), "r"(a[2]), "r"(a[3]), "r"(b[0]), "r"(b[1]));
}

// ldmatrix x4 (b16)
__device__ __forceinline__ void ldsm4(uint32_t* r, const void* p) {
    uint32_t addr = (uint32_t)__cvta_generic_to_shared(p);
    asm volatile("ldmatrix.sync.aligned.m8n8.x4.shared.b16 {%0,%1,%2,%3}, [%4];"
        : "=r"(r[0]), "=r"(r[1]), "=r"(r[2]), "=r"(r[3]) : "r"(addr));
}

// cp.async 16B, with zfill predication (sz=0 -> no memory access, zero fill)
__device__ __forceinline__ void cpa16(void* smem, const void* gmem, bool pred) {
    uint32_t s = (uint32_t)__cvta_generic_to_shared(smem);
    int sz = pred ? 16 : 0;
    asm volatile("cp.async.cg.shared.global [%0], [%1], 16, %2;\n"
                 :: "r"(s), "l"(gmem), "r"(sz));
}
__device__ __forceinline__ void cpcommit() {
    asm volatile("cp.async.commit_group;\n");
}
template <int N>
__device__ __forceinline__ void cpwait() {
    asm volatile("cp.async.wait_group %0;\n" :: "n"(N));
}

// one BK=32 tile via ldmatrix: warp tile 32x32, 2 k16 steps
__device__ __forceinline__ void tile_mma32(const uint32_t (*As)[20], const uint32_t (*Bs)[20],
                                           float acc[2][4][4], int wm, int wn, int lane) {
    const int ar = wm * 32 + (lane & 15);
    const int aw = (lane >> 4) * 4;
    const int br = wn * 32 + ((lane >> 4) << 3) + (lane & 7);
    const int bw = ((lane >> 3) & 1) * 4;
#pragma unroll
    for (int ks = 0; ks < 2; ks++) {
        uint32_t a[2][4], b[2][4];
        ldsm4(a[0], &As[ar][ks * 8 + aw]);
        ldsm4(a[1], &As[ar + 16][ks * 8 + aw]);
        ldsm4(b[0], &Bs[br][ks * 8 + bw]);
        ldsm4(b[1], &Bs[br + 16][ks * 8 + bw]);
#pragma unroll
        for (int mt = 0; mt < 2; mt++)
#pragma unroll
            for (int p = 0; p < 2; p++) {
                mma16(acc[mt][p * 2],     a[mt], b[p]);
                mma16(acc[mt][p * 2 + 1], a[mt], b[p] + 2);
            }
    }
}

// ---------------- prep kernels ----------------
__global__ void wpack_kernel(const float* __restrict__ w, uint16_t* __restrict__ out,
                             int N, int K, int Ksm) {
    int idx = blockIdx.x * 256 + threadIdx.x;
    if (idx >= N * Ksm) return;
    int n = idx / Ksm, k = idx - n * Ksm;
    out[idx] = (k < K) ? f2b(w[n * K + k]) : (uint16_t)0;
}

__global__ void repack1_kernel(const float* __restrict__ cw1, uint16_t* __restrict__ w1m) {
    int idx = blockIdx.x * 256 + threadIdx.x;
    if (idx >= 27 * 64 * 192) return;
    int tap = idx / (64 * 192);
    int rem = idx - tap * 64 * 192;
    int o = rem / 192, c = rem - o * 192;
    w1m[idx] = (o < 60 && c < 180) ? f2b(cw1[(o * 180 + c) * 27 + tap]) : (uint16_t)0;
}

__global__ void repack2_kernel(const float* __restrict__ cw2, uint16_t* __restrict__ w2m) {
    int idx = blockIdx.x * 256 + threadIdx.x;
    if (idx >= 27 * 192 * 64) return;
    int tap = idx / (192 * 64);
    int rem = idx - tap * 192 * 64;
    int o = rem >> 6, c = rem & 63;
    w2m[idx] = (o < 180 && c < 60) ? f2b(cw2[(o * 60 + c) * 27 + tap]) : (uint16_t)0;
}

// bias table: [h][query][key] bf16
__global__ void biasprep_kernel(const int* __restrict__ rpi, const float* __restrict__ rpb,
                                uint16_t* __restrict__ biasT) {
    int q = blockIdx.x, k = threadIdx.x;
    int t = rpi[q * 512 + k];
#pragma unroll
    for (int h = 0; h < NHEADS; h++)
        biasT[(h * 512 + q) * 512 + k] = f2b(rpb[t * NHEADS + h]);
}

__global__ void zero_pool_kernel(float* __restrict__ pool) {
    if (threadIdx.x < 2 * CC) pool[threadIdx.x] = 0.f;
}

// ---------------- layernorm (warp per row), bf16 out ----------------
__global__ void __launch_bounds__(256) ln_kernel(const float* __restrict__ in, int ins,
        const float* __restrict__ gg, const float* __restrict__ bb,
        uint16_t* __restrict__ outp, int outs) {
    int row = blockIdx.x * 8 + (threadIdx.x >> 5);
    int lane = threadIdx.x & 31;
    const float* p = in + (long)row * ins;
    float v[6];
    float s = 0.f;
#pragma unroll
    for (int i = 0; i < 6; i++) {
        int c = lane + i * 32;
        v[i] = (c < CC) ? p[c] : 0.f;
        s += v[i];
    }
    for (int o = 16; o; o >>= 1) s += __shfl_xor_sync(~0u, s, o);
    float mean = s * (1.f / CC);
    float vs = 0.f;
#pragma unroll
    for (int i = 0; i < 6; i++) {
        int c = lane + i * 32;
        float d = (c < CC) ? (v[i] - mean) : 0.f;
        vs += d * d;
    }
    for (int o = 16; o; o >>= 1) vs += __shfl_xor_sync(~0u, vs, o);
    float inv = rsqrtf(vs * (1.f / CC) + 1e-5f);
    uint16_t* q = outp + (long)row * outs;
#pragma unroll
    for (int i = 0; i < 6; i++) {
        int c = lane + i * 32;
        if (c < CC) q[c] = f2b((v[i] - mean) * inv * gg[c] + bb[c]);
    }
}

// ---------------- bf16 MMA GEMM, cp.async 3-stage, BK=32, fused epilogues ----------------
template <int EPI, bool GATHER>
__global__ void __launch_bounds__(256) mma_gemm(
        const uint16_t* __restrict__ A, int Asr,
        const uint16_t* __restrict__ Wm, const float* __restrict__ bias,
        void* __restrict__ CoutV, int Nc, int Ksm, int OS,
        const float* __restrict__ e0, const float* __restrict__ e1,
        const float* __restrict__ e2) {
    __shared__ uint32_t As[3][128][20];
    __shared__ uint32_t Bs[3][64][20];
    const int tid = threadIdx.x;
    const int row0 = blockIdx.x * 128, col0 = blockIdx.y * 64;
    const int T = Ksm >> 5;

    // loaders: 4 threads per row, each thread = 8 bf16 elements (one 16B cp.async)
    int ar[2], akq[2];
    long abase[2];
#pragma unroll
    for (int i = 0; i < 2; i++) {
        int id = tid + i * 256;
        ar[i] = id >> 2;
        akq[i] = id & 3;
        int r = row0 + ar[i];
        int src = GATHER ? win_src_row(r) : r;
        abase[i] = (long)src * Asr + akq[i] * 8;
    }
    const int bn = tid >> 2, bkq = tid & 3;
    const long bbase = (long)(col0 + bn) * Ksm + bkq * 8;

    const int wid = tid >> 5, lane = tid & 31, lr = lane >> 2, lc = lane & 3;
    const int wm = wid >> 1, wn = wid & 1;
    float acc[2][4][4] = {};

    auto loadT = [&](int t) {
        int buf = t % 3;
        int k0 = t * 32;
#pragma unroll
        for (int i = 0; i < 2; i++)
            cpa16(&As[buf][ar[i]][akq[i] * 4], A + abase[i] + k0, true);
        cpa16(&Bs[buf][bn][bkq * 4], Wm + bbase + k0, true);
        cpcommit();
    };

    loadT(0);
    loadT(1);
    for (int t = 0; t < T; t++) {
        if (t + 1 < T) cpwait<1>(); else cpwait<0>();
        __syncthreads();
        if (t + 2 < T) loadT(t + 2);
        tile_mma32(As[t % 3], Bs[t % 3], acc, wm, wn, lane);
    }

#pragma unroll
    for (int mt = 0; mt < 2; mt++) {
#pragma unroll
        for (int nt = 0; nt < 4; nt++) {
            int rbase = row0 + wm * 32 + mt * 16 + lr;
            int cb = col0 + wn * 32 + nt * 8 + lc * 2;   // even
            if (cb >= Nc) continue;
#pragma unroll
            for (int half = 0; half < 2; half++) {
                int row = rbase + half * 8;
                float v0 = acc[mt][nt][half * 2] + bias[cb];
                float v1 = acc[mt][nt][half * 2 + 1] + bias[cb + 1];
                if constexpr (EPI == 0) {
                    int tq = cb / 180;
                    int rem = cb - tq * 180;
                    int hh = rem / 30, hd = rem - hh * 30;   // hd even
                    if (tq == 0) { v0 *= QSCALE; v1 *= QSCALE; }
                    int win = row >> 9, n = row & 511;
                    long idx = ((long)((win * 3 + tq) * NHEADS + hh) * NTOK + n) * HDIM + hd;
                    ((uint32_t*)CoutV)[idx >> 1] = pk(v0, v1);
                } else if constexpr (EPI == 1) {
                    int src = win_src_row(row);
                    long gi = (long)src * CC + cb;
                    int b = src >> 14;
                    float* Cf = (float*)CoutV;
                    Cf[gi]     = e0[gi]     + v0 + 0.01f * e1[gi]     * e2[b * CC + cb];
                    Cf[gi + 1] = e0[gi + 1] + v1 + 0.01f * e1[gi + 1] * e2[b * CC + cb + 1];
                } else if constexpr (EPI == 2) {
                    long idx = (long)row * OS + cb;
                    ((uint32_t*)CoutV)[idx >> 1] = pk(gelu_exact(v0), gelu_exact(v1));
                } else {
                    long gi = (long)row * CC + cb;
                    float* Cf = (float*)CoutV;
                    Cf[gi]     = e0[gi]     + v0;
                    Cf[gi + 1] = e0[gi + 1] + v1;
                }
            }
        }
    }
}

// ---------------- bf16 MMA implicit-GEMM 3x3x3 conv, cp.async 3-stage, BK=32 ----------------
template <int CV>
__global__ void __launch_bounds__(256) mma_conv(
        const uint16_t* __restrict__ A, const uint16_t* __restrict__ Wt,
        const float* __restrict__ bias, void* __restrict__ OutV) {
    constexpr int Asr = (CV == 1) ? 192 : 64;
    constexpr int KT = (CV == 1) ? 6 : 2;      // 32-wide k-tiles per tap
    constexpr int T = 27 * KT;
    constexpr int Wn = (CV == 1) ? 64 : 192;
    constexpr int Wk = (CV == 1) ? 192 : 64;
    __shared__ uint32_t As[3][128][20];
    __shared__ uint32_t Bs[3][64][20];
    const int tid = threadIdx.x;
    const int row0 = blockIdx.x * 128, col0 = blockIdx.y * 64;

    int ar[2], akq[2], pd[2], ph[2], pw[2];
#pragma unroll
    for (int i = 0; i < 2; i++) {
        int id = tid + i * 256;
        ar[i] = id >> 2;
        akq[i] = id & 3;
        int p = row0 + ar[i];
        pd[i] = (p >> 10) & 15;
        ph[i] = (p >> 5) & 31;
        pw[i] = p & 31;
    }
    const int bn = tid >> 2, bkq = tid & 3;

    const int wid = tid >> 5, lane = tid & 31, lr = lane >> 2, lc = lane & 3;
    const int wm = wid >> 1, wn = wid & 1;
    float acc[2][4][4] = {};

    auto loadT = [&](int t) {
        int buf = t % 3;
        int tap = t / KT;
        int kt = t - tap * KT;
        int k0 = kt * 32;
        int kd = tap / 9 - 1;
        int r9 = tap - (kd + 1) * 9;
        int kh = r9 / 3 - 1;
        int kw = r9 - (kh + 1) * 3 - 1;
        int off = (kd << 10) + (kh << 5) + kw;
#pragma unroll
        for (int i = 0; i < 2; i++) {
            bool valid = ((unsigned)(pd[i] + kd) < 16u) &&
                         ((unsigned)(ph[i] + kh) < 32u) &&
                         ((unsigned)(pw[i] + kw) < 32u);
            const uint16_t* src = valid
                ? A + (long)(row0 + ar[i] + off) * Asr + k0 + akq[i] * 8 : A;
            cpa16(&As[buf][ar[i]][akq[i] * 4], src, valid);
        }
        cpa16(&Bs[buf][bn][bkq * 4],
              Wt + ((long)tap * Wn + col0 + bn) * Wk + k0 + bkq * 8, true);
        cpcommit();
    };

    loadT(0);
    loadT(1);
    for (int t = 0; t < T; t++) {
        if (t + 1 < T) cpwait<1>(); else cpwait<0>();
        __syncthreads();
        if (t + 2 < T) loadT(t + 2);
        tile_mma32(As[t % 3], Bs[t % 3], acc, wm, wn, lane);
    }

#pragma unroll
    for (int mt = 0; mt < 2; mt++) {
#pragma unroll
        for (int nt = 0; nt < 4; nt++) {
            int rbase = row0 + wm * 32 + mt * 16 + lr;
            int cb = col0 + wn * 32 + nt * 8 + lc * 2;   // even
#pragma unroll
            for (int half = 0; half < 2; half++) {
                int row = rbase + half * 8;
                float v0 = acc[mt][nt][half * 2];
                float v1 = acc[mt][nt][half * 2 + 1];
                if constexpr (CV == 1) {
                    v0 = gelu_exact(v0 + ((cb < 60) ? bias[cb] : 0.f));
                    v1 = gelu_exact(v1 + ((cb + 1 < 60) ? bias[cb + 1] : 0.f));
                    ((uint32_t*)OutV)[((long)row * 64 + cb) >> 1] = pk(v0, v1);
                } else {
                    if (cb < CC) {
                        float* Of = (float*)OutV;
                        Of[(long)row * CC + cb] = v0 + bias[cb];
                        if (cb + 1 < CC) Of[(long)row * CC + cb + 1] = v1 + bias[cb + 1];
                    }
                }
            }
        }
    }
}

// ---------------- pooled sum + channel attention ----------------
__global__ void pooled_kernel(const float* __restrict__ y2, float* __restrict__ pool) {
    int r0 = blockIdx.x * 64;
    int b = r0 >> 14;
    int c = threadIdx.x;
    if (c >= CC) return;
    float s = 0.f;
    for (int i = 0; i < 64; i++) s += y2[(long)(r0 + i) * CC + c];
    atomicAdd(&pool[b * CC + c], s);
}

__global__ void catt_kernel(const float* __restrict__ pool,
        const float* __restrict__ caw1, const float* __restrict__ cab1,
        const float* __restrict__ caw2, const float* __restrict__ cab2,
        float* __restrict__ catt) {
    __shared__ float sq[2][8];
    int tid = threadIdx.x;
    if (tid < 12) {
        int b = tid / 6, j = tid % 6;
        float s = cab1[j];
        for (int c = 0; c < CC; c++)
            s += (pool[b * CC + c] * (1.f / LL)) * caw1[j * CC + c];
        sq[b][j] = fmaxf(s, 0.f);
    }
    __syncthreads();
    if (tid < CC) {
        for (int b = 0; b < 2; b++) {
            float s = cab2[tid];
#pragma unroll
            for (int j = 0; j < 6; j++) s += sq[b][j] * caw2[tid * 6 + j];
            catt[b * CC + tid] = 1.f / (1.f + __expf(-s));
        }
    }
}

// ---------------- bf16 MMA flash attention (ldmatrix frags) ----------------
#define ATTN_WORDS (128 * 20 * 2 + 32 * 68 + 128 * 132 + 128)
#define ATTN_SMEM (ATTN_WORDS * 4)
__global__ void __launch_bounds__(256) attn_mma(const uint16_t* __restrict__ qkv,
        const uint16_t* __restrict__ biasQ, uint16_t* __restrict__ outp) {
    extern __shared__ char smraw[];
    uint32_t* Qs = (uint32_t*)smraw;
    uint32_t* Ks = Qs + 128 * 20;
    uint32_t* Vs = Ks + 128 * 20;
    float* Ss = (float*)(Vs + 32 * 68);
    float* fs = Ss + 128 * 132;

    const int qt = blockIdx.x;
    const int win = blockIdx.y / NHEADS, hh = blockIdx.y % NHEADS;
    const uint32_t* qbu = (const uint32_t*)(qkv +
        ((long)((win * 3 + 0) * NHEADS + hh) * NTOK + qt * 128) * HDIM);
    const uint32_t* kbu = (const uint32_t*)(qkv +
        (long)((win * 3 + 1) * NHEADS + hh) * NTOK * HDIM);
    const uint16_t* vb = qkv + (long)((win * 3 + 2) * NHEADS + hh) * NTOK * HDIM;
    const uint16_t* bq = biasQ + ((long)(hh * NTOK) + qt * 128) * NTOK;

    const int tid = threadIdx.x;
    const int w = tid >> 5, lane = tid & 31, g = lane >> 2, lc = lane & 3;
    const int wm = w >> 1, wn = w & 1;

    const int lar = lane & 15;
    const int law = (lane >> 4) * 4;
    const int lbr = ((lane >> 4) << 3) + (lane & 7);
    const int lbw = ((lane >> 3) & 1) * 4;

    // Q: 128 rows x 16 words (15 data words = 30 bf16, word 15 zero)
    for (int idx = tid; idx < 128 * 16; idx += 256) {
        int r = idx >> 4, d = idx & 15;
        Qs[r * 20 + d] = (d < 15) ? qbu[r * 15 + d] : 0u;
    }

    const int srow = w * 16 + (lane >> 1);
    const int shalf = lane & 1;
    float m_run = -1e30f, l_run = 0.f;
    float oacc[2][2][4] = {};

    for (int t0 = 0; t0 < NTOK; t0 += 128) {
        __syncthreads();
        for (int idx = tid; idx < 128 * 16; idx += 256) {
            int r = idx >> 4, d = idx & 15;
            Ks[r * 20 + d] = (d < 15) ? kbu[(t0 + r) * 15 + d] : 0u;
        }
        // V transposed: Vs[d][j] = {V[2j][d], V[2j+1][d]}
        for (int idx = tid; idx < 32 * 64; idx += 256) {
            int d = idx >> 6, j = idx & 63;
            uint32_t u = 0u;
            if (d < HDIM) {
                uint32_t lo = vb[(long)(t0 + 2 * j) * HDIM + d];
                uint32_t hi = vb[(long)(t0 + 2 * j + 1) * HDIM + d];
                u = lo | (hi << 16);
            }
            Vs[d * 68 + j] = u;
        }
        __syncthreads();

        // S = Q K^T : warp tile 32(q) x 64(k), ldmatrix frags
        float sacc[2][8][4] = {};
        {
            const int qr = wm * 32 + lar;
#pragma unroll
            for (int ks = 0; ks < 2; ks++) {
                uint32_t a[2][4];
                ldsm4(a[0], &Qs[qr * 20 + ks * 8 + law]);
                ldsm4(a[1], &Qs[(qr + 16) * 20 + ks * 8 + law]);
#pragma unroll
                for (int p = 0; p < 4; p++) {
                    uint32_t b2[4];
                    ldsm4(b2, &Ks[(wn * 64 + p * 16 + lbr) * 20 + ks * 8 + lbw]);
#pragma unroll
                    for (int mt = 0; mt < 2; mt++) {
                        mma16(sacc[mt][p * 2],     a[mt], b2);
                        mma16(sacc[mt][p * 2 + 1], a[mt], b2 + 2);
                    }
                }
            }
        }
        // bias add (bf16 words) + store S (f32) to smem
        const uint32_t* bqu = (const uint32_t*)bq;
#pragma unroll
        for (int mt = 0; mt < 2; mt++)
#pragma unroll
            for (int nt = 0; nt < 8; nt++) {
                int r0 = wm * 32 + mt * 16 + g;
                int c0 = wn * 64 + nt * 8 + lc * 2;   // even
                uint32_t u0 = bqu[((long)r0 * NTOK + t0 + c0) >> 1];
                uint32_t u1 = bqu[((long)(r0 + 8) * NTOK + t0 + c0) >> 1];
                Ss[r0 * 132 + c0]           = sacc[mt][nt][0] + b2f(u0 & 0xFFFF);
                Ss[r0 * 132 + c0 + 1]       = sacc[mt][nt][1] + b2f(u0 >> 16);
                Ss[(r0 + 8) * 132 + c0]     = sacc[mt][nt][2] + b2f(u1 & 0xFFFF);
                Ss[(r0 + 8) * 132 + c0 + 1] = sacc[mt][nt][3] + b2f(u1 >> 16);
            }
        __syncthreads();

        // online softmax: lane pair per row; each half-lane owns contiguous 64 keys.
        float* rowp = Ss + srow * 132;
        uint32_t* prow = (uint32_t*)rowp;
        float tmax = -1e30f;
#pragma unroll
        for (int j = 0; j < 64; j++) tmax = fmaxf(tmax, rowp[shalf * 64 + j]);
        tmax = fmaxf(tmax, __shfl_xor_sync(~0u, tmax, 1));
        float newm = fmaxf(m_run, tmax);
        float f = __expf(m_run - newm);
        float ssum = 0.f;
#pragma unroll
        for (int j = 0; j < 32; j++) {
            float e0 = __expf(rowp[shalf * 64 + 2 * j] - newm);
            float e1 = __expf(rowp[shalf * 64 + 2 * j + 1] - newm);
            ssum += e0 + e1;
            prow[shalf * 32 + j] = pk(e0, e1);
        }
        ssum += __shfl_xor_sync(~0u, ssum, 1);
        l_run = l_run * f + ssum;
        m_run = newm;
        if (!shalf) fs[srow] = f;
        __syncthreads();

        // rescale O, then O += P @ V : warp tile 32(q) x 16(d), 8 k16 steps
        uint32_t* Ps = (uint32_t*)Ss;
#pragma unroll
        for (int mt = 0; mt < 2; mt++) {
            int r = wm * 32 + mt * 16 + g;
            float f0 = fs[r], f1 = fs[r + 8];
#pragma unroll
            for (int nt = 0; nt < 2; nt++) {
                oacc[mt][nt][0] *= f0; oacc[mt][nt][1] *= f0;
                oacc[mt][nt][2] *= f1; oacc[mt][nt][3] *= f1;
            }
        }
        {
            const int pr = wm * 32 + lar;
            const int vr = wn * 16 + lbr;
#pragma unroll
            for (int ks = 0; ks < 8; ks++) {
                uint32_t a[2][4], b2[4];
                ldsm4(a[0], &Ps[pr * 132 + ks * 8 + law]);
                ldsm4(a[1], &Ps[(pr + 16) * 132 + ks * 8 + law]);
                ldsm4(b2, &Vs[vr * 68 + ks * 8 + lbw]);
#pragma unroll
                for (int mt = 0; mt < 2; mt++) {
                    mma16(oacc[mt][0], a[mt], b2);
                    mma16(oacc[mt][1], a[mt], b2 + 2);
                }
            }
        }
    }

    __syncthreads();
    if (!shalf) fs[srow] = 1.f / l_run;
    __syncthreads();

    uint16_t* ob = outp + (long)(win * NTOK + qt * 128) * CP + hh * HDIM;
#pragma unroll
    for (int mt = 0; mt < 2; mt++) {
        int r = wm * 32 + mt * 16 + g;
        float i0 = fs[r], i1 = fs[r + 8];
#pragma unroll
        for (int nt = 0; nt < 2; nt++) {
            int c = wn * 16 + nt * 8 + lc * 2;   // even
            if (c < HDIM) {
                *(uint32_t*)&ob[(long)r * CP + c] =
                    pk(oacc[mt][nt][0] * i0, oacc[mt][nt][1] * i0);
                *(uint32_t*)&ob[(long)(r + 8) * CP + c] =
                    pk(oacc[mt][nt][2] * i1, oacc[mt][nt][3] * i1);
            }
        }
    }
}

// ---------------- host launch ----------------
extern "C" void kernel_launch(void* const* d_in, const int* in_sizes, int n_in,
                              void* d_out, int out_size) {
    const float* x      = (const float*)d_in[0];
    const int*   rpi    = (const int*)  d_in[4];
    const float* g1     = (const float*)d_in[7];
    const float* b1     = (const float*)d_in[8];
    const float* qkv_w  = (const float*)d_in[9];
    const float* qkv_b  = (const float*)d_in[10];
    const float* rpb    = (const float*)d_in[11];
    const float* proj_w = (const float*)d_in[12];
    const float* proj_b = (const float*)d_in[13];
    const float* cw1    = (const float*)d_in[14];
    const float* cb1    = (const float*)d_in[15];
    const float* cw2    = (const float*)d_in[16];
    const float* cb2    = (const float*)d_in[17];
    const float* caw1   = (const float*)d_in[18];
    const float* cab1   = (const float*)d_in[19];
    const float* caw2   = (const float*)d_in[20];
    const float* cab2   = (const float*)d_in[21];
    const float* g2     = (const float*)d_in[22];
    const float* b2     = (const float*)d_in[23];
    const float* fc1_w  = (const float*)d_in[24];
    const float* fc1_b  = (const float*)d_in[25];
    const float* fc2_w  = (const float*)d_in[26];
    const float* fc2_b  = (const float*)d_in[27];
    float* outp = (float*)d_out;

    uint16_t *p_xn, *p_ln2, *p_ao, *p_y1, *p_qkv, *p_h, *p_bt;
    uint16_t *p_w1m, *p_w2m, *p_wq, *p_wp, *p_wf1, *p_wf2;
    float *p_x1, *p_y2, *p_pool, *p_catt;
    cudaGetSymbolAddress((void**)&p_xn,   g_xn);
    cudaGetSymbolAddress((void**)&p_ln2,  g_ln2);
    cudaGetSymbolAddress((void**)&p_ao,   g_ao);
    cudaGetSymbolAddress((void**)&p_x1,   g_x1);
    cudaGetSymbolAddress((void**)&p_y1,   g_y1);
    cudaGetSymbolAddress((void**)&p_y2,   g_y2);
    cudaGetSymbolAddress((void**)&p_qkv,  g_qkv);
    cudaGetSymbolAddress((void**)&p_h,    g_hbuf);
    cudaGetSymbolAddress((void**)&p_bt,   g_biasT);
    cudaGetSymbolAddress((void**)&p_w1m,  g_w1m);
    cudaGetSymbolAddress((void**)&p_w2m,  g_w2m);
    cudaGetSymbolAddress((void**)&p_wq,   g_wq);
    cudaGetSymbolAddress((void**)&p_wp,   g_wp);
    cudaGetSymbolAddress((void**)&p_wf1,  g_wf1);
    cudaGetSymbolAddress((void**)&p_wf2,  g_wf2);
    cudaGetSymbolAddress((void**)&p_pool, g_pool);
    cudaGetSymbolAddress((void**)&p_catt, g_catt);

    cudaFuncSetAttribute(attn_mma, cudaFuncAttributeMaxDynamicSharedMemorySize, ATTN_SMEM);

    // prep: weight/bias repack to bf16
    repack1_kernel<<<(27 * 64 * 192 + 255) / 256, 256>>>(cw1, p_w1m);
    repack2_kernel<<<(27 * 192 * 64 + 255) / 256, 256>>>(cw2, p_w2m);
    wpack_kernel<<<(540 * 192 + 255) / 256, 256>>>(qkv_w, p_wq, 540, 180, 192);
    wpack_kernel<<<(180 * 192 + 255) / 256, 256>>>(proj_w, p_wp, 180, 180, 192);
    wpack_kernel<<<(720 * 192 + 255) / 256, 256>>>(fc1_w, p_wf1, 720, 180, 192);
    wpack_kernel<<<(180 * HIDP + 255) / 256, 256>>>(fc2_w, p_wf2, 180, 720, HIDP);
    biasprep_kernel<<<512, 512>>>(rpi, rpb, p_bt);
    zero_pool_kernel<<<1, 384>>>(p_pool);

    // LN1 -> bf16 (stride 192; pads stay zero from static init)
    ln_kernel<<<LT / 8, 256>>>(x, CC, g1, b1, p_xn, CP);

    // CAB conv branch
    mma_conv<1><<<dim3(LT / 128, 1), 256>>>(p_xn, p_w1m, cb1, p_y1);
    mma_conv<2><<<dim3(LT / 128, 3), 256>>>(p_y1, p_w2m, cb2, p_y2);
    pooled_kernel<<<LT / 64, 192>>>(p_y2, p_pool);
    catt_kernel<<<1, 192>>>(p_pool, caw1, cab1, caw2, cab2, p_catt);

    // window attention path
    mma_gemm<0, true><<<dim3(LT / 128, 9), 256>>>(p_xn, CP, p_wq, qkv_b, p_qkv,
                                                  540, 192, 0, nullptr, nullptr, nullptr);
    attn_mma<<<dim3(4, NWIN * NHEADS), 256, ATTN_SMEM>>>(p_qkv, p_bt, p_ao);
    mma_gemm<1, false><<<dim3(LT / 128, 3), 256>>>(p_ao, CP, p_wp, proj_b, p_x1,
                                                   180, 192, 0, x, p_y2, p_catt);

    // MLP
    ln_kernel<<<LT / 8, 256>>>(p_x1, CC, g2, b2, p_ln2, CP);
    mma_gemm<2, false><<<dim3(LT / 128, 12), 256>>>(p_ln2, CP, p_wf1, fc1_b, p_h,
                                                    720, 192, HIDP, nullptr, nullptr, nullptr);
    mma_gemm<3, false><<<dim3(LT / 128, 3), 256>>>(p_h, HIDP, p_wf2, fc2_b, outp,
                                                   180, HIDP, 0, p_x1, nullptr, nullptr);
}

// round 10
// speedup vs baseline: 5.6805x; 1.0159x over previous
#include <cuda_runtime.h>
#include <math.h>
#include <stdint.h>

// ---------------- problem constants ----------------
#define BB 2
#define CC 180
#define CP 192              // padded channel stride (multiple of 32)
#define DD 16
#define HH 32
#define WW 32
#define LL 16384            // D*H*W
#define LT 32768            // B*L
#define NHEADS 6
#define HDIM 30
#define NTOK 512
#define NWIN 64
#define HIDD 720
#define HIDP 736            // padded fc2 K (multiple of 32)
#define QSCALE 0.18257418583505537f  // 30^-0.5

// ---------------- device scratch (zero-initialized; pads never written) ----------------
__device__ uint16_t g_xn[LT * CP];              // bf16, LN1 out
__device__ uint16_t g_ln2[LT * CP];             // bf16, LN2 out
__device__ uint16_t g_ao[LT * CP];              // bf16, attention out (window order)
__device__ float    g_x1[LT * CC];              // fp32 residual
__device__ uint16_t g_y1[LT * 64];              // bf16 conv1 out (gelu'd, 64-pad)
__device__ uint16_t g_y2[LT * CC];              // bf16 conv2 out + bias
__device__ uint16_t g_qkv[NWIN * 3 * NHEADS * NTOK * HDIM];  // bf16
__device__ uint16_t g_hbuf[LT * HIDP];          // bf16 fc1 gelu out (K-pad 736)
__device__ uint16_t g_biasT[NHEADS * NTOK * NTOK]; // bf16 [h][query][key]
__device__ uint16_t g_w1m[27 * 64 * 192];       // bf16 [tap][cout64][cin192]
__device__ uint16_t g_w2m[27 * 192 * 64];       // bf16 [tap][cout192][cin64]
__device__ uint16_t g_wq[576 * 192];            // bf16 qkv_w (row-pad 576)
__device__ uint16_t g_wp[192 * 192];            // bf16 proj_w (row-pad 192)
__device__ uint16_t g_wf1[768 * 192];           // bf16 fc1_w (row-pad 768)
__device__ uint16_t g_wf2[192 * HIDP];          // bf16 fc2_w (row-pad 192)
__device__ float g_pool[2 * CC];
__device__ float g_catt[2 * CC];

// window (win, n) -> flat row b*LL + l  (bijection)
__device__ __forceinline__ int win_src_row(int r) {
    int win = r >> 9, n = r & 511;
    int sb = win >> 2, wq = win & 3;
    int b = sb >> 3, isp = sb & 7;
    int id = isp >> 2, ih = (isp >> 1) & 1, iw = isp & 1;
    int nhi = wq >> 1, nwi = wq & 1;
    int wd = n >> 6, wh = (n >> 3) & 7, ww = n & 7;
    int d = wd * 2 + id;
    int h = (nhi * 8 + wh) * 2 + ih;
    int w = (nwi * 8 + ww) * 2 + iw;
    return ((b * DD + d) * HH + h) * WW + w;
}

__device__ __forceinline__ float gelu_exact(float v) {
    return 0.5f * v * (1.f + erff(v * 0.70710678118654752f));
}

// pack two floats -> bf16x2 word (lo = first)
__device__ __forceinline__ uint32_t pk(float lo, float hi) {
    uint32_t r;
    asm("cvt.rn.bf16x2.f32 %0, %1, %2;" : "=r"(r) : "f"(hi), "f"(lo));
    return r;
}
__device__ __forceinline__ uint16_t f2b(float v) { return (uint16_t)pk(v, 0.f); }
__device__ __forceinline__ float b2f(uint32_t bits16) {
    return __int_as_float((int)(bits16 << 16));
}

__device__ __forceinline__ void mma16(float* c, const uint32_t* a, const uint32_t* b) {
    asm volatile(
        "mma.sync.aligned.m16n8k16.row.col.f32.bf16.bf16.f32 "
        "{%0,%1,%2,%3},{%4,%5,%6,%7},{%8,%9},{%0,%1,%2,%3};\n"
        : "+f"(c[0]), "+f"(c[1]), "+f"(c[2]), "+f"(c[3])
        : "r"(a[0]), "r"(a[1]), "r"(a[2]), "r"(a[3]), "r"(b[0]), "r"(b[1]));
}

// ldmatrix x4 (b16)
__device__ __forceinline__ void ldsm4(uint32_t* r, const void* p) {
    uint32_t addr = (uint32_t)__cvta_generic_to_shared(p);
    asm volatile("ldmatrix.sync.aligned.m8n8.x4.shared.b16 {%0,%1,%2,%3}, [%4];"
        : "=r"(r[0]), "=r"(r[1]), "=r"(r[2]), "=r"(r[3]) : "r"(addr));
}

// cp.async 16B, with zfill predication (sz=0 -> no memory access, zero fill)
__device__ __forceinline__ void cpa16(void* smem, const void* gmem, bool pred) {
    uint32_t s = (uint32_t)__cvta_generic_to_shared(smem);
    int sz = pred ? 16 : 0;
    asm volatile("cp.async.cg.shared.global [%0], [%1], 16, %2;\n"
                 :: "r"(s), "l"(gmem), "r"(sz));
}
__device__ __forceinline__ void cpcommit() {
    asm volatile("cp.async.commit_group;\n");
}
template <int N>
__device__ __forceinline__ void cpwait() {
    asm volatile("cp.async.wait_group %0;\n" :: "n"(N));
}

// one BK=32 tile via ldmatrix: warp tile 32x32, 2 k16 steps
__device__ __forceinline__ void tile_mma32(const uint32_t (*As)[20], const uint32_t (*Bs)[20],
                                           float acc[2][4][4], int wm, int wn, int lane) {
    const int ar = wm * 32 + (lane & 15);
    const int aw = (lane >> 4) * 4;
    const int br = wn * 32 + ((lane >> 4) << 3) + (lane & 7);
    const int bw = ((lane >> 3) & 1) * 4;
#pragma unroll
    for (int ks = 0; ks < 2; ks++) {
        uint32_t a[2][4], b[2][4];
        ldsm4(a[0], &As[ar][ks * 8 + aw]);
        ldsm4(a[1], &As[ar + 16][ks * 8 + aw]);
        ldsm4(b[0], &Bs[br][ks * 8 + bw]);
        ldsm4(b[1], &Bs[br + 16][ks * 8 + bw]);
#pragma unroll
        for (int mt = 0; mt < 2; mt++)
#pragma unroll
            for (int p = 0; p < 2; p++) {
                mma16(acc[mt][p * 2],     a[mt], b[p]);
                mma16(acc[mt][p * 2 + 1], a[mt], b[p] + 2);
            }
    }
}

// ---------------- prep kernels ----------------
__global__ void wpack_kernel(const float* __restrict__ w, uint16_t* __restrict__ out,
                             int N, int K, int Ksm) {
    int idx = blockIdx.x * 256 + threadIdx.x;
    if (idx >= N * Ksm) return;
    int n = idx / Ksm, k = idx - n * Ksm;
    out[idx] = (k < K) ? f2b(w[n * K + k]) : (uint16_t)0;
}

__global__ void repack1_kernel(const float* __restrict__ cw1, uint16_t* __restrict__ w1m) {
    int idx = blockIdx.x * 256 + threadIdx.x;
    if (idx >= 27 * 64 * 192) return;
    int tap = idx / (64 * 192);
    int rem = idx - tap * 64 * 192;
    int o = rem / 192, c = rem - o * 192;
    w1m[idx] = (o < 60 && c < 180) ? f2b(cw1[(o * 180 + c) * 27 + tap]) : (uint16_t)0;
}

__global__ void repack2_kernel(const float* __restrict__ cw2, uint16_t* __restrict__ w2m) {
    int idx = blockIdx.x * 256 + threadIdx.x;
    if (idx >= 27 * 192 * 64) return;
    int tap = idx / (192 * 64);
    int rem = idx - tap * 192 * 64;
    int o = rem >> 6, c = rem & 63;
    w2m[idx] = (o < 180 && c < 60) ? f2b(cw2[(o * 60 + c) * 27 + tap]) : (uint16_t)0;
}

// bias table: [h][query][key] bf16
__global__ void biasprep_kernel(const int* __restrict__ rpi, const float* __restrict__ rpb,
                                uint16_t* __restrict__ biasT) {
    int q = blockIdx.x, k = threadIdx.x;
    int t = rpi[q * 512 + k];
#pragma unroll
    for (int h = 0; h < NHEADS; h++)
        biasT[(h * 512 + q) * 512 + k] = f2b(rpb[t * NHEADS + h]);
}

__global__ void zero_pool_kernel(float* __restrict__ pool) {
    if (threadIdx.x < 2 * CC) pool[threadIdx.x] = 0.f;
}

// ---------------- layernorm (warp per row), bf16 out ----------------
__global__ void __launch_bounds__(256) ln_kernel(const float* __restrict__ in, int ins,
        const float* __restrict__ gg, const float* __restrict__ bb,
        uint16_t* __restrict__ outp, int outs) {
    int row = blockIdx.x * 8 + (threadIdx.x >> 5);
    int lane = threadIdx.x & 31;
    const float* p = in + (long)row * ins;
    float v[6];
    float s = 0.f;
#pragma unroll
    for (int i = 0; i < 6; i++) {
        int c = lane + i * 32;
        v[i] = (c < CC) ? p[c] : 0.f;
        s += v[i];
    }
    for (int o = 16; o; o >>= 1) s += __shfl_xor_sync(~0u, s, o);
    float mean = s * (1.f / CC);
    float vs = 0.f;
#pragma unroll
    for (int i = 0; i < 6; i++) {
        int c = lane + i * 32;
        float d = (c < CC) ? (v[i] - mean) : 0.f;
        vs += d * d;
    }
    for (int o = 16; o; o >>= 1) vs += __shfl_xor_sync(~0u, vs, o);
    float inv = rsqrtf(vs * (1.f / CC) + 1e-5f);
    uint16_t* q = outp + (long)row * outs;
#pragma unroll
    for (int i = 0; i < 6; i++) {
        int c = lane + i * 32;
        if (c < CC) q[c] = f2b((v[i] - mean) * inv * gg[c] + bb[c]);
    }
}

// ---------------- bf16 MMA GEMM, cp.async 3-stage, BK=32, fused epilogues ----------------
// EPI 0: qkv scatter bf16 (+q scale); 1: proj scatter + triple residual (e1 = bf16 y2);
//     2: gelu -> bf16 (stride OS); 3: residual -> fp32 out
template <int EPI, bool GATHER>
__global__ void __launch_bounds__(256) mma_gemm(
        const uint16_t* __restrict__ A, int Asr,
        const uint16_t* __restrict__ Wm, const float* __restrict__ bias,
        void* __restrict__ CoutV, int Nc, int Ksm, int OS,
        const float* __restrict__ e0, const uint16_t* __restrict__ e1,
        const float* __restrict__ e2) {
    __shared__ uint32_t As[3][128][20];
    __shared__ uint32_t Bs[3][64][20];
    const int tid = threadIdx.x;
    const int row0 = blockIdx.x * 128, col0 = blockIdx.y * 64;
    const int T = Ksm >> 5;

    int ar[2], akq[2];
    long abase[2];
#pragma unroll
    for (int i = 0; i < 2; i++) {
        int id = tid + i * 256;
        ar[i] = id >> 2;
        akq[i] = id & 3;
        int r = row0 + ar[i];
        int src = GATHER ? win_src_row(r) : r;
        abase[i] = (long)src * Asr + akq[i] * 8;
    }
    const int bn = tid >> 2, bkq = tid & 3;
    const long bbase = (long)(col0 + bn) * Ksm + bkq * 8;

    const int wid = tid >> 5, lane = tid & 31, lr = lane >> 2, lc = lane & 3;
    const int wm = wid >> 1, wn = wid & 1;
    float acc[2][4][4] = {};

    auto loadT = [&](int t) {
        int buf = t % 3;
        int k0 = t * 32;
#pragma unroll
        for (int i = 0; i < 2; i++)
            cpa16(&As[buf][ar[i]][akq[i] * 4], A + abase[i] + k0, true);
        cpa16(&Bs[buf][bn][bkq * 4], Wm + bbase + k0, true);
        cpcommit();
    };

    loadT(0);
    loadT(1);
    for (int t = 0; t < T; t++) {
        if (t + 1 < T) cpwait<1>(); else cpwait<0>();
        __syncthreads();
        if (t + 2 < T) loadT(t + 2);
        tile_mma32(As[t % 3], Bs[t % 3], acc, wm, wn, lane);
    }

#pragma unroll
    for (int mt = 0; mt < 2; mt++) {
#pragma unroll
        for (int nt = 0; nt < 4; nt++) {
            int rbase = row0 + wm * 32 + mt * 16 + lr;
            int cb = col0 + wn * 32 + nt * 8 + lc * 2;   // even
            if (cb >= Nc) continue;
#pragma unroll
            for (int half = 0; half < 2; half++) {
                int row = rbase + half * 8;
                float v0 = acc[mt][nt][half * 2] + bias[cb];
                float v1 = acc[mt][nt][half * 2 + 1] + bias[cb + 1];
                if constexpr (EPI == 0) {
                    int tq = cb / 180;
                    int rem = cb - tq * 180;
                    int hh = rem / 30, hd = rem - hh * 30;   // hd even
                    if (tq == 0) { v0 *= QSCALE; v1 *= QSCALE; }
                    int win = row >> 9, n = row & 511;
                    long idx = ((long)((win * 3 + tq) * NHEADS + hh) * NTOK + n) * HDIM + hd;
                    ((uint32_t*)CoutV)[idx >> 1] = pk(v0, v1);
                } else if constexpr (EPI == 1) {
                    int src = win_src_row(row);
                    long gi = (long)src * CC + cb;
                    int b = src >> 14;
                    uint32_t uy = ((const uint32_t*)e1)[gi >> 1];
                    float* Cf = (float*)CoutV;
                    Cf[gi]     = e0[gi]     + v0 + 0.01f * b2f(uy & 0xFFFF) * e2[b * CC + cb];
                    Cf[gi + 1] = e0[gi + 1] + v1 + 0.01f * b2f(uy >> 16)    * e2[b * CC + cb + 1];
                } else if constexpr (EPI == 2) {
                    long idx = (long)row * OS + cb;
                    ((uint32_t*)CoutV)[idx >> 1] = pk(gelu_exact(v0), gelu_exact(v1));
                } else {
                    long gi = (long)row * CC + cb;
                    float* Cf = (float*)CoutV;
                    Cf[gi]     = e0[gi]     + v0;
                    Cf[gi + 1] = e0[gi + 1] + v1;
                }
            }
        }
    }
}

// ---------------- bf16 MMA implicit-GEMM 3x3x3 conv, cp.async 3-stage, BK=32 ----------------
template <int CV>
__global__ void __launch_bounds__(256) mma_conv(
        const uint16_t* __restrict__ A, const uint16_t* __restrict__ Wt,
        const float* __restrict__ bias, void* __restrict__ OutV) {
    constexpr int Asr = (CV == 1) ? 192 : 64;
    constexpr int KT = (CV == 1) ? 6 : 2;      // 32-wide k-tiles per tap
    constexpr int T = 27 * KT;
    constexpr int Wn = (CV == 1) ? 64 : 192;
    constexpr int Wk = (CV == 1) ? 192 : 64;
    __shared__ uint32_t As[3][128][20];
    __shared__ uint32_t Bs[3][64][20];
    const int tid = threadIdx.x;
    const int row0 = blockIdx.x * 128, col0 = blockIdx.y * 64;

    int ar[2], akq[2], pd[2], ph[2], pw[2];
#pragma unroll
    for (int i = 0; i < 2; i++) {
        int id = tid + i * 256;
        ar[i] = id >> 2;
        akq[i] = id & 3;
        int p = row0 + ar[i];
        pd[i] = (p >> 10) & 15;
        ph[i] = (p >> 5) & 31;
        pw[i] = p & 31;
    }
    const int bn = tid >> 2, bkq = tid & 3;

    const int wid = tid >> 5, lane = tid & 31, lr = lane >> 2, lc = lane & 3;
    const int wm = wid >> 1, wn = wid & 1;
    float acc[2][4][4] = {};

    auto loadT = [&](int t) {
        int buf = t % 3;
        int tap = t / KT;
        int kt = t - tap * KT;
        int k0 = kt * 32;
        int kd = tap / 9 - 1;
        int r9 = tap - (kd + 1) * 9;
        int kh = r9 / 3 - 1;
        int kw = r9 - (kh + 1) * 3 - 1;
        int off = (kd << 10) + (kh << 5) + kw;
#pragma unroll
        for (int i = 0; i < 2; i++) {
            bool valid = ((unsigned)(pd[i] + kd) < 16u) &&
                         ((unsigned)(ph[i] + kh) < 32u) &&
                         ((unsigned)(pw[i] + kw) < 32u);
            const uint16_t* src = valid
                ? A + (long)(row0 + ar[i] + off) * Asr + k0 + akq[i] * 8 : A;
            cpa16(&As[buf][ar[i]][akq[i] * 4], src, valid);
        }
        cpa16(&Bs[buf][bn][bkq * 4],
              Wt + ((long)tap * Wn + col0 + bn) * Wk + k0 + bkq * 8, true);
        cpcommit();
    };

    loadT(0);
    loadT(1);
    for (int t = 0; t < T; t++) {
        if (t + 1 < T) cpwait<1>(); else cpwait<0>();
        __syncthreads();
        if (t + 2 < T) loadT(t + 2);
        tile_mma32(As[t % 3], Bs[t % 3], acc, wm, wn, lane);
    }

#pragma unroll
    for (int mt = 0; mt < 2; mt++) {
#pragma unroll
        for (int nt = 0; nt < 4; nt++) {
            int rbase = row0 + wm * 32 + mt * 16 + lr;
            int cb = col0 + wn * 32 + nt * 8 + lc * 2;   // even
#pragma unroll
            for (int half = 0; half < 2; half++) {
                int row = rbase + half * 8;
                float v0 = acc[mt][nt][half * 2];
                float v1 = acc[mt][nt][half * 2 + 1];
                if constexpr (CV == 1) {
                    v0 = gelu_exact(v0 + ((cb < 60) ? bias[cb] : 0.f));
                    v1 = gelu_exact(v1 + ((cb + 1 < 60) ? bias[cb + 1] : 0.f));
                    ((uint32_t*)OutV)[((long)row * 64 + cb) >> 1] = pk(v0, v1);
                } else {
                    if (cb < CC) {
                        ((uint32_t*)OutV)[((long)row * CC + cb) >> 1] =
                            pk(v0 + bias[cb], v1 + bias[cb + 1]);
                    }
                }
            }
        }
    }
}

// ---------------- pooled sum + channel attention ----------------
__global__ void pooled_kernel(const uint16_t* __restrict__ y2, float* __restrict__ pool) {
    int r0 = blockIdx.x * 64;
    int b = r0 >> 14;
    int c = threadIdx.x;
    if (c >= CC) return;
    float s = 0.f;
    for (int i = 0; i < 64; i++) s += b2f(y2[(long)(r0 + i) * CC + c]);
    atomicAdd(&pool[b * CC + c], s);
}

__global__ void catt_kernel(const float* __restrict__ pool,
        const float* __restrict__ caw1, const float* __restrict__ cab1,
        const float* __restrict__ caw2, const float* __restrict__ cab2,
        float* __restrict__ catt) {
    __shared__ float sq[2][8];
    int tid = threadIdx.x;
    if (tid < 12) {
        int b = tid / 6, j = tid % 6;
        float s = cab1[j];
        for (int c = 0; c < CC; c++)
            s += (pool[b * CC + c] * (1.f / LL)) * caw1[j * CC + c];
        sq[b][j] = fmaxf(s, 0.f);
    }
    __syncthreads();
    if (tid < CC) {
        for (int b = 0; b < 2; b++) {
            float s = cab2[tid];
#pragma unroll
            for (int j = 0; j < 6; j++) s += sq[b][j] * caw2[tid * 6 + j];
            catt[b * CC + tid] = 1.f / (1.f + __expf(-s));
        }
    }
}

// ---------------- bf16 MMA flash attention, register-resident softmax ----------------
// block = (q-tile 128, win*6+head); 256 thr = 8 warps; warp w owns q-rows [16w,16w+16),
// ALL 128 keys of each tile (16 m16n8 S-frags in regs). Row stats via 2 shfl_xor.
// P repacked bf16 A-frags in registers (C-frag pair == A-frag layout). No S smem.
__global__ void __launch_bounds__(256) attn_mma(const uint16_t* __restrict__ qkv,
        const uint16_t* __restrict__ biasQ, uint16_t* __restrict__ outp) {
    __shared__ uint32_t Qs[128 * 20];
    __shared__ uint32_t Ks[128 * 20];
    __shared__ uint32_t Vs[32 * 68];

    const int qt = blockIdx.x;
    const int win = blockIdx.y / NHEADS, hh = blockIdx.y % NHEADS;
    const uint32_t* qbu = (const uint32_t*)(qkv +
        ((long)((win * 3 + 0) * NHEADS + hh) * NTOK + qt * 128) * HDIM);
    const uint32_t* kbu = (const uint32_t*)(qkv +
        (long)((win * 3 + 1) * NHEADS + hh) * NTOK * HDIM);
    const uint16_t* vb = qkv + (long)((win * 3 + 2) * NHEADS + hh) * NTOK * HDIM;
    const uint32_t* bqu = (const uint32_t*)(biasQ + ((long)(hh * NTOK) + qt * 128) * NTOK);

    const int tid = threadIdx.x;
    const int w = tid >> 5, lane = tid & 31, g = lane >> 2, lc = lane & 3;
    const int lar = lane & 15;
    const int law = (lane >> 4) * 4;
    const int lbr = ((lane >> 4) << 3) + (lane & 7);
    const int lbw = ((lane >> 3) & 1) * 4;

    // Q: 128 rows x 16 words (15 data = 30 bf16, word 15 zero)
    for (int idx = tid; idx < 128 * 16; idx += 256) {
        int r = idx >> 4, d = idx & 15;
        Qs[r * 20 + d] = (d < 15) ? qbu[r * 15 + d] : 0u;
    }
    __syncthreads();
    uint32_t qf[2][4];
    ldsm4(qf[0], &Qs[(w * 16 + lar) * 20 + law]);
    ldsm4(qf[1], &Qs[(w * 16 + lar) * 20 + 8 + law]);

    const int row0 = w * 16 + g;     // row within q-tile (this lane: row0, row0+8)
    float m0 = -1e30f, m1 = -1e30f, l0 = 0.f, l1 = 0.f;
    float oacc[4][4] = {};

    for (int t0 = 0; t0 < NTOK; t0 += 128) {
        __syncthreads();
        for (int idx = tid; idx < 128 * 16; idx += 256) {
            int r = idx >> 4, d = idx & 15;
            Ks[r * 20 + d] = (d < 15) ? kbu[(t0 + r) * 15 + d] : 0u;
        }
        // V transposed: Vs[d][j] = {V[2j][d], V[2j+1][d]}
        for (int idx = tid; idx < 32 * 64; idx += 256) {
            int d = idx >> 6, j = idx & 63;
            uint32_t u = 0u;
            if (d < HDIM) {
                uint32_t lo = vb[(long)(t0 + 2 * j) * HDIM + d];
                uint32_t hi = vb[(long)(t0 + 2 * j + 1) * HDIM + d];
                u = lo | (hi << 16);
            }
            Vs[d * 68 + j] = u;
        }
        __syncthreads();

        // S = Q K^T : warp tile 16(q) x 128(k) = 16 n8 frags
        float sacc[16][4] = {};
#pragma unroll
        for (int ks = 0; ks < 2; ks++) {
#pragma unroll
            for (int p = 0; p < 8; p++) {
                uint32_t b2[4];
                ldsm4(b2, &Ks[(p * 16 + lbr) * 20 + ks * 8 + lbw]);
                mma16(sacc[p * 2],     qf[ks], b2);
                mma16(sacc[p * 2 + 1], qf[ks], b2 + 2);
            }
        }

        // bias add + partial row max (in registers)
        float pm0 = -1e30f, pm1 = -1e30f;
#pragma unroll
        for (int nt = 0; nt < 16; nt++) {
            int c0 = t0 + nt * 8 + lc * 2;
            uint32_t u0 = bqu[((long)row0 * NTOK + c0) >> 1];
            uint32_t u1 = bqu[((long)(row0 + 8) * NTOK + c0) >> 1];
            sacc[nt][0] += b2f(u0 & 0xFFFF);
            sacc[nt][1] += b2f(u0 >> 16);
            sacc[nt][2] += b2f(u1 & 0xFFFF);
            sacc[nt][3] += b2f(u1 >> 16);
            pm0 = fmaxf(pm0, fmaxf(sacc[nt][0], sacc[nt][1]));
            pm1 = fmaxf(pm1, fmaxf(sacc[nt][2], sacc[nt][3]));
        }
        pm0 = fmaxf(pm0, __shfl_xor_sync(~0u, pm0, 1));
        pm0 = fmaxf(pm0, __shfl_xor_sync(~0u, pm0, 2));
        pm1 = fmaxf(pm1, __shfl_xor_sync(~0u, pm1, 1));
        pm1 = fmaxf(pm1, __shfl_xor_sync(~0u, pm1, 2));
        float nm0 = fmaxf(m0, pm0), nm1 = fmaxf(m1, pm1);
        float f0 = __expf(m0 - nm0), f1 = __expf(m1 - nm1);
        m0 = nm0; m1 = nm1;

        // exp + sum + pack P A-frags (C-frag pair (2k,2k+1) == A-frag for k16 step k)
        float ps0 = 0.f, ps1 = 0.f;
        uint32_t pf[8][4];
#pragma unroll
        for (int k2 = 0; k2 < 8; k2++) {
            float e00 = __expf(sacc[2 * k2][0] - m0);
            float e01 = __expf(sacc[2 * k2][1] - m0);
            float e10 = __expf(sacc[2 * k2][2] - m1);
            float e11 = __expf(sacc[2 * k2][3] - m1);
            float e20 = __expf(sacc[2 * k2 + 1][0] - m0);
            float e21 = __expf(sacc[2 * k2 + 1][1] - m0);
            float e30 = __expf(sacc[2 * k2 + 1][2] - m1);
            float e31 = __expf(sacc[2 * k2 + 1][3] - m1);
            ps0 += e00 + e01 + e20 + e21;
            ps1 += e10 + e11 + e30 + e31;
            pf[k2][0] = pk(e00, e01);
            pf[k2][1] = pk(e10, e11);
            pf[k2][2] = pk(e20, e21);
            pf[k2][3] = pk(e30, e31);
        }
        ps0 += __shfl_xor_sync(~0u, ps0, 1);
        ps0 += __shfl_xor_sync(~0u, ps0, 2);
        ps1 += __shfl_xor_sync(~0u, ps1, 1);
        ps1 += __shfl_xor_sync(~0u, ps1, 2);
        l0 = l0 * f0 + ps0;
        l1 = l1 * f1 + ps1;

        // rescale O, then O += P @ V (4 n8 d-tiles)
#pragma unroll
        for (int nt = 0; nt < 4; nt++) {
            oacc[nt][0] *= f0; oacc[nt][1] *= f0;
            oacc[nt][2] *= f1; oacc[nt][3] *= f1;
        }
#pragma unroll
        for (int k2 = 0; k2 < 8; k2++) {
            uint32_t ba[4], bb[4];
            ldsm4(ba, &Vs[lbr * 68 + k2 * 8 + lbw]);
            ldsm4(bb, &Vs[(lbr + 16) * 68 + k2 * 8 + lbw]);
            mma16(oacc[0], pf[k2], ba);
            mma16(oacc[1], pf[k2], ba + 2);
            mma16(oacc[2], pf[k2], bb);
            mma16(oacc[3], pf[k2], bb + 2);
        }
    }

    float i0 = 1.f / l0, i1 = 1.f / l1;
    uint16_t* ob = outp + (long)(win * NTOK + qt * 128 + w * 16) * CP + hh * HDIM;
#pragma unroll
    for (int nt = 0; nt < 4; nt++) {
        int c = nt * 8 + lc * 2;   // even
        if (c < HDIM) {
            *(uint32_t*)&ob[(long)g * CP + c] = pk(oacc[nt][0] * i0, oacc[nt][1] * i0);
            *(uint32_t*)&ob[(long)(g + 8) * CP + c] = pk(oacc[nt][2] * i1, oacc[nt][3] * i1);
        }
    }
}

// ---------------- host launch ----------------
extern "C" void kernel_launch(void* const* d_in, const int* in_sizes, int n_in,
                              void* d_out, int out_size) {
    const float* x      = (const float*)d_in[0];
    const int*   rpi    = (const int*)  d_in[4];
    const float* g1     = (const float*)d_in[7];
    const float* b1     = (const float*)d_in[8];
    const float* qkv_w  = (const float*)d_in[9];
    const float* qkv_b  = (const float*)d_in[10];
    const float* rpb    = (const float*)d_in[11];
    const float* proj_w = (const float*)d_in[12];
    const float* proj_b = (const float*)d_in[13];
    const float* cw1    = (const float*)d_in[14];
    const float* cb1    = (const float*)d_in[15];
    const float* cw2    = (const float*)d_in[16];
    const float* cb2    = (const float*)d_in[17];
    const float* caw1   = (const float*)d_in[18];
    const float* cab1   = (const float*)d_in[19];
    const float* caw2   = (const float*)d_in[20];
    const float* cab2   = (const float*)d_in[21];
    const float* g2     = (const float*)d_in[22];
    const float* b2     = (const float*)d_in[23];
    const float* fc1_w  = (const float*)d_in[24];
    const float* fc1_b  = (const float*)d_in[25];
    const float* fc2_w  = (const float*)d_in[26];
    const float* fc2_b  = (const float*)d_in[27];
    float* outp = (float*)d_out;

    uint16_t *p_xn, *p_ln2, *p_ao, *p_y1, *p_y2, *p_qkv, *p_h, *p_bt;
    uint16_t *p_w1m, *p_w2m, *p_wq, *p_wp, *p_wf1, *p_wf2;
    float *p_x1, *p_pool, *p_catt;
    cudaGetSymbolAddress((void**)&p_xn,   g_xn);
    cudaGetSymbolAddress((void**)&p_ln2,  g_ln2);
    cudaGetSymbolAddress((void**)&p_ao,   g_ao);
    cudaGetSymbolAddress((void**)&p_x1,   g_x1);
    cudaGetSymbolAddress((void**)&p_y1,   g_y1);
    cudaGetSymbolAddress((void**)&p_y2,   g_y2);
    cudaGetSymbolAddress((void**)&p_qkv,  g_qkv);
    cudaGetSymbolAddress((void**)&p_h,    g_hbuf);
    cudaGetSymbolAddress((void**)&p_bt,   g_biasT);
    cudaGetSymbolAddress((void**)&p_w1m,  g_w1m);
    cudaGetSymbolAddress((void**)&p_w2m,  g_w2m);
    cudaGetSymbolAddress((void**)&p_wq,   g_wq);
    cudaGetSymbolAddress((void**)&p_wp,   g_wp);
    cudaGetSymbolAddress((void**)&p_wf1,  g_wf1);
    cudaGetSymbolAddress((void**)&p_wf2,  g_wf2);
    cudaGetSymbolAddress((void**)&p_pool, g_pool);
    cudaGetSymbolAddress((void**)&p_catt, g_catt);

    // prep: weight/bias repack to bf16
    repack1_kernel<<<(27 * 64 * 192 + 255) / 256, 256>>>(cw1, p_w1m);
    repack2_kernel<<<(27 * 192 * 64 + 255) / 256, 256>>>(cw2, p_w2m);
    wpack_kernel<<<(540 * 192 + 255) / 256, 256>>>(qkv_w, p_wq, 540, 180, 192);
    wpack_kernel<<<(180 * 192 + 255) / 256, 256>>>(proj_w, p_wp, 180, 180, 192);
    wpack_kernel<<<(720 * 192 + 255) / 256, 256>>>(fc1_w, p_wf1, 720, 180, 192);
    wpack_kernel<<<(180 * HIDP + 255) / 256, 256>>>(fc2_w, p_wf2, 180, 720, HIDP);
    biasprep_kernel<<<512, 512>>>(rpi, rpb, p_bt);
    zero_pool_kernel<<<1, 384>>>(p_pool);

    // LN1 -> bf16 (stride 192; pads stay zero from static init)
    ln_kernel<<<LT / 8, 256>>>(x, CC, g1, b1, p_xn, CP);

    // CAB conv branch
    mma_conv<1><<<dim3(LT / 128, 1), 256>>>(p_xn, p_w1m, cb1, p_y1);
    mma_conv<2><<<dim3(LT / 128, 3), 256>>>(p_y1, p_w2m, cb2, p_y2);
    pooled_kernel<<<LT / 64, 192>>>(p_y2, p_pool);
    catt_kernel<<<1, 192>>>(p_pool, caw1, cab1, caw2, cab2, p_catt);

    // window attention path
    mma_gemm<0, true><<<dim3(LT / 128, 9), 256>>>(p_xn, CP, p_wq, qkv_b, p_qkv,
                                                  540, 192, 0, nullptr, nullptr, nullptr);
    attn_mma<<<dim3(4, NWIN * NHEADS), 256>>>(p_qkv, p_bt, p_ao);
    mma_gemm<1, false><<<dim3(LT / 128, 3), 256>>>(p_ao, CP, p_wp, proj_b, p_x1,
                                                   180, 192, 0, x, p_y2, p_catt);

    // MLP
    ln_kernel<<<LT / 8, 256>>>(p_x1, CC, g2, b2, p_ln2, CP);
    mma_gemm<2, false><<<dim3(LT / 128, 12), 256>>>(p_ln2, CP, p_wf1, fc1_b, p_h,
                                                    720, 192, HIDP, nullptr, nullptr, nullptr);
    mma_gemm<3, false><<<dim3(LT / 128, 3), 256>>>(p_h, HIDP, p_wf2, fc2_b, outp,
                                                   180, HIDP, 0, p_x1, nullptr, nullptr);
}

// round 12
// speedup vs baseline: 6.2697x; 1.1037x over previous
#include <cuda_runtime.h>
#include <math.h>
#include <stdint.h>

// ---------------- problem constants ----------------
#define BB 2
#define CC 180
#define CP 192              // padded channel stride (multiple of 32)
#define DD 16
#define HH 32
#define WW 32
#define LL 16384            // D*H*W
#define LT 32768            // B*L
#define NHEADS 6
#define HDIM 30
#define NTOK 512
#define NWIN 64
#define HIDD 720
#define HIDP 736            // padded fc2 K (multiple of 32)
#define QSCALE 0.18257418583505537f  // 30^-0.5

// ---------------- device scratch (zero-initialized; pads never written) ----------------
__device__ uint16_t g_xn[LT * CP];              // bf16, LN1 out
__device__ uint16_t g_ln2[LT * CP];             // bf16, LN2 out
__device__ uint16_t g_ao[LT * CP];              // bf16, attention out (window order)
__device__ float    g_x1[LT * CC];              // fp32 residual
__device__ uint16_t g_y1[LT * 64];              // bf16 conv1 out (gelu'd, 64-pad)
__device__ uint16_t g_y2[LT * CC];              // bf16 conv2 out + bias
__device__ uint16_t g_qkv[NWIN * 3 * NHEADS * NTOK * HDIM];  // bf16
__device__ uint16_t g_hbuf[LT * HIDP];          // bf16 fc1 gelu out (K-pad 736)
__device__ uint16_t g_biasT[NHEADS * NTOK * NTOK]; // bf16 [h][query][key]
__device__ uint16_t g_w1m[27 * 64 * 192];       // bf16 [tap][cout64][cin192]
__device__ uint16_t g_w2m[27 * 192 * 64];       // bf16 [tap][cout192][cin64]
__device__ uint16_t g_wq[576 * 192];            // bf16 qkv_w (row-pad 576)
__device__ uint16_t g_wp[192 * 192];            // bf16 proj_w (row-pad 192)
__device__ uint16_t g_wf1[768 * 192];           // bf16 fc1_w (row-pad 768)
__device__ uint16_t g_wf2[192 * HIDP];          // bf16 fc2_w (row-pad 192)
__device__ float g_pool[2 * CC];
__device__ float g_catt[2 * CC];

// window (win, n) -> flat row b*LL + l  (bijection)
__device__ __forceinline__ int win_src_row(int r) {
    int win = r >> 9, n = r & 511;
    int sb = win >> 2, wq = win & 3;
    int b = sb >> 3, isp = sb & 7;
    int id = isp >> 2, ih = (isp >> 1) & 1, iw = isp & 1;
    int nhi = wq >> 1, nwi = wq & 1;
    int wd = n >> 6, wh = (n >> 3) & 7, ww = n & 7;
    int d = wd * 2 + id;
    int h = (nhi * 8 + wh) * 2 + ih;
    int w = (nwi * 8 + ww) * 2 + iw;
    return ((b * DD + d) * HH + h) * WW + w;
}

__device__ __forceinline__ float gelu_exact(float v) {
    return 0.5f * v * (1.f + erff(v * 0.70710678118654752f));
}

// pack two floats -> bf16x2 word (lo = first)
__device__ __forceinline__ uint32_t pk(float lo, float hi) {
    uint32_t r;
    asm("cvt.rn.bf16x2.f32 %0, %1, %2;" : "=r"(r) : "f"(hi), "f"(lo));
    return r;
}
__device__ __forceinline__ uint16_t f2b(float v) { return (uint16_t)pk(v, 0.f); }
__device__ __forceinline__ float b2f(uint32_t bits16) {
    return __int_as_float((int)(bits16 << 16));
}

__device__ __forceinline__ void mma16(float* c, const uint32_t* a, const uint32_t* b) {
    asm volatile(
        "mma.sync.aligned.m16n8k16.row.col.f32.bf16.bf16.f32 "
        "{%0,%1,%2,%3},{%4,%5,%6,%7},{%8,%9},{%0,%1,%2,%3};\n"
        : "+f"(c[0]), "+f"(c[1]), "+f"(c[2]), "+f"(c[3])
        : "r"(a[0]), "r"(a[1]), "r"(a[2]), "r"(a[3]), "r"(b[0]), "r"(b[1]));
}

// ldmatrix x4 (b16)
__device__ __forceinline__ void ldsm4(uint32_t* r, const void* p) {
    uint32_t addr = (uint32_t)__cvta_generic_to_shared(p);
    asm volatile("ldmatrix.sync.aligned.m8n8.x4.shared.b16 {%0,%1,%2,%3}, [%4];"
        : "=r"(r[0]), "=r"(r[1]), "=r"(r[2]), "=r"(r[3]) : "r"(addr));
}

// cp.async 16B, with zfill predication (sz=0 -> no memory access, zero fill)
__device__ __forceinline__ void cpa16(void* smem, const void* gmem, bool pred) {
    uint32_t s = (uint32_t)__cvta_generic_to_shared(smem);
    int sz = pred ? 16 : 0;
    asm volatile("cp.async.cg.shared.global [%0], [%1], 16, %2;\n"
                 :: "r"(s), "l"(gmem), "r"(sz));
}
__device__ __forceinline__ void cpcommit() {
    asm volatile("cp.async.commit_group;\n");
}
template <int N>
__device__ __forceinline__ void cpwait() {
    asm volatile("cp.async.wait_group %0;\n" :: "n"(N));
}

// one BK=32 tile via ldmatrix: warp tile 32x32, 2 k16 steps
__device__ __forceinline__ void tile_mma32(const uint32_t (*As)[20], const uint32_t (*Bs)[20],
                                           float acc[2][4][4], int wm, int wn, int lane) {
    const int ar = wm * 32 + (lane & 15);
    const int aw = (lane >> 4) * 4;
    const int br = wn * 32 + ((lane >> 4) << 3) + (lane & 7);
    const int bw = ((lane >> 3) & 1) * 4;
#pragma unroll
    for (int ks = 0; ks < 2; ks++) {
        uint32_t a[2][4], b[2][4];
        ldsm4(a[0], &As[ar][ks * 8 + aw]);
        ldsm4(a[1], &As[ar + 16][ks * 8 + aw]);
        ldsm4(b[0], &Bs[br][ks * 8 + bw]);
        ldsm4(b[1], &Bs[br + 16][ks * 8 + bw]);
#pragma unroll
        for (int mt = 0; mt < 2; mt++)
#pragma unroll
            for (int p = 0; p < 2; p++) {
                mma16(acc[mt][p * 2],     a[mt], b[p]);
                mma16(acc[mt][p * 2 + 1], a[mt], b[p] + 2);
            }
    }
}

// ---------------- prep kernels ----------------
__global__ void wpack_kernel(const float* __restrict__ w, uint16_t* __restrict__ out,
                             int N, int K, int Ksm) {
    int idx = blockIdx.x * 256 + threadIdx.x;
    if (idx >= N * Ksm) return;
    int n = idx / Ksm, k = idx - n * Ksm;
    out[idx] = (k < K) ? f2b(w[n * K + k]) : (uint16_t)0;
}

__global__ void repack1_kernel(const float* __restrict__ cw1, uint16_t* __restrict__ w1m) {
    int idx = blockIdx.x * 256 + threadIdx.x;
    if (idx >= 27 * 64 * 192) return;
    int tap = idx / (64 * 192);
    int rem = idx - tap * 64 * 192;
    int o = rem / 192, c = rem - o * 192;
    w1m[idx] = (o < 60 && c < 180) ? f2b(cw1[(o * 180 + c) * 27 + tap]) : (uint16_t)0;
}

__global__ void repack2_kernel(const float* __restrict__ cw2, uint16_t* __restrict__ w2m) {
    int idx = blockIdx.x * 256 + threadIdx.x;
    if (idx >= 27 * 192 * 64) return;
    int tap = idx / (192 * 64);
    int rem = idx - tap * 192 * 64;
    int o = rem >> 6, c = rem & 63;
    w2m[idx] = (o < 180 && c < 60) ? f2b(cw2[(o * 60 + c) * 27 + tap]) : (uint16_t)0;
}

// bias table: [h][query][key] bf16
__global__ void biasprep_kernel(const int* __restrict__ rpi, const float* __restrict__ rpb,
                                uint16_t* __restrict__ biasT) {
    int q = blockIdx.x, k = threadIdx.x;
    int t = rpi[q * 512 + k];
#pragma unroll
    for (int h = 0; h < NHEADS; h++)
        biasT[(h * 512 + q) * 512 + k] = f2b(rpb[t * NHEADS + h]);
}

__global__ void zero_pool_kernel(float* __restrict__ pool) {
    if (threadIdx.x < 2 * CC) pool[threadIdx.x] = 0.f;
}

// ---------------- layernorm (warp per row), bf16 out ----------------
__global__ void __launch_bounds__(256) ln_kernel(const float* __restrict__ in, int ins,
        const float* __restrict__ gg, const float* __restrict__ bb,
        uint16_t* __restrict__ outp, int outs) {
    int row = blockIdx.x * 8 + (threadIdx.x >> 5);
    int lane = threadIdx.x & 31;
    const float* p = in + (long)row * ins;
    float v[6];
    float s = 0.f;
#pragma unroll
    for (int i = 0; i < 6; i++) {
        int c = lane + i * 32;
        v[i] = (c < CC) ? p[c] : 0.f;
        s += v[i];
    }
    for (int o = 16; o; o >>= 1) s += __shfl_xor_sync(~0u, s, o);
    float mean = s * (1.f / CC);
    float vs = 0.f;
#pragma unroll
    for (int i = 0; i < 6; i++) {
        int c = lane + i * 32;
        float d = (c < CC) ? (v[i] - mean) : 0.f;
        vs += d * d;
    }
    for (int o = 16; o; o >>= 1) vs += __shfl_xor_sync(~0u, vs, o);
    float inv = rsqrtf(vs * (1.f / CC) + 1e-5f);
    uint16_t* q = outp + (long)row * outs;
#pragma unroll
    for (int i = 0; i < 6; i++) {
        int c = lane + i * 32;
        if (c < CC) q[c] = f2b((v[i] - mean) * inv * gg[c] + bb[c]);
    }
}

// ---------------- bf16 MMA GEMM, cp.async 3-stage, BK=32, fused epilogues ----------------
// EPI 0: qkv scatter bf16 (+q scale); 1: proj scatter + triple residual (e1 = bf16 y2);
//     2: gelu -> bf16 (stride OS); 3: residual -> fp32 out
template <int EPI, bool GATHER>
__global__ void __launch_bounds__(256) mma_gemm(
        const uint16_t* __restrict__ A, int Asr,
        const uint16_t* __restrict__ Wm, const float* __restrict__ bias,
        void* __restrict__ CoutV, int Nc, int Ksm, int OS,
        const float* __restrict__ e0, const uint16_t* __restrict__ e1,
        const float* __restrict__ e2) {
    __shared__ uint32_t As[3][128][20];
    __shared__ uint32_t Bs[3][64][20];
    const int tid = threadIdx.x;
    const int row0 = blockIdx.x * 128, col0 = blockIdx.y * 64;
    const int T = Ksm >> 5;

    int ar[2], akq[2];
    long abase[2];
#pragma unroll
    for (int i = 0; i < 2; i++) {
        int id = tid + i * 256;
        ar[i] = id >> 2;
        akq[i] = id & 3;
        int r = row0 + ar[i];
        int src = GATHER ? win_src_row(r) : r;
        abase[i] = (long)src * Asr + akq[i] * 8;
    }
    const int bn = tid >> 2, bkq = tid & 3;
    const long bbase = (long)(col0 + bn) * Ksm + bkq * 8;

    const int wid = tid >> 5, lane = tid & 31, lr = lane >> 2, lc = lane & 3;
    const int wm = wid >> 1, wn = wid & 1;
    float acc[2][4][4] = {};

    auto loadT = [&](int t) {
        int buf = t % 3;
        int k0 = t * 32;
#pragma unroll
        for (int i = 0; i < 2; i++)
            cpa16(&As[buf][ar[i]][akq[i] * 4], A + abase[i] + k0, true);
        cpa16(&Bs[buf][bn][bkq * 4], Wm + bbase + k0, true);
        cpcommit();
    };

    loadT(0);
    loadT(1);
    for (int t = 0; t < T; t++) {
        if (t + 1 < T) cpwait<1>(); else cpwait<0>();
        __syncthreads();
        if (t + 2 < T) loadT(t + 2);
        tile_mma32(As[t % 3], Bs[t % 3], acc, wm, wn, lane);
    }

#pragma unroll
    for (int mt = 0; mt < 2; mt++) {
#pragma unroll
        for (int nt = 0; nt < 4; nt++) {
            int rbase = row0 + wm * 32 + mt * 16 + lr;
            int cb = col0 + wn * 32 + nt * 8 + lc * 2;   // even
            if (cb >= Nc) continue;
#pragma unroll
            for (int half = 0; half < 2; half++) {
                int row = rbase + half * 8;
                float v0 = acc[mt][nt][half * 2] + bias[cb];
                float v1 = acc[mt][nt][half * 2 + 1] + bias[cb + 1];
                if constexpr (EPI == 0) {
                    int tq = cb / 180;
                    int rem = cb - tq * 180;
                    int hh = rem / 30, hd = rem - hh * 30;   // hd even
                    if (tq == 0) { v0 *= QSCALE; v1 *= QSCALE; }
                    int win = row >> 9, n = row & 511;
                    long idx = ((long)((win * 3 + tq) * NHEADS + hh) * NTOK + n) * HDIM + hd;
                    ((uint32_t*)CoutV)[idx >> 1] = pk(v0, v1);
                } else if constexpr (EPI == 1) {
                    int src = win_src_row(row);
                    long gi = (long)src * CC + cb;
                    int b = src >> 14;
                    uint32_t uy = ((const uint32_t*)e1)[gi >> 1];
                    float* Cf = (float*)CoutV;
                    Cf[gi]     = e0[gi]     + v0 + 0.01f * b2f(uy & 0xFFFF) * e2[b * CC + cb];
                    Cf[gi + 1] = e0[gi + 1] + v1 + 0.01f * b2f(uy >> 16)    * e2[b * CC + cb + 1];
                } else if constexpr (EPI == 2) {
                    long idx = (long)row * OS + cb;
                    ((uint32_t*)CoutV)[idx >> 1] = pk(gelu_exact(v0), gelu_exact(v1));
                } else {
                    long gi = (long)row * CC + cb;
                    float* Cf = (float*)CoutV;
                    Cf[gi]     = e0[gi]     + v0;
                    Cf[gi + 1] = e0[gi + 1] + v1;
                }
            }
        }
    }
}

// ---------------- bf16 MMA implicit-GEMM 3x3x3 conv, cp.async 3-stage, BK=32 ----------------
template <int CV>
__global__ void __launch_bounds__(256) mma_conv(
        const uint16_t* __restrict__ A, const uint16_t* __restrict__ Wt,
        const float* __restrict__ bias, void* __restrict__ OutV) {
    constexpr int Asr = (CV == 1) ? 192 : 64;
    constexpr int KT = (CV == 1) ? 6 : 2;      // 32-wide k-tiles per tap
    constexpr int T = 27 * KT;
    constexpr int Wn = (CV == 1) ? 64 : 192;
    constexpr int Wk = (CV == 1) ? 192 : 64;
    __shared__ uint32_t As[3][128][20];
    __shared__ uint32_t Bs[3][64][20];
    const int tid = threadIdx.x;
    const int row0 = blockIdx.x * 128, col0 = blockIdx.y * 64;

    int ar[2], akq[2], pd[2], ph[2], pw[2];
#pragma unroll
    for (int i = 0; i < 2; i++) {
        int id = tid + i * 256;
        ar[i] = id >> 2;
        akq[i] = id & 3;
        int p = row0 + ar[i];
        pd[i] = (p >> 10) & 15;
        ph[i] = (p >> 5) & 31;
        pw[i] = p & 31;
    }
    const int bn = tid >> 2, bkq = tid & 3;

    const int wid = tid >> 5, lane = tid & 31, lr = lane >> 2, lc = lane & 3;
    const int wm = wid >> 1, wn = wid & 1;
    float acc[2][4][4] = {};

    auto loadT = [&](int t) {
        int buf = t % 3;
        int tap = t / KT;
        int kt = t - tap * KT;
        int k0 = kt * 32;
        int kd = tap / 9 - 1;
        int r9 = tap - (kd + 1) * 9;
        int kh = r9 / 3 - 1;
        int kw = r9 - (kh + 1) * 3 - 1;
        int off = (kd << 10) + (kh << 5) + kw;
#pragma unroll
        for (int i = 0; i < 2; i++) {
            bool valid = ((unsigned)(pd[i] + kd) < 16u) &&
                         ((unsigned)(ph[i] + kh) < 32u) &&
                         ((unsigned)(pw[i] + kw) < 32u);
            const uint16_t* src = valid
                ? A + (long)(row0 + ar[i] + off) * Asr + k0 + akq[i] * 8 : A;
            cpa16(&As[buf][ar[i]][akq[i] * 4], src, valid);
        }
        cpa16(&Bs[buf][bn][bkq * 4],
              Wt + ((long)tap * Wn + col0 + bn) * Wk + k0 + bkq * 8, true);
        cpcommit();
    };

    loadT(0);
    loadT(1);
    for (int t = 0; t < T; t++) {
        if (t + 1 < T) cpwait<1>(); else cpwait<0>();
        __syncthreads();
        if (t + 2 < T) loadT(t + 2);
        tile_mma32(As[t % 3], Bs[t % 3], acc, wm, wn, lane);
    }

#pragma unroll
    for (int mt = 0; mt < 2; mt++) {
#pragma unroll
        for (int nt = 0; nt < 4; nt++) {
            int rbase = row0 + wm * 32 + mt * 16 + lr;
            int cb = col0 + wn * 32 + nt * 8 + lc * 2;   // even
#pragma unroll
            for (int half = 0; half < 2; half++) {
                int row = rbase + half * 8;
                float v0 = acc[mt][nt][half * 2];
                float v1 = acc[mt][nt][half * 2 + 1];
                if constexpr (CV == 1) {
                    v0 = gelu_exact(v0 + ((cb < 60) ? bias[cb] : 0.f));
                    v1 = gelu_exact(v1 + ((cb + 1 < 60) ? bias[cb + 1] : 0.f));
                    ((uint32_t*)OutV)[((long)row * 64 + cb) >> 1] = pk(v0, v1);
                } else {
                    if (cb < CC) {
                        ((uint32_t*)OutV)[((long)row * CC + cb) >> 1] =
                            pk(v0 + bias[cb], v1 + bias[cb + 1]);
                    }
                }
            }
        }
    }
}

// ---------------- pooled sum + channel attention ----------------
__global__ void pooled_kernel(const uint16_t* __restrict__ y2, float* __restrict__ pool) {
    int r0 = blockIdx.x * 64;
    int b = r0 >> 14;
    int c = threadIdx.x;
    if (c >= CC) return;
    float s = 0.f;
    for (int i = 0; i < 64; i++) s += b2f(y2[(long)(r0 + i) * CC + c]);
    atomicAdd(&pool[b * CC + c], s);
}

__global__ void catt_kernel(const float* __restrict__ pool,
        const float* __restrict__ caw1, const float* __restrict__ cab1,
        const float* __restrict__ caw2, const float* __restrict__ cab2,
        float* __restrict__ catt) {
    __shared__ float sq[2][8];
    int tid = threadIdx.x;
    if (tid < 12) {
        int b = tid / 6, j = tid % 6;
        float s = cab1[j];
        for (int c = 0; c < CC; c++)
            s += (pool[b * CC + c] * (1.f / LL)) * caw1[j * CC + c];
        sq[b][j] = fmaxf(s, 0.f);
    }
    __syncthreads();
    if (tid < CC) {
        for (int b = 0; b < 2; b++) {
            float s = cab2[tid];
#pragma unroll
            for (int j = 0; j < 6; j++) s += sq[b][j] * caw2[tid * 6 + j];
            catt[b * CC + tid] = 1.f / (1.f + __expf(-s));
        }
    }
}

// ---------------- bf16 MMA flash attention, register-resident softmax ----------------
__global__ void __launch_bounds__(256) attn_mma(const uint16_t* __restrict__ qkv,
        const uint16_t* __restrict__ biasQ, uint16_t* __restrict__ outp) {
    __shared__ uint32_t Qs[128 * 20];
    __shared__ uint32_t Ks[128 * 20];
    __shared__ uint32_t Vs[32 * 68];

    const int qt = blockIdx.x;
    const int win = blockIdx.y / NHEADS, hh = blockIdx.y % NHEADS;
    const uint32_t* qbu = (const uint32_t*)(qkv +
        ((long)((win * 3 + 0) * NHEADS + hh) * NTOK + qt * 128) * HDIM);
    const uint32_t* kbu = (const uint32_t*)(qkv +
        (long)((win * 3 + 1) * NHEADS + hh) * NTOK * HDIM);
    const uint16_t* vb = qkv + (long)((win * 3 + 2) * NHEADS + hh) * NTOK * HDIM;
    const uint32_t* bqu = (const uint32_t*)(biasQ + ((long)(hh * NTOK) + qt * 128) * NTOK);

    const int tid = threadIdx.x;
    const int w = tid >> 5, lane = tid & 31, g = lane >> 2, lc = lane & 3;
    const int lar = lane & 15;
    const int law = (lane >> 4) * 4;
    const int lbr = ((lane >> 4) << 3) + (lane & 7);
    const int lbw = ((lane >> 3) & 1) * 4;

    for (int idx = tid; idx < 128 * 16; idx += 256) {
        int r = idx >> 4, d = idx & 15;
        Qs[r * 20 + d] = (d < 15) ? qbu[r * 15 + d] : 0u;
    }
    __syncthreads();
    uint32_t qf[2][4];
    ldsm4(qf[0], &Qs[(w * 16 + lar) * 20 + law]);
    ldsm4(qf[1], &Qs[(w * 16 + lar) * 20 + 8 + law]);

    const int row0 = w * 16 + g;
    float m0 = -1e30f, m1 = -1e30f, l0 = 0.f, l1 = 0.f;
    float oacc[4][4] = {};

    for (int t0 = 0; t0 < NTOK; t0 += 128) {
        __syncthreads();
        for (int idx = tid; idx < 128 * 16; idx += 256) {
            int r = idx >> 4, d = idx & 15;
            Ks[r * 20 + d] = (d < 15) ? kbu[(t0 + r) * 15 + d] : 0u;
        }
        for (int idx = tid; idx < 32 * 64; idx += 256) {
            int d = idx >> 6, j = idx & 63;
            uint32_t u = 0u;
            if (d < HDIM) {
                uint32_t lo = vb[(long)(t0 + 2 * j) * HDIM + d];
                uint32_t hi = vb[(long)(t0 + 2 * j + 1) * HDIM + d];
                u = lo | (hi << 16);
            }
            Vs[d * 68 + j] = u;
        }
        __syncthreads();

        float sacc[16][4] = {};
#pragma unroll
        for (int ks = 0; ks < 2; ks++) {
#pragma unroll
            for (int p = 0; p < 8; p++) {
                uint32_t b2[4];
                ldsm4(b2, &Ks[(p * 16 + lbr) * 20 + ks * 8 + lbw]);
                mma16(sacc[p * 2],     qf[ks], b2);
                mma16(sacc[p * 2 + 1], qf[ks], b2 + 2);
            }
        }

        float pm0 = -1e30f, pm1 = -1e30f;
#pragma unroll
        for (int nt = 0; nt < 16; nt++) {
            int c0 = t0 + nt * 8 + lc * 2;
            uint32_t u0 = bqu[((long)row0 * NTOK + c0) >> 1];
            uint32_t u1 = bqu[((long)(row0 + 8) * NTOK + c0) >> 1];
            sacc[nt][0] += b2f(u0 & 0xFFFF);
            sacc[nt][1] += b2f(u0 >> 16);
            sacc[nt][2] += b2f(u1 & 0xFFFF);
            sacc[nt][3] += b2f(u1 >> 16);
            pm0 = fmaxf(pm0, fmaxf(sacc[nt][0], sacc[nt][1]));
            pm1 = fmaxf(pm1, fmaxf(sacc[nt][2], sacc[nt][3]));
        }
        pm0 = fmaxf(pm0, __shfl_xor_sync(~0u, pm0, 1));
        pm0 = fmaxf(pm0, __shfl_xor_sync(~0u, pm0, 2));
        pm1 = fmaxf(pm1, __shfl_xor_sync(~0u, pm1, 1));
        pm1 = fmaxf(pm1, __shfl_xor_sync(~0u, pm1, 2));
        float nm0 = fmaxf(m0, pm0), nm1 = fmaxf(m1, pm1);
        float f0 = __expf(m0 - nm0), f1 = __expf(m1 - nm1);
        m0 = nm0; m1 = nm1;

        float ps0 = 0.f, ps1 = 0.f;
        uint32_t pf[8][4];
#pragma unroll
        for (int k2 = 0; k2 < 8; k2++) {
            float e00 = __expf(sacc[2 * k2][0] - m0);
            float e01 = __expf(sacc[2 * k2][1] - m0);
            float e10 = __expf(sacc[2 * k2][2] - m1);
            float e11 = __expf(sacc[2 * k2][3] - m1);
            float e20 = __expf(sacc[2 * k2 + 1][0] - m0);
            float e21 = __expf(sacc[2 * k2 + 1][1] - m0);
            float e30 = __expf(sacc[2 * k2 + 1][2] - m1);
            float e31 = __expf(sacc[2 * k2 + 1][3] - m1);
            ps0 += e00 + e01 + e20 + e21;
            ps1 += e10 + e11 + e30 + e31;
            pf[k2][0] = pk(e00, e01);
            pf[k2][1] = pk(e10, e11);
            pf[k2][2] = pk(e20, e21);
            pf[k2][3] = pk(e30, e31);
        }
        ps0 += __shfl_xor_sync(~0u, ps0, 1);
        ps0 += __shfl_xor_sync(~0u, ps0, 2);
        ps1 += __shfl_xor_sync(~0u, ps1, 1);
        ps1 += __shfl_xor_sync(~0u, ps1, 2);
        l0 = l0 * f0 + ps0;
        l1 = l1 * f1 + ps1;

#pragma unroll
        for (int nt = 0; nt < 4; nt++) {
            oacc[nt][0] *= f0; oacc[nt][1] *= f0;
            oacc[nt][2] *= f1; oacc[nt][3] *= f1;
        }
#pragma unroll
        for (int k2 = 0; k2 < 8; k2++) {
            uint32_t ba[4], bb[4];
            ldsm4(ba, &Vs[lbr * 68 + k2 * 8 + lbw]);
            ldsm4(bb, &Vs[(lbr + 16) * 68 + k2 * 8 + lbw]);
            mma16(oacc[0], pf[k2], ba);
            mma16(oacc[1], pf[k2], ba + 2);
            mma16(oacc[2], pf[k2], bb);
            mma16(oacc[3], pf[k2], bb + 2);
        }
    }

    float i0 = 1.f / l0, i1 = 1.f / l1;
    uint16_t* ob = outp + (long)(win * NTOK + qt * 128 + w * 16) * CP + hh * HDIM;
#pragma unroll
    for (int nt = 0; nt < 4; nt++) {
        int c = nt * 8 + lc * 2;
        if (c < HDIM) {
            *(uint32_t*)&ob[(long)g * CP + c] = pk(oacc[nt][0] * i0, oacc[nt][1] * i0);
            *(uint32_t*)&ob[(long)(g + 8) * CP + c] = pk(oacc[nt][2] * i1, oacc[nt][3] * i1);
        }
    }
}

// ---------------- host launch (dual-stream fork/join for graph capture) ----------------
extern "C" void kernel_launch(void* const* d_in, const int* in_sizes, int n_in,
                              void* d_out, int out_size) {
    const float* x      = (const float*)d_in[0];
    const int*   rpi    = (const int*)  d_in[4];
    const float* g1     = (const float*)d_in[7];
    const float* b1     = (const float*)d_in[8];
    const float* qkv_w  = (const float*)d_in[9];
    const float* qkv_b  = (const float*)d_in[10];
    const float* rpb    = (const float*)d_in[11];
    const float* proj_w = (const float*)d_in[12];
    const float* proj_b = (const float*)d_in[13];
    const float* cw1    = (const float*)d_in[14];
    const float* cb1    = (const float*)d_in[15];
    const float* cw2    = (const float*)d_in[16];
    const float* cb2    = (const float*)d_in[17];
    const float* caw1   = (const float*)d_in[18];
    const float* cab1   = (const float*)d_in[19];
    const float* caw2   = (const float*)d_in[20];
    const float* cab2   = (const float*)d_in[21];
    const float* g2     = (const float*)d_in[22];
    const float* b2     = (const float*)d_in[23];
    const float* fc1_w  = (const float*)d_in[24];
    const float* fc1_b  = (const float*)d_in[25];
    const float* fc2_w  = (const float*)d_in[26];
    const float* fc2_b  = (const float*)d_in[27];
    float* outp = (float*)d_out;

    uint16_t *p_xn, *p_ln2, *p_ao, *p_y1, *p_y2, *p_qkv, *p_h, *p_bt;
    uint16_t *p_w1m, *p_w2m, *p_wq, *p_wp, *p_wf1, *p_wf2;
    float *p_x1, *p_pool, *p_catt;
    cudaGetSymbolAddress((void**)&p_xn,   g_xn);
    cudaGetSymbolAddress((void**)&p_ln2,  g_ln2);
    cudaGetSymbolAddress((void**)&p_ao,   g_ao);
    cudaGetSymbolAddress((void**)&p_x1,   g_x1);
    cudaGetSymbolAddress((void**)&p_y1,   g_y1);
    cudaGetSymbolAddress((void**)&p_y2,   g_y2);
    cudaGetSymbolAddress((void**)&p_qkv,  g_qkv);
    cudaGetSymbolAddress((void**)&p_h,    g_hbuf);
    cudaGetSymbolAddress((void**)&p_bt,   g_biasT);
    cudaGetSymbolAddress((void**)&p_w1m,  g_w1m);
    cudaGetSymbolAddress((void**)&p_w2m,  g_w2m);
    cudaGetSymbolAddress((void**)&p_wq,   g_wq);
    cudaGetSymbolAddress((void**)&p_wp,   g_wp);
    cudaGetSymbolAddress((void**)&p_wf1,  g_wf1);
    cudaGetSymbolAddress((void**)&p_wf2,  g_wf2);
    cudaGetSymbolAddress((void**)&p_pool, g_pool);
    cudaGetSymbolAddress((void**)&p_catt, g_catt);

    // one-time side-stream + events (host resources only; work per call is identical)
    static cudaStream_t s1 = nullptr;
    static cudaEvent_t evStart = nullptr, evLN1 = nullptr, evJoin = nullptr;
    if (s1 == nullptr) {
        cudaStreamCreateWithFlags(&s1, cudaStreamNonBlocking);
        cudaEventCreateWithFlags(&evStart, cudaEventDisableTiming);
        cudaEventCreateWithFlags(&evLN1, cudaEventDisableTiming);
        cudaEventCreateWithFlags(&evJoin, cudaEventDisableTiming);
    }

    // fork: s1 branches off the capture-origin (default) stream
    cudaEventRecord(evStart, 0);
    cudaStreamWaitEvent(s1, evStart, 0);

    // ---- side stream s1: weight prep for conv/proj/mlp, then conv branch ----
    repack1_kernel<<<(27 * 64 * 192 + 255) / 256, 256, 0, s1>>>(cw1, p_w1m);
    repack2_kernel<<<(27 * 192 * 64 + 255) / 256, 256, 0, s1>>>(cw2, p_w2m);
    wpack_kernel<<<(180 * 192 + 255) / 256, 256, 0, s1>>>(proj_w, p_wp, 180, 180, 192);
    wpack_kernel<<<(720 * 192 + 255) / 256, 256, 0, s1>>>(fc1_w, p_wf1, 720, 180, 192);
    wpack_kernel<<<(180 * HIDP + 255) / 256, 256, 0, s1>>>(fc2_w, p_wf2, 180, 720, HIDP);
    zero_pool_kernel<<<1, 384, 0, s1>>>(p_pool);

    // ---- main stream: attention-path prep + LN1 ----
    wpack_kernel<<<(540 * 192 + 255) / 256, 256>>>(qkv_w, p_wq, 540, 180, 192);
    biasprep_kernel<<<512, 512>>>(rpi, rpb, p_bt);
    ln_kernel<<<LT / 8, 256>>>(x, CC, g1, b1, p_xn, CP);
    cudaEventRecord(evLN1, 0);

    // ---- s1: conv branch (needs xn) ----
    cudaStreamWaitEvent(s1, evLN1, 0);
    mma_conv<1><<<dim3(LT / 128, 1), 256, 0, s1>>>(p_xn, p_w1m, cb1, p_y1);
    mma_conv<2><<<dim3(LT / 128, 3), 256, 0, s1>>>(p_y1, p_w2m, cb2, p_y2);
    pooled_kernel<<<LT / 64, 192, 0, s1>>>(p_y2, p_pool);
    catt_kernel<<<1, 192, 0, s1>>>(p_pool, caw1, cab1, caw2, cab2, p_catt);
    cudaEventRecord(evJoin, s1);

    // ---- main stream: window attention path (concurrent with conv branch) ----
    mma_gemm<0, true><<<dim3(LT / 128, 9), 256>>>(p_xn, CP, p_wq, qkv_b, p_qkv,
                                                  540, 192, 0, nullptr, nullptr, nullptr);
    attn_mma<<<dim3(4, NWIN * NHEADS), 256>>>(p_qkv, p_bt, p_ao);

    // join: proj needs y2 + catt (s1) and wp (s1)
    cudaStreamWaitEvent(0, evJoin, 0);
    mma_gemm<1, false><<<dim3(LT / 128, 3), 256>>>(p_ao, CP, p_wp, proj_b, p_x1,
                                                   180, 192, 0, x, p_y2, p_catt);

    // MLP
    ln_kernel<<<LT / 8, 256>>>(p_x1, CC, g2, b2, p_ln2, CP);
    mma_gemm<2, false><<<dim3(LT / 128, 12), 256>>>(p_ln2, CP, p_wf1, fc1_b, p_h,
                                                    720, 192, HIDP, nullptr, nullptr, nullptr);
    mma_gemm<3, false><<<dim3(LT / 128, 3), 256>>>(p_h, HIDP, p_wf2, fc2_b, outp,
                                                   180, HIDP, 0, p_x1, nullptr, nullptr);
}